// round 8
// baseline (speedup 1.0000x reference)
#include <cuda_runtime.h>
#include <math.h>

#define NNODE 118
#define TT 2048
#define M_ROWS (NNODE*TT)

typedef unsigned long long ull;
union F2U { ull u; float2 f; };

__device__ __forceinline__ ull pk2(float x, float y){ ull r; asm("mov.b64 %0, {%1,%2};" : "=l"(r) : "f"(x), "f"(y)); return r; }
__device__ __forceinline__ ull dupf(float x){ ull r; asm("mov.b64 %0, {%1,%1};" : "=l"(r) : "f"(x)); return r; }
__device__ __forceinline__ void fma2(ull& d, ull a, ull b){ asm("fma.rn.f32x2 %0, %1, %2, %0;" : "+l"(d) : "l"(a), "l"(b)); }

// unpack bf16x2 word -> f32x2 (low bf16 = even element)
__device__ __forceinline__ ull unpk(unsigned w){
    unsigned lo = w << 16;
    unsigned hi = w & 0xFFFF0000u;
    ull r; asm("mov.b64 %0, {%1,%2};" : "=l"(r) : "r"(lo), "r"(hi));
    return r;
}
__device__ __forceinline__ unsigned bf1(float f){
    unsigned b = __float_as_uint(f);
    return (b + 0x7FFFu + ((b >> 16) & 1u)) >> 16;   // RNE
}
__device__ __forceinline__ unsigned bfpair(float e, float o){ return bf1(e) | (bf1(o) << 16); }

// column permutation: semantic gate-major n (= g*128+c)  <->  stored col' = 4c+g
__device__ __forceinline__ int invperm(int cp){ return (cp & 3)*128 + (cp >> 2); }

// ---------------- scratch (device globals; no allocation allowed) ----------
__device__ __align__(256) float g_xpre[(size_t)M_ROWS*512];
__device__ __align__(256) float g_h1[(size_t)M_ROWS*128];
__device__ __align__(256) float g_h2last[NNODE*128];
__device__ __align__(256) float g_vm[2*128];
__device__ __align__(256) float g_flag[1];
__device__ __align__(256) float g_n[NNODE*256];
__device__ __align__(256) float g_Pa[NNODE*192];
__device__ __align__(256) float g_Pb[NNODE*192];
__device__ __align__(256) float g_Qa[NNODE*256];
__device__ __align__(256) float g_Qb[NNODE*256];
__device__ __align__(256) float g_Ra[NNODE*256];
__device__ __align__(256) float g_Rb[NNODE*256];
__device__ __align__(256) float g_alpha[NNODE*NNODE];
__device__ __align__(256) float g_G[4*128*128];

__device__ __forceinline__ float leaky(float z){ return z >= 0.f ? z : 0.01f*z; }

// ---------------- GEMM: C(M,512) = A(M,128) @ W(512,128)^T + b1 + b2 -------
// Output columns PERMUTED: stored col' = 4c+g for semantic n = g*128+c.
#define GP2 132
#define GEMM_SMEM (2*128*GP2*4)

__global__ void __launch_bounds__(256) gemm_k(const float* __restrict__ A,
                                              const float* __restrict__ W,
                                              const float* __restrict__ b1,
                                              const float* __restrict__ b2,
                                              float* __restrict__ C)
{
    extern __shared__ float sm[];
    float* As = sm;               // [k][m] pad GP2
    float* Ws = sm + 128*GP2;     // [k][n'] pad GP2
    const int tid = threadIdx.x;
    const int mbase = blockIdx.y * 128;
    const int nbase = blockIdx.x * 128;

    const float4* A4 = (const float4*)(A + (size_t)mbase*128);
    const float4* W4 = (const float4*)W;
    #pragma unroll
    for (int r = 0; r < 16; r++) {
        int idx = tid + r*256;          // 0..4095
        int row = idx >> 5;             // 0..127
        int kg  = idx & 31;             // 0..31
        float4 va = A4[idx];
        As[(4*kg+0)*GP2 + row] = va.x;
        As[(4*kg+1)*GP2 + row] = va.y;
        As[(4*kg+2)*GP2 + row] = va.z;
        As[(4*kg+3)*GP2 + row] = va.w;
        int srow = invperm(nbase + row);      // permuted W row source
        float4 vw = W4[srow*32 + kg];
        Ws[(4*kg+0)*GP2 + row] = vw.x;
        Ws[(4*kg+1)*GP2 + row] = vw.y;
        Ws[(4*kg+2)*GP2 + row] = vw.z;
        Ws[(4*kg+3)*GP2 + row] = vw.w;
    }
    __syncthreads();

    const int tx = tid & 15;   // n micro
    const int ty = tid >> 4;   // m micro
    const int m0 = ty*8, n0 = tx*8;

    F2U acc[4][8];
    #pragma unroll
    for (int p = 0; p < 4; p++)
        #pragma unroll
        for (int j = 0; j < 8; j++) acc[p][j].u = 0ull;

    #pragma unroll 8
    for (int k = 0; k < 128; k++) {
        const float4 a0 = *(const float4*)(As + k*GP2 + m0);
        const float4 a1 = *(const float4*)(As + k*GP2 + m0 + 4);
        const float4 w0 = *(const float4*)(Ws + k*GP2 + n0);
        const float4 w1 = *(const float4*)(Ws + k*GP2 + n0 + 4);
        ull ap0 = pk2(a0.x, a0.y), ap1 = pk2(a0.z, a0.w);
        ull ap2 = pk2(a1.x, a1.y), ap3 = pk2(a1.z, a1.w);
        ull wd;
        wd = dupf(w0.x); fma2(acc[0][0].u, ap0, wd); fma2(acc[1][0].u, ap1, wd); fma2(acc[2][0].u, ap2, wd); fma2(acc[3][0].u, ap3, wd);
        wd = dupf(w0.y); fma2(acc[0][1].u, ap0, wd); fma2(acc[1][1].u, ap1, wd); fma2(acc[2][1].u, ap2, wd); fma2(acc[3][1].u, ap3, wd);
        wd = dupf(w0.z); fma2(acc[0][2].u, ap0, wd); fma2(acc[1][2].u, ap1, wd); fma2(acc[2][2].u, ap2, wd); fma2(acc[3][2].u, ap3, wd);
        wd = dupf(w0.w); fma2(acc[0][3].u, ap0, wd); fma2(acc[1][3].u, ap1, wd); fma2(acc[2][3].u, ap2, wd); fma2(acc[3][3].u, ap3, wd);
        wd = dupf(w1.x); fma2(acc[0][4].u, ap0, wd); fma2(acc[1][4].u, ap1, wd); fma2(acc[2][4].u, ap2, wd); fma2(acc[3][4].u, ap3, wd);
        wd = dupf(w1.y); fma2(acc[0][5].u, ap0, wd); fma2(acc[1][5].u, ap1, wd); fma2(acc[2][5].u, ap2, wd); fma2(acc[3][5].u, ap3, wd);
        wd = dupf(w1.z); fma2(acc[0][6].u, ap0, wd); fma2(acc[1][6].u, ap1, wd); fma2(acc[2][6].u, ap2, wd); fma2(acc[3][6].u, ap3, wd);
        wd = dupf(w1.w); fma2(acc[0][7].u, ap0, wd); fma2(acc[1][7].u, ap1, wd); fma2(acc[2][7].u, ap2, wd); fma2(acc[3][7].u, ap3, wd);
    }

    const int col = nbase + n0;
    float bias[8];
    #pragma unroll
    for (int c = 0; c < 8; c++) {
        int src = invperm(col + c);
        bias[c] = b1[src] + b2[src];
    }

    #pragma unroll
    for (int p = 0; p < 4; p++) {
        float4 o;
        float* r0 = C + (size_t)(mbase + m0 + 2*p)*512 + col;
        float* r1 = r0 + 512;
        o.x = acc[p][0].f.x + bias[0]; o.y = acc[p][1].f.x + bias[1];
        o.z = acc[p][2].f.x + bias[2]; o.w = acc[p][3].f.x + bias[3];
        *(float4*)(r0) = o;
        o.x = acc[p][4].f.x + bias[4]; o.y = acc[p][5].f.x + bias[5];
        o.z = acc[p][6].f.x + bias[6]; o.w = acc[p][7].f.x + bias[7];
        *(float4*)(r0 + 4) = o;
        o.x = acc[p][0].f.y + bias[0]; o.y = acc[p][1].f.y + bias[1];
        o.z = acc[p][2].f.y + bias[2]; o.w = acc[p][3].f.y + bias[3];
        *(float4*)(r1) = o;
        o.x = acc[p][4].f.y + bias[4]; o.y = acc[p][5].f.y + bias[5];
        o.z = acc[p][6].f.y + bias[6]; o.w = acc[p][7].f.y + bias[7];
        *(float4*)(r1 + 4) = o;
    }
}

// ---------------- LSTM recurrence: one block per node ----------------------
// xpre columns permuted (col' = 4c+g) -> thread j reads column j (coalesced).
// Quad {i,f,g,o} of a cell = 4 consecutive lanes -> SHFL update, ONE barrier
// per step, h double-buffered.
// Weight split tuned to avoid spills: k=0..79 fp32 in regs (40 ull = 80 regs),
// k=80..127 bf16 in smem (6 uint4 = 48 KB/block).
template<int WRITE_ALL>
__global__ void __launch_bounds__(512, 1) lstm_rec(const float* __restrict__ xpre,
                                                   const float* __restrict__ Whh,
                                                   float* __restrict__ hout)
{
    __shared__ __align__(16) float hs[2][128];
    __shared__ __align__(16) uint4 wsb[6*512];   // 48 KB bf16 weight slice

    const int j = threadIdx.x;
    const int n = blockIdx.x;
    const int l = j & 31;
    const int w = j >> 5;
    const int gate = l & 3;
    const int cell = w*8 + (l >> 2);
    const int row  = gate*128 + cell;            // = invperm(j)

    // load weights: row `row` of Whh (128 floats)
    const float* wg = Whh + row*128;
    ull wr[40];                                   // k = 0..79
    #pragma unroll
    for (int g = 0; g < 20; g++) {
        float4 v = *(const float4*)(wg + 4*g);
        wr[2*g]   = pk2(v.x, v.y);
        wr[2*g+1] = pk2(v.z, v.w);
    }
    #pragma unroll
    for (int s = 0; s < 6; s++) {                 // k = 80..127 as bf16
        const float* base = wg + 80 + s*8;
        uint4 pk;
        pk.x = bfpair(base[0], base[1]);
        pk.y = bfpair(base[2], base[3]);
        pk.z = bfpair(base[4], base[5]);
        pk.w = bfpair(base[6], base[7]);
        wsb[s*512 + j] = pk;
    }

    if (j < 128) hs[0][j] = 0.f;
    float c = 0.f;
    __syncthreads();

    const float* xp = xpre + (size_t)n*TT*512 + j;   // coalesced (permuted layout)
    float xnext = xp[0];
    float* hw = hout + (WRITE_ALL ? ((size_t)n*TT*128 + cell) : ((size_t)n*128 + cell));

    int p = 0;
    for (int t = 0; t < TT; t++) {
        F2U A0, A1, A2, A3;
        A0.u = pk2(xnext, 0.f); A1.u = 0ull; A2.u = 0ull; A3.u = 0ull;
        if (t + 1 < TT) xnext = xp[(size_t)(t+1)*512];

        const ulonglong2* h2 = (const ulonglong2*)hs[p];
        #pragma unroll
        for (int g = 0; g < 20; g += 2) {            // k = 0..79
            ulonglong2 hv0 = h2[g];
            ulonglong2 hv1 = h2[g+1];
            fma2(A0.u, wr[2*g],   hv0.x);
            fma2(A1.u, wr[2*g+1], hv0.y);
            fma2(A2.u, wr[2*g+2], hv1.x);
            fma2(A3.u, wr[2*g+3], hv1.y);
        }
        #pragma unroll
        for (int s = 0; s < 6; s++) {                // k = 80..127
            uint4 wv = wsb[s*512 + j];
            ulonglong2 hv0 = h2[20 + 2*s];
            ulonglong2 hv1 = h2[21 + 2*s];
            fma2(A0.u, unpk(wv.x), hv0.x);
            fma2(A1.u, unpk(wv.y), hv0.y);
            fma2(A2.u, unpk(wv.z), hv1.x);
            fma2(A3.u, unpk(wv.w), hv1.y);
        }
        float acc = (A0.f.x + A0.f.y) + (A1.f.x + A1.f.y)
                  + (A2.f.x + A2.f.y) + (A3.f.x + A3.f.y);

        // branch-free activation: sigmoid for i,f,o; tanh = 2*sig(2x)-1 for g
        const bool isg = (gate == 2);
        float u  = isg ? 2.f*acc : acc;
        float e  = __expf(-u);
        float s_ = __fdividef(1.f, 1.f + e);
        float a  = isg ? (2.f*s_ - 1.f) : s_;

        const int base = l & ~3;
        float iv = __shfl_sync(0xFFFFFFFFu, a, base);
        float fv = __shfl_sync(0xFFFFFFFFu, a, base + 1);
        float gv = __shfl_sync(0xFFFFFFFFu, a, base + 2);
        float ov = __shfl_sync(0xFFFFFFFFu, a, base + 3);
        c = fv*c + iv*gv;
        float e2 = __expf(-2.f*c);
        float th = __fdividef(2.f, 1.f + e2) - 1.f;
        float hv = ov * th;
        p ^= 1;
        if (gate == 0) {
            hs[p][cell] = hv;
            if (WRITE_ALL)      hw[(size_t)t*128] = hv;
            else if (t == TT-1) hw[0] = hv;
        }
        __syncthreads();
    }
}

// ---------------- E0: pseudo-message projections + direct outputs ----------
__global__ void prep_kernel(const float* __restrict__ x_tag,
                            const float* __restrict__ pm,
                            const float* __restrict__ Wvm,
                            float* __restrict__ out, int osz)
{
    const int tid = threadIdx.x;  // 128
    __shared__ float pms[768];
    for (int i = tid; i < 768; i += 128) pms[i] = pm[i];
    __syncthreads();

    float base = 0.f;
    for (int k = 0; k < 768; k++) base += pms[k]*Wvm[k*128 + tid];
    g_vm[tid]       = leaky(base);
    g_vm[128 + tid] = leaky(base + Wvm[768*128 + tid]);

    if (tid < NNODE) {
        int o;
        o = 236 + tid*2 + 0; if (o < osz) out[o] = x_tag[tid*3+0];
        o = 236 + tid*2 + 1; if (o < osz) out[o] = x_tag[tid*3+1];
        float a = x_tag[tid*3+2];
        o = 474 + tid; if (o < osz) out[o] = (a == 0.f) ? 1.f : 0.f;
        o = 592 + tid; if (o < osz) out[o] = (a == 1.f) ? 1.f : 0.f;
    }
    if (tid == 0) {
        int cnt = 0;
        for (int i = 0; i < NNODE; i++) if (x_tag[i*3+2] == 0.f) cnt++;
        g_flag[0] = (cnt > 0) ? 1.f : 0.f;
    }
}

// ---------------- Gram matrices for l_ort -----------------------------
__global__ void gram_kernel(const float* __restrict__ Wum, const float* __restrict__ Wvm,
                            const float* __restrict__ Wup, const float* __restrict__ Wvp)
{
    const int bid = blockIdx.x;
    const int mat = bid >> 7;
    const int k   = bid & 127;
    const int l   = threadIdx.x;  // 128
    const float* W; int rows;
    if      (mat == 0) { W = Wum; rows = 769; }
    else if (mat == 1) { W = Wvm; rows = 769; }
    else if (mat == 2) { W = Wup; rows = 128; }
    else               { W = Wvp; rows = 128; }
    float acc = 0.f;
    for (int i = 0; i < rows; i++) acc += W[i*128 + k] * W[i*128 + l];
    g_G[mat*16384 + k*128 + l] = acc;
}

// ---------------- E1: per-node MLP chain -> n -------------------------
__global__ void node_kernel(const float* __restrict__ x_tag,
                            const float* __restrict__ Wup,
                            const float* __restrict__ W_hyb, const float* __restrict__ b_hyb,
                            const float* __restrict__ W_act, const float* __restrict__ b_act,
                            const float* __restrict__ W_inact, const float* __restrict__ b_inact)
{
    const int n = blockIdx.x, tid = threadIdx.x;  // 256
    __shared__ float p[128], up[128], vm_s[128], hh[256];
    const float act = x_tag[n*3+2];
    if (tid < 128) {
        p[tid]    = leaky(g_h2last[n*128 + tid]);
        vm_s[tid] = (act == 1.f) ? g_vm[128 + tid] : g_vm[tid];
    }
    __syncthreads();
    if (tid < 128) {
        float a = 0.f;
        for (int k = 0; k < 128; k++) a += p[k]*Wup[k*128 + tid];
        up[tid] = leaky(a);
    }
    __syncthreads();
    {
        float a = b_hyb[tid];
        for (int k = 0; k < 128; k++) {
            float u_ = up[k], v_ = vm_s[k];
            a += u_*W_hyb[k*256 + tid] + (u_ + v_)*W_hyb[(128+k)*256 + tid] + v_*W_hyb[(256+k)*256 + tid];
        }
        hh[tid] = leaky(a);
    }
    __syncthreads();
    {
        float na = b_act[tid], ni = b_inact[tid];
        for (int k = 0; k < 256; k++) {
            float h_ = hh[k];
            na += h_*W_act[k*256 + tid];
            ni += h_*W_inact[k*256 + tid];
        }
        na += x_tag[n*3+0]*W_act[256*256 + tid] + x_tag[n*3+1]*W_act[257*256 + tid];
        g_n[n*256 + tid] = leaky(na*(1.f - act) + ni*act);
    }
}

// ---------------- E2: per-node pair projections -----------------------
__global__ void proj_kernel(const float* __restrict__ Wphin,
                            const float* __restrict__ Won,
                            const float* __restrict__ Weo)
{
    const int n = blockIdx.x, tid = threadIdx.x;  // 256
    __shared__ float nn_s[256];
    nn_s[tid] = g_n[n*256 + tid];
    __syncthreads();
    if (tid < 192) {
        float pb = 0.f, pa = 0.f;
        for (int k = 0; k < 256; k++) {
            float v = nn_s[k];
            pb += v*Wphin[k*192 + tid];
            pa += v*Wphin[(256+k)*192 + tid];
        }
        g_Pb[n*192 + tid] = pb;
        g_Pa[n*192 + tid] = pa;
    }
    float qb = 0.f, qa = 0.f, rb = 0.f, ra = 0.f;
    for (int k = 0; k < 256; k++) {
        float v = nn_s[k];
        qb += v*Won[k*256 + tid];
        qa += v*Won[(256+k)*256 + tid];
        rb += v*Weo[(256+k)*256 + tid];
        ra += v*Weo[(512+k)*256 + tid];
    }
    g_Qb[n*256 + tid] = qb;
    g_Qa[n*256 + tid] = qa;
    g_Rb[n*256 + tid] = rb;
    g_Ra[n*256 + tid] = ra;
}

// ---------------- E3: phi column + masked softmaxes -> alpha ----------
__device__ __forceinline__ float blockmax128(float v, float* red){
    int tid = threadIdx.x; red[tid] = v; __syncthreads();
    #pragma unroll
    for (int s = 64; s > 0; s >>= 1) { if (tid < s) red[tid] = fmaxf(red[tid], red[tid+s]); __syncthreads(); }
    float r = red[0]; __syncthreads(); return r;
}
__device__ __forceinline__ float blocksum128(float v, float* red){
    int tid = threadIdx.x; red[tid] = v; __syncthreads();
    #pragma unroll
    for (int s = 64; s > 0; s >>= 1) { if (tid < s) red[tid] += red[tid+s]; __syncthreads(); }
    float r = red[0]; __syncthreads(); return r;
}

__global__ void phi_alpha_kernel(const float* __restrict__ x_tag,
                                 const float* __restrict__ aphi)
{
    const int b = blockIdx.x;
    const int tid = threadIdx.x;  // 128
    __shared__ float pb_s[192], ap_s[192], red[128];
    for (int i = tid; i < 192; i += 128) { pb_s[i] = g_Pb[b*192 + i]; ap_s[i] = aphi[i]; }
    __syncthreads();

    float ph = 0.f, v1 = 0.f;
    if (tid < NNODE) {
        const float* pa = g_Pa + tid*192;
        #pragma unroll 8
        for (int d = 0; d < 192; d++) ph += leaky(pb_s[d] + pa[d]) * ap_s[d];
        v1 = (x_tag[tid*3+2] == 0.f) ? 1.f : 0.f;
    }

    const float NEG = -1000000000.f;
    float m1 = (tid < NNODE) ? (v1 > 0.f ? ph : NEG) : -INFINITY;
    float m0 = (tid < NNODE) ? (v1 > 0.f ? NEG : ph) : -INFINITY;
    float ma = (tid < NNODE) ? ph : -INFINITY;

    float mx = blockmax128(m1, red);
    float e  = (tid < NNODE) ? __expf(m1 - mx) : 0.f;
    float s  = blocksum128(e, red);
    float sm1 = e / s;

    mx = blockmax128(m0, red);
    e  = (tid < NNODE) ? __expf(m0 - mx) : 0.f;
    s  = blocksum128(e, red);
    float sm0 = e / s;

    mx = blockmax128(ma, red);
    e  = (tid < NNODE) ? __expf(ma - mx) : 0.f;
    s  = blocksum128(e, red);
    float sma = e / s;

    if (tid < NNODE) {
        float a = (g_flag[0] > 0.f) ? (v1 > 0.f ? sm1 : sm0) : sma;
        g_alpha[tid*NNODE + b] = a;
    }
}

// ---------------- E4: hyper messages + y_hat --------------------------
__global__ void hyper_kernel(const float* __restrict__ x_tag,
                             const float* __restrict__ Weo,
                             const float* __restrict__ Wi,
                             const float* __restrict__ bi,
                             float* __restrict__ out, int osz)
{
    const int n = blockIdx.x, tid = threadIdx.x;  // 256
    __shared__ float qa[256], ra[256], nn_s[256], u[256], al[NNODE], red[256];
    qa[tid]   = g_Qa[n*256 + tid];
    ra[tid]   = g_Ra[n*256 + tid];
    nn_s[tid] = g_n[n*256 + tid];
    if (tid < NNODE) al[tid] = g_alpha[n*NNODE + tid];
    __syncthreads();

    float uacc = 0.f, racc = 0.f, alsum = 0.f;
    const float qad = qa[tid];
    for (int j = 0; j < NNODE; j++) {
        float a_ = al[j];
        uacc  += a_ * leaky(g_Qb[j*256 + tid] + qad);
        racc  += a_ * g_Rb[j*256 + tid];
        alsum += a_;
    }
    u[tid] = uacc;
    __syncthreads();

    float T = racc + alsum*ra[tid];
    for (int k = 0; k < 256; k++) T += u[k]*Weo[k*256 + tid];

    const float act = x_tag[n*3+2];
    float hm0 = leaky(act*T);
    float hm1 = leaky((1.f - act)*T);

    const float* Win = Wi + (size_t)n*768*2;
    float p0 = nn_s[tid]*Win[tid*2+0] + hm0*Win[(256+tid)*2+0] + hm1*Win[(512+tid)*2+0];
    float p1 = nn_s[tid]*Win[tid*2+1] + hm0*Win[(256+tid)*2+1] + hm1*Win[(512+tid)*2+1];

    red[tid] = p0; __syncthreads();
    #pragma unroll
    for (int s = 128; s > 0; s >>= 1) { if (tid < s) red[tid] += red[tid+s]; __syncthreads(); }
    float y0 = red[0] + bi[n*2+0]; __syncthreads();

    red[tid] = p1; __syncthreads();
    #pragma unroll
    for (int s = 128; s > 0; s >>= 1) { if (tid < s) red[tid] += red[tid+s]; __syncthreads(); }
    float y1 = red[0] + bi[n*2+1];

    if (tid == 0) {
        float mx = fmaxf(y0, y1);
        float e0 = __expf(y0 - mx), e1 = __expf(y1 - mx);
        int o;
        o = n*2+0; if (o < osz) out[o] = e0/(e0+e1);
        o = n*2+1; if (o < osz) out[o] = e1/(e0+e1);
    }
}

// ---------------- E5: l_ort + l_pol -----------------------------------
__global__ void finals_kernel(const float* __restrict__ x_tag,
                              float* __restrict__ out, int osz)
{
    const int tid = threadIdx.x;  // 256
    __shared__ float red[256], w[NNODE];

    float s1 = 0.f, s2 = 0.f;
    for (int i = tid; i < 16384; i += 256) {
        s1 += g_G[i]          * g_G[16384 + i];
        s2 += g_G[32768 + i]  * g_G[49152 + i];
    }
    red[tid] = s1; __syncthreads();
    #pragma unroll
    for (int s = 128; s > 0; s >>= 1) { if (tid < s) red[tid] += red[tid+s]; __syncthreads(); }
    float S1 = red[0]; __syncthreads();
    red[tid] = s2; __syncthreads();
    #pragma unroll
    for (int s = 128; s > 0; s >>= 1) { if (tid < s) red[tid] += red[tid+s]; __syncthreads(); }
    float S2 = red[0]; __syncthreads();
    if (tid == 0 && 472 < osz) out[472] = sqrtf(S1) + sqrtf(S2);

    if (tid < NNODE) {
        float nr = 0.f;
        const float* np = g_n + tid*256;
        for (int d = 0; d < 256; d++) nr += np[d]*np[d];
        nr = fmaxf(sqrtf(nr), 1e-8f);
        float diff = x_tag[tid*3+1] - x_tag[tid*3+0];
        float sg = (diff > 0.f ? 1.f : (diff < 0.f ? -1.f : 0.f));
        sg *= (x_tag[tid*3+2] == 0.f) ? 1.f : 0.f;
        w[tid] = sg / nr;
    }
    __syncthreads();
    float v = 0.f;
    for (int i = 0; i < NNODE; i++) v += w[i]*g_n[i*256 + tid];
    red[tid] = v*v; __syncthreads();
    #pragma unroll
    for (int s = 128; s > 0; s >>= 1) { if (tid < s) red[tid] += red[tid+s]; __syncthreads(); }
    if (tid == 0 && 473 < osz) out[473] = red[0];
}

// ---------------- launch ----------------------------------------------
extern "C" void kernel_launch(void* const* d_in, const int* in_sizes, int n_in,
                              void* d_out, int out_size)
{
    const float* x       = (const float*)d_in[0];
    const float* x_tag   = (const float*)d_in[1];
    const float* W_ih0   = (const float*)d_in[2];
    const float* W_hh0   = (const float*)d_in[3];
    const float* b_ih0   = (const float*)d_in[4];
    const float* b_hh0   = (const float*)d_in[5];
    const float* W_ih1   = (const float*)d_in[6];
    const float* W_hh1   = (const float*)d_in[7];
    const float* b_ih1   = (const float*)d_in[8];
    const float* b_hh1   = (const float*)d_in[9];
    const float* pm      = (const float*)d_in[10];
    const float* Wum     = (const float*)d_in[11];
    const float* Wvm     = (const float*)d_in[12];
    const float* Wup     = (const float*)d_in[13];
    const float* Wvp     = (const float*)d_in[14];
    const float* W_hyb   = (const float*)d_in[15];
    const float* b_hyb   = (const float*)d_in[16];
    const float* W_act   = (const float*)d_in[17];
    const float* b_act   = (const float*)d_in[18];
    const float* W_inact = (const float*)d_in[19];
    const float* b_inact = (const float*)d_in[20];
    const float* Wphin   = (const float*)d_in[21];
    const float* aphi    = (const float*)d_in[22];
    const float* Won     = (const float*)d_in[23];
    const float* Weo     = (const float*)d_in[24];
    const float* Wi      = (const float*)d_in[25];
    const float* bi      = (const float*)d_in[26];
    float* out = (float*)d_out;

    float *xpre = nullptr, *h1 = nullptr, *h2last = nullptr;
    cudaGetSymbolAddress((void**)&xpre,   g_xpre);
    cudaGetSymbolAddress((void**)&h1,     g_h1);
    cudaGetSymbolAddress((void**)&h2last, g_h2last);

    cudaFuncSetAttribute(gemm_k, cudaFuncAttributeMaxDynamicSharedMemorySize, GEMM_SMEM);

    dim3 gg(4, M_ROWS/128);

    // layer 0
    gemm_k<<<gg, 256, GEMM_SMEM>>>(x, W_ih0, b_ih0, b_hh0, xpre);
    lstm_rec<1><<<NNODE, 512>>>(xpre, W_hh0, h1);
    // layer 1
    gemm_k<<<gg, 256, GEMM_SMEM>>>(h1, W_ih1, b_ih1, b_hh1, xpre);
    lstm_rec<0><<<NNODE, 512>>>(xpre, W_hh1, h2last);

    // epilogue
    prep_kernel<<<1, 128>>>(x_tag, pm, Wvm, out, out_size);
    gram_kernel<<<512, 128>>>(Wum, Wvm, Wup, Wvp);
    node_kernel<<<NNODE, 256>>>(x_tag, Wup, W_hyb, b_hyb, W_act, b_act, W_inact, b_inact);
    proj_kernel<<<NNODE, 256>>>(Wphin, Won, Weo);
    phi_alpha_kernel<<<NNODE, 128>>>(x_tag, aphi);
    hyper_kernel<<<NNODE, 256>>>(x_tag, Weo, Wi, bi, out, out_size);
    finals_kernel<<<1, 256>>>(x_tag, out, out_size);
}

// round 9
// speedup vs baseline: 1.1699x; 1.1699x over previous
#include <cuda_runtime.h>
#include <math.h>

#define NNODE 118
#define TT 2048
#define M_ROWS (NNODE*TT)

typedef unsigned long long ull;
union F2U { ull u; float2 f; };

__device__ __forceinline__ ull pk2(float x, float y){ ull r; asm("mov.b64 %0, {%1,%2};" : "=l"(r) : "f"(x), "f"(y)); return r; }
__device__ __forceinline__ ull dupf(float x){ ull r; asm("mov.b64 %0, {%1,%1};" : "=l"(r) : "f"(x)); return r; }
__device__ __forceinline__ void fma2(ull& d, ull a, ull b){ asm("fma.rn.f32x2 %0, %1, %2, %0;" : "+l"(d) : "l"(a), "l"(b)); }

// unpack bf16x2 word -> f32x2 (low bf16 = even element)
__device__ __forceinline__ ull unpk(unsigned w){
    unsigned lo = w << 16;
    unsigned hi = w & 0xFFFF0000u;
    ull r; asm("mov.b64 %0, {%1,%2};" : "=l"(r) : "r"(lo), "r"(hi));
    return r;
}
__device__ __forceinline__ unsigned bf1(float f){
    unsigned b = __float_as_uint(f);
    return (b + 0x7FFFu + ((b >> 16) & 1u)) >> 16;   // RNE
}
__device__ __forceinline__ unsigned bfpair(float e, float o){ return bf1(e) | (bf1(o) << 16); }

// column permutation: semantic gate-major n (= g*128+c)  <->  stored col' = 4c+g
__device__ __forceinline__ int invperm(int cp){ return (cp & 3)*128 + (cp >> 2); }

// ---------------- scratch (device globals; no allocation allowed) ----------
__device__ __align__(256) float g_xpre[(size_t)M_ROWS*512];
__device__ __align__(256) float g_h1[(size_t)M_ROWS*128];
__device__ __align__(256) float g_h2last[NNODE*128];
__device__ __align__(256) float g_vm[2*128];
__device__ __align__(256) float g_flag[1];
__device__ __align__(256) float g_n[NNODE*256];
__device__ __align__(256) float g_Pa[NNODE*192];
__device__ __align__(256) float g_Pb[NNODE*192];
__device__ __align__(256) float g_Qa[NNODE*256];
__device__ __align__(256) float g_Qb[NNODE*256];
__device__ __align__(256) float g_Ra[NNODE*256];
__device__ __align__(256) float g_Rb[NNODE*256];
__device__ __align__(256) float g_alpha[NNODE*NNODE];
__device__ __align__(256) float g_G[4*128*128];

__device__ __forceinline__ float leaky(float z){ return z >= 0.f ? z : 0.01f*z; }

// ---------------- GEMM: C(M,512) = A(M,128) @ W(512,128)^T + b1 + b2 -------
// Output columns PERMUTED: stored col' = 4c+g for semantic n = g*128+c.
// Loader: warp covers 8 rows x 4 kg per iteration -> STS banks spread (2-way
// max conflict instead of 16-way).
#define GP2 132
#define GEMM_SMEM (2*128*GP2*4)

__global__ void __launch_bounds__(256) gemm_k(const float* __restrict__ A,
                                              const float* __restrict__ W,
                                              const float* __restrict__ b1,
                                              const float* __restrict__ b2,
                                              float* __restrict__ C)
{
    extern __shared__ float sm[];
    float* As = sm;               // [k][m] pad GP2
    float* Ws = sm + 128*GP2;     // [k][n'] pad GP2
    const int tid = threadIdx.x;
    const int mbase = blockIdx.y * 128;
    const int nbase = blockIdx.x * 128;
    const int l = tid & 31;
    const int w = tid >> 5;

    const float4* A4 = (const float4*)(A + (size_t)mbase*128);
    const float4* W4 = (const float4*)W;
    #pragma unroll
    for (int r = 0; r < 16; r++) {
        int row = 8*w + (l & 7) + 64*(r >> 3);     // 0..127
        int kg  = 4*(r & 7) + (l >> 3);            // 0..31
        float4 va = A4[row*32 + kg];
        As[(4*kg+0)*GP2 + row] = va.x;
        As[(4*kg+1)*GP2 + row] = va.y;
        As[(4*kg+2)*GP2 + row] = va.z;
        As[(4*kg+3)*GP2 + row] = va.w;
        int srow = invperm(nbase + row);           // permuted W row source
        float4 vw = W4[srow*32 + kg];
        Ws[(4*kg+0)*GP2 + row] = vw.x;
        Ws[(4*kg+1)*GP2 + row] = vw.y;
        Ws[(4*kg+2)*GP2 + row] = vw.z;
        Ws[(4*kg+3)*GP2 + row] = vw.w;
    }
    __syncthreads();

    const int tx = tid & 15;   // n micro
    const int ty = tid >> 4;   // m micro
    const int m0 = ty*8, n0 = tx*8;

    F2U acc[4][8];
    #pragma unroll
    for (int p = 0; p < 4; p++)
        #pragma unroll
        for (int j = 0; j < 8; j++) acc[p][j].u = 0ull;

    #pragma unroll 8
    for (int k = 0; k < 128; k++) {
        const float4 a0 = *(const float4*)(As + k*GP2 + m0);
        const float4 a1 = *(const float4*)(As + k*GP2 + m0 + 4);
        const float4 w0 = *(const float4*)(Ws + k*GP2 + n0);
        const float4 w1 = *(const float4*)(Ws + k*GP2 + n0 + 4);
        ull ap0 = pk2(a0.x, a0.y), ap1 = pk2(a0.z, a0.w);
        ull ap2 = pk2(a1.x, a1.y), ap3 = pk2(a1.z, a1.w);
        ull wd;
        wd = dupf(w0.x); fma2(acc[0][0].u, ap0, wd); fma2(acc[1][0].u, ap1, wd); fma2(acc[2][0].u, ap2, wd); fma2(acc[3][0].u, ap3, wd);
        wd = dupf(w0.y); fma2(acc[0][1].u, ap0, wd); fma2(acc[1][1].u, ap1, wd); fma2(acc[2][1].u, ap2, wd); fma2(acc[3][1].u, ap3, wd);
        wd = dupf(w0.z); fma2(acc[0][2].u, ap0, wd); fma2(acc[1][2].u, ap1, wd); fma2(acc[2][2].u, ap2, wd); fma2(acc[3][2].u, ap3, wd);
        wd = dupf(w0.w); fma2(acc[0][3].u, ap0, wd); fma2(acc[1][3].u, ap1, wd); fma2(acc[2][3].u, ap2, wd); fma2(acc[3][3].u, ap3, wd);
        wd = dupf(w1.x); fma2(acc[0][4].u, ap0, wd); fma2(acc[1][4].u, ap1, wd); fma2(acc[2][4].u, ap2, wd); fma2(acc[3][4].u, ap3, wd);
        wd = dupf(w1.y); fma2(acc[0][5].u, ap0, wd); fma2(acc[1][5].u, ap1, wd); fma2(acc[2][5].u, ap2, wd); fma2(acc[3][5].u, ap3, wd);
        wd = dupf(w1.z); fma2(acc[0][6].u, ap0, wd); fma2(acc[1][6].u, ap1, wd); fma2(acc[2][6].u, ap2, wd); fma2(acc[3][6].u, ap3, wd);
        wd = dupf(w1.w); fma2(acc[0][7].u, ap0, wd); fma2(acc[1][7].u, ap1, wd); fma2(acc[2][7].u, ap2, wd); fma2(acc[3][7].u, ap3, wd);
    }

    const int col = nbase + n0;
    float bias[8];
    #pragma unroll
    for (int c = 0; c < 8; c++) {
        int src = invperm(col + c);
        bias[c] = b1[src] + b2[src];
    }

    #pragma unroll
    for (int p = 0; p < 4; p++) {
        float4 o;
        float* r0 = C + (size_t)(mbase + m0 + 2*p)*512 + col;
        float* r1 = r0 + 512;
        o.x = acc[p][0].f.x + bias[0]; o.y = acc[p][1].f.x + bias[1];
        o.z = acc[p][2].f.x + bias[2]; o.w = acc[p][3].f.x + bias[3];
        *(float4*)(r0) = o;
        o.x = acc[p][4].f.x + bias[4]; o.y = acc[p][5].f.x + bias[5];
        o.z = acc[p][6].f.x + bias[6]; o.w = acc[p][7].f.x + bias[7];
        *(float4*)(r0 + 4) = o;
        o.x = acc[p][0].f.y + bias[0]; o.y = acc[p][1].f.y + bias[1];
        o.z = acc[p][2].f.y + bias[2]; o.w = acc[p][3].f.y + bias[3];
        *(float4*)(r1) = o;
        o.x = acc[p][4].f.y + bias[4]; o.y = acc[p][5].f.y + bias[5];
        o.z = acc[p][6].f.y + bias[6]; o.w = acc[p][7].f.y + bias[7];
        *(float4*)(r1 + 4) = o;
    }
}

// ---------------- LSTM recurrence: one block per node ----------------------
// xpre columns permuted (col' = 4c+g) -> thread j reads column j (coalesced).
// Quad {i,f,g,o} of a cell = 4 consecutive lanes -> SHFL update, ONE barrier
// per step, h double-buffered.
// Weight split: k=0..95 fp32 in regs (48 ull = 96 regs), k=96..127 bf16 in
// smem (4 uint4 = 32 KB/block). Maximizes register residency (R8 showed smem
// slices are the expensive resource).
template<int WRITE_ALL>
__global__ void __launch_bounds__(512, 1) lstm_rec(const float* __restrict__ xpre,
                                                   const float* __restrict__ Whh,
                                                   float* __restrict__ hout)
{
    __shared__ __align__(16) float hs[2][128];
    __shared__ __align__(16) uint4 wsb[4*512];   // 32 KB bf16 weight slice

    const int j = threadIdx.x;
    const int n = blockIdx.x;
    const int l = j & 31;
    const int w = j >> 5;
    const int gate = l & 3;
    const int cell = w*8 + (l >> 2);
    const int row  = gate*128 + cell;            // = invperm(j)

    // load weights: row `row` of Whh (128 floats)
    const float* wg = Whh + row*128;
    ull wr[48];                                   // k = 0..95
    #pragma unroll
    for (int g = 0; g < 24; g++) {
        float4 v = *(const float4*)(wg + 4*g);
        wr[2*g]   = pk2(v.x, v.y);
        wr[2*g+1] = pk2(v.z, v.w);
    }
    #pragma unroll
    for (int s = 0; s < 4; s++) {                 // k = 96..127 as bf16
        const float* base = wg + 96 + s*8;
        uint4 pk;
        pk.x = bfpair(base[0], base[1]);
        pk.y = bfpair(base[2], base[3]);
        pk.z = bfpair(base[4], base[5]);
        pk.w = bfpair(base[6], base[7]);
        wsb[s*512 + j] = pk;
    }

    if (j < 128) hs[0][j] = 0.f;
    float c = 0.f;
    __syncthreads();

    const float* xp = xpre + (size_t)n*TT*512 + j;   // coalesced (permuted layout)
    float xnext = xp[0];
    float* hw = hout + (WRITE_ALL ? ((size_t)n*TT*128 + cell) : ((size_t)n*128 + cell));

    int p = 0;
    for (int t = 0; t < TT; t++) {
        F2U A0, A1, A2, A3;
        A0.u = pk2(xnext, 0.f); A1.u = 0ull; A2.u = 0ull; A3.u = 0ull;
        if (t + 1 < TT) xnext = xp[(size_t)(t+1)*512];

        const ulonglong2* h2 = (const ulonglong2*)hs[p];
        #pragma unroll
        for (int g = 0; g < 24; g += 2) {            // k = 0..95
            ulonglong2 hv0 = h2[g];
            ulonglong2 hv1 = h2[g+1];
            fma2(A0.u, wr[2*g],   hv0.x);
            fma2(A1.u, wr[2*g+1], hv0.y);
            fma2(A2.u, wr[2*g+2], hv1.x);
            fma2(A3.u, wr[2*g+3], hv1.y);
        }
        #pragma unroll
        for (int s = 0; s < 4; s++) {                // k = 96..127
            uint4 wv = wsb[s*512 + j];
            ulonglong2 hv0 = h2[24 + 2*s];
            ulonglong2 hv1 = h2[25 + 2*s];
            fma2(A0.u, unpk(wv.x), hv0.x);
            fma2(A1.u, unpk(wv.y), hv0.y);
            fma2(A2.u, unpk(wv.z), hv1.x);
            fma2(A3.u, unpk(wv.w), hv1.y);
        }
        float acc = (A0.f.x + A0.f.y) + (A1.f.x + A1.f.y)
                  + (A2.f.x + A2.f.y) + (A3.f.x + A3.f.y);

        // branch-free activation: sigmoid for i,f,o; tanh = 2*sig(2x)-1 for g
        const bool isg = (gate == 2);
        float u  = isg ? 2.f*acc : acc;
        float e  = __expf(-u);
        float s_ = __fdividef(1.f, 1.f + e);
        float a  = isg ? (2.f*s_ - 1.f) : s_;

        const int base = l & ~3;
        float iv = __shfl_sync(0xFFFFFFFFu, a, base);
        float fv = __shfl_sync(0xFFFFFFFFu, a, base + 1);
        float gv = __shfl_sync(0xFFFFFFFFu, a, base + 2);
        float ov = __shfl_sync(0xFFFFFFFFu, a, base + 3);
        c = fv*c + iv*gv;
        float e2 = __expf(-2.f*c);
        float th = __fdividef(2.f, 1.f + e2) - 1.f;
        float hv = ov * th;
        p ^= 1;
        if (gate == 0) {
            hs[p][cell] = hv;
            if (WRITE_ALL)      hw[(size_t)t*128] = hv;
            else if (t == TT-1) hw[0] = hv;
        }
        __syncthreads();
    }
}

// ---------------- E0: pseudo-message projections + direct outputs ----------
__global__ void prep_kernel(const float* __restrict__ x_tag,
                            const float* __restrict__ pm,
                            const float* __restrict__ Wvm,
                            float* __restrict__ out, int osz)
{
    const int tid = threadIdx.x;  // 128
    __shared__ float pms[768];
    for (int i = tid; i < 768; i += 128) pms[i] = pm[i];
    __syncthreads();

    float base = 0.f;
    for (int k = 0; k < 768; k++) base += pms[k]*Wvm[k*128 + tid];
    g_vm[tid]       = leaky(base);
    g_vm[128 + tid] = leaky(base + Wvm[768*128 + tid]);

    if (tid < NNODE) {
        int o;
        o = 236 + tid*2 + 0; if (o < osz) out[o] = x_tag[tid*3+0];
        o = 236 + tid*2 + 1; if (o < osz) out[o] = x_tag[tid*3+1];
        float a = x_tag[tid*3+2];
        o = 474 + tid; if (o < osz) out[o] = (a == 0.f) ? 1.f : 0.f;
        o = 592 + tid; if (o < osz) out[o] = (a == 1.f) ? 1.f : 0.f;
    }
    if (tid == 0) {
        int cnt = 0;
        for (int i = 0; i < NNODE; i++) if (x_tag[i*3+2] == 0.f) cnt++;
        g_flag[0] = (cnt > 0) ? 1.f : 0.f;
    }
}

// ---------------- Gram matrices for l_ort -----------------------------
__global__ void gram_kernel(const float* __restrict__ Wum, const float* __restrict__ Wvm,
                            const float* __restrict__ Wup, const float* __restrict__ Wvp)
{
    const int bid = blockIdx.x;
    const int mat = bid >> 7;
    const int k   = bid & 127;
    const int l   = threadIdx.x;  // 128
    const float* W; int rows;
    if      (mat == 0) { W = Wum; rows = 769; }
    else if (mat == 1) { W = Wvm; rows = 769; }
    else if (mat == 2) { W = Wup; rows = 128; }
    else               { W = Wvp; rows = 128; }
    float acc = 0.f;
    for (int i = 0; i < rows; i++) acc += W[i*128 + k] * W[i*128 + l];
    g_G[mat*16384 + k*128 + l] = acc;
}

// ---------------- E1: per-node MLP chain -> n -------------------------
__global__ void node_kernel(const float* __restrict__ x_tag,
                            const float* __restrict__ Wup,
                            const float* __restrict__ W_hyb, const float* __restrict__ b_hyb,
                            const float* __restrict__ W_act, const float* __restrict__ b_act,
                            const float* __restrict__ W_inact, const float* __restrict__ b_inact)
{
    const int n = blockIdx.x, tid = threadIdx.x;  // 256
    __shared__ float p[128], up[128], vm_s[128], hh[256];
    const float act = x_tag[n*3+2];
    if (tid < 128) {
        p[tid]    = leaky(g_h2last[n*128 + tid]);
        vm_s[tid] = (act == 1.f) ? g_vm[128 + tid] : g_vm[tid];
    }
    __syncthreads();
    if (tid < 128) {
        float a = 0.f;
        for (int k = 0; k < 128; k++) a += p[k]*Wup[k*128 + tid];
        up[tid] = leaky(a);
    }
    __syncthreads();
    {
        float a = b_hyb[tid];
        for (int k = 0; k < 128; k++) {
            float u_ = up[k], v_ = vm_s[k];
            a += u_*W_hyb[k*256 + tid] + (u_ + v_)*W_hyb[(128+k)*256 + tid] + v_*W_hyb[(256+k)*256 + tid];
        }
        hh[tid] = leaky(a);
    }
    __syncthreads();
    {
        float na = b_act[tid], ni = b_inact[tid];
        for (int k = 0; k < 256; k++) {
            float h_ = hh[k];
            na += h_*W_act[k*256 + tid];
            ni += h_*W_inact[k*256 + tid];
        }
        na += x_tag[n*3+0]*W_act[256*256 + tid] + x_tag[n*3+1]*W_act[257*256 + tid];
        g_n[n*256 + tid] = leaky(na*(1.f - act) + ni*act);
    }
}

// ---------------- E2: per-node pair projections -----------------------
__global__ void proj_kernel(const float* __restrict__ Wphin,
                            const float* __restrict__ Won,
                            const float* __restrict__ Weo)
{
    const int n = blockIdx.x, tid = threadIdx.x;  // 256
    __shared__ float nn_s[256];
    nn_s[tid] = g_n[n*256 + tid];
    __syncthreads();
    if (tid < 192) {
        float pb = 0.f, pa = 0.f;
        for (int k = 0; k < 256; k++) {
            float v = nn_s[k];
            pb += v*Wphin[k*192 + tid];
            pa += v*Wphin[(256+k)*192 + tid];
        }
        g_Pb[n*192 + tid] = pb;
        g_Pa[n*192 + tid] = pa;
    }
    float qb = 0.f, qa = 0.f, rb = 0.f, ra = 0.f;
    for (int k = 0; k < 256; k++) {
        float v = nn_s[k];
        qb += v*Won[k*256 + tid];
        qa += v*Won[(256+k)*256 + tid];
        rb += v*Weo[(256+k)*256 + tid];
        ra += v*Weo[(512+k)*256 + tid];
    }
    g_Qb[n*256 + tid] = qb;
    g_Qa[n*256 + tid] = qa;
    g_Rb[n*256 + tid] = rb;
    g_Ra[n*256 + tid] = ra;
}

// ---------------- E3: phi column + masked softmaxes -> alpha ----------
__device__ __forceinline__ float blockmax128(float v, float* red){
    int tid = threadIdx.x; red[tid] = v; __syncthreads();
    #pragma unroll
    for (int s = 64; s > 0; s >>= 1) { if (tid < s) red[tid] = fmaxf(red[tid], red[tid+s]); __syncthreads(); }
    float r = red[0]; __syncthreads(); return r;
}
__device__ __forceinline__ float blocksum128(float v, float* red){
    int tid = threadIdx.x; red[tid] = v; __syncthreads();
    #pragma unroll
    for (int s = 64; s > 0; s >>= 1) { if (tid < s) red[tid] += red[tid+s]; __syncthreads(); }
    float r = red[0]; __syncthreads(); return r;
}

__global__ void phi_alpha_kernel(const float* __restrict__ x_tag,
                                 const float* __restrict__ aphi)
{
    const int b = blockIdx.x;
    const int tid = threadIdx.x;  // 128
    __shared__ float pb_s[192], ap_s[192], red[128];
    for (int i = tid; i < 192; i += 128) { pb_s[i] = g_Pb[b*192 + i]; ap_s[i] = aphi[i]; }
    __syncthreads();

    float ph = 0.f, v1 = 0.f;
    if (tid < NNODE) {
        const float* pa = g_Pa + tid*192;
        #pragma unroll 8
        for (int d = 0; d < 192; d++) ph += leaky(pb_s[d] + pa[d]) * ap_s[d];
        v1 = (x_tag[tid*3+2] == 0.f) ? 1.f : 0.f;
    }

    const float NEG = -1000000000.f;
    float m1 = (tid < NNODE) ? (v1 > 0.f ? ph : NEG) : -INFINITY;
    float m0 = (tid < NNODE) ? (v1 > 0.f ? NEG : ph) : -INFINITY;
    float ma = (tid < NNODE) ? ph : -INFINITY;

    float mx = blockmax128(m1, red);
    float e  = (tid < NNODE) ? __expf(m1 - mx) : 0.f;
    float s  = blocksum128(e, red);
    float sm1 = e / s;

    mx = blockmax128(m0, red);
    e  = (tid < NNODE) ? __expf(m0 - mx) : 0.f;
    s  = blocksum128(e, red);
    float sm0 = e / s;

    mx = blockmax128(ma, red);
    e  = (tid < NNODE) ? __expf(ma - mx) : 0.f;
    s  = blocksum128(e, red);
    float sma = e / s;

    if (tid < NNODE) {
        float a = (g_flag[0] > 0.f) ? (v1 > 0.f ? sm1 : sm0) : sma;
        g_alpha[tid*NNODE + b] = a;
    }
}

// ---------------- E4: hyper messages + y_hat --------------------------
__global__ void hyper_kernel(const float* __restrict__ x_tag,
                             const float* __restrict__ Weo,
                             const float* __restrict__ Wi,
                             const float* __restrict__ bi,
                             float* __restrict__ out, int osz)
{
    const int n = blockIdx.x, tid = threadIdx.x;  // 256
    __shared__ float qa[256], ra[256], nn_s[256], u[256], al[NNODE], red[256];
    qa[tid]   = g_Qa[n*256 + tid];
    ra[tid]   = g_Ra[n*256 + tid];
    nn_s[tid] = g_n[n*256 + tid];
    if (tid < NNODE) al[tid] = g_alpha[n*NNODE + tid];
    __syncthreads();

    float uacc = 0.f, racc = 0.f, alsum = 0.f;
    const float qad = qa[tid];
    for (int j = 0; j < NNODE; j++) {
        float a_ = al[j];
        uacc  += a_ * leaky(g_Qb[j*256 + tid] + qad);
        racc  += a_ * g_Rb[j*256 + tid];
        alsum += a_;
    }
    u[tid] = uacc;
    __syncthreads();

    float T = racc + alsum*ra[tid];
    for (int k = 0; k < 256; k++) T += u[k]*Weo[k*256 + tid];

    const float act = x_tag[n*3+2];
    float hm0 = leaky(act*T);
    float hm1 = leaky((1.f - act)*T);

    const float* Win = Wi + (size_t)n*768*2;
    float p0 = nn_s[tid]*Win[tid*2+0] + hm0*Win[(256+tid)*2+0] + hm1*Win[(512+tid)*2+0];
    float p1 = nn_s[tid]*Win[tid*2+1] + hm0*Win[(256+tid)*2+1] + hm1*Win[(512+tid)*2+1];

    red[tid] = p0; __syncthreads();
    #pragma unroll
    for (int s = 128; s > 0; s >>= 1) { if (tid < s) red[tid] += red[tid+s]; __syncthreads(); }
    float y0 = red[0] + bi[n*2+0]; __syncthreads();

    red[tid] = p1; __syncthreads();
    #pragma unroll
    for (int s = 128; s > 0; s >>= 1) { if (tid < s) red[tid] += red[tid+s]; __syncthreads(); }
    float y1 = red[0] + bi[n*2+1];

    if (tid == 0) {
        float mx = fmaxf(y0, y1);
        float e0 = __expf(y0 - mx), e1 = __expf(y1 - mx);
        int o;
        o = n*2+0; if (o < osz) out[o] = e0/(e0+e1);
        o = n*2+1; if (o < osz) out[o] = e1/(e0+e1);
    }
}

// ---------------- E5: l_ort + l_pol -----------------------------------
__global__ void finals_kernel(const float* __restrict__ x_tag,
                              float* __restrict__ out, int osz)
{
    const int tid = threadIdx.x;  // 256
    __shared__ float red[256], w[NNODE];

    float s1 = 0.f, s2 = 0.f;
    for (int i = tid; i < 16384; i += 256) {
        s1 += g_G[i]          * g_G[16384 + i];
        s2 += g_G[32768 + i]  * g_G[49152 + i];
    }
    red[tid] = s1; __syncthreads();
    #pragma unroll
    for (int s = 128; s > 0; s >>= 1) { if (tid < s) red[tid] += red[tid+s]; __syncthreads(); }
    float S1 = red[0]; __syncthreads();
    red[tid] = s2; __syncthreads();
    #pragma unroll
    for (int s = 128; s > 0; s >>= 1) { if (tid < s) red[tid] += red[tid+s]; __syncthreads(); }
    float S2 = red[0]; __syncthreads();
    if (tid == 0 && 472 < osz) out[472] = sqrtf(S1) + sqrtf(S2);

    if (tid < NNODE) {
        float nr = 0.f;
        const float* np = g_n + tid*256;
        for (int d = 0; d < 256; d++) nr += np[d]*np[d];
        nr = fmaxf(sqrtf(nr), 1e-8f);
        float diff = x_tag[tid*3+1] - x_tag[tid*3+0];
        float sg = (diff > 0.f ? 1.f : (diff < 0.f ? -1.f : 0.f));
        sg *= (x_tag[tid*3+2] == 0.f) ? 1.f : 0.f;
        w[tid] = sg / nr;
    }
    __syncthreads();
    float v = 0.f;
    for (int i = 0; i < NNODE; i++) v += w[i]*g_n[i*256 + tid];
    red[tid] = v*v; __syncthreads();
    #pragma unroll
    for (int s = 128; s > 0; s >>= 1) { if (tid < s) red[tid] += red[tid+s]; __syncthreads(); }
    if (tid == 0 && 473 < osz) out[473] = red[0];
}

// ---------------- launch ----------------------------------------------
extern "C" void kernel_launch(void* const* d_in, const int* in_sizes, int n_in,
                              void* d_out, int out_size)
{
    const float* x       = (const float*)d_in[0];
    const float* x_tag   = (const float*)d_in[1];
    const float* W_ih0   = (const float*)d_in[2];
    const float* W_hh0   = (const float*)d_in[3];
    const float* b_ih0   = (const float*)d_in[4];
    const float* b_hh0   = (const float*)d_in[5];
    const float* W_ih1   = (const float*)d_in[6];
    const float* W_hh1   = (const float*)d_in[7];
    const float* b_ih1   = (const float*)d_in[8];
    const float* b_hh1   = (const float*)d_in[9];
    const float* pm      = (const float*)d_in[10];
    const float* Wum     = (const float*)d_in[11];
    const float* Wvm     = (const float*)d_in[12];
    const float* Wup     = (const float*)d_in[13];
    const float* Wvp     = (const float*)d_in[14];
    const float* W_hyb   = (const float*)d_in[15];
    const float* b_hyb   = (const float*)d_in[16];
    const float* W_act   = (const float*)d_in[17];
    const float* b_act   = (const float*)d_in[18];
    const float* W_inact = (const float*)d_in[19];
    const float* b_inact = (const float*)d_in[20];
    const float* Wphin   = (const float*)d_in[21];
    const float* aphi    = (const float*)d_in[22];
    const float* Won     = (const float*)d_in[23];
    const float* Weo     = (const float*)d_in[24];
    const float* Wi      = (const float*)d_in[25];
    const float* bi      = (const float*)d_in[26];
    float* out = (float*)d_out;

    float *xpre = nullptr, *h1 = nullptr, *h2last = nullptr;
    cudaGetSymbolAddress((void**)&xpre,   g_xpre);
    cudaGetSymbolAddress((void**)&h1,     g_h1);
    cudaGetSymbolAddress((void**)&h2last, g_h2last);

    cudaFuncSetAttribute(gemm_k, cudaFuncAttributeMaxDynamicSharedMemorySize, GEMM_SMEM);

    dim3 gg(4, M_ROWS/128);

    // layer 0
    gemm_k<<<gg, 256, GEMM_SMEM>>>(x, W_ih0, b_ih0, b_hh0, xpre);
    lstm_rec<1><<<NNODE, 512>>>(xpre, W_hh0, h1);
    // layer 1
    gemm_k<<<gg, 256, GEMM_SMEM>>>(h1, W_ih1, b_ih1, b_hh1, xpre);
    lstm_rec<0><<<NNODE, 512>>>(xpre, W_hh1, h2last);

    // epilogue
    prep_kernel<<<1, 128>>>(x_tag, pm, Wvm, out, out_size);
    gram_kernel<<<512, 128>>>(Wum, Wvm, Wup, Wvp);
    node_kernel<<<NNODE, 256>>>(x_tag, Wup, W_hyb, b_hyb, W_act, b_act, W_inact, b_inact);
    proj_kernel<<<NNODE, 256>>>(Wphin, Won, Weo);
    phi_alpha_kernel<<<NNODE, 128>>>(x_tag, aphi);
    hyper_kernel<<<NNODE, 256>>>(x_tag, Weo, Wi, bi, out, out_size);
    finals_kernel<<<1, 256>>>(x_tag, out, out_size);
}

// round 10
// speedup vs baseline: 1.2367x; 1.0571x over previous
#include <cuda_runtime.h>
#include <math.h>

#define NNODE 118
#define TT 2048
#define M_ROWS (NNODE*TT)

typedef unsigned long long ull;
union F2U { ull u; float2 f; };

__device__ __forceinline__ ull pk2(float x, float y){ ull r; asm("mov.b64 %0, {%1,%2};" : "=l"(r) : "f"(x), "f"(y)); return r; }
__device__ __forceinline__ ull dupf(float x){ ull r; asm("mov.b64 %0, {%1,%1};" : "=l"(r) : "f"(x)); return r; }
__device__ __forceinline__ void fma2(ull& d, ull a, ull b){ asm("fma.rn.f32x2 %0, %1, %2, %0;" : "+l"(d) : "l"(a), "l"(b)); }
__device__ __forceinline__ ull add2(ull a, ull b){ ull r; asm("add.rn.f32x2 %0, %1, %2;" : "=l"(r) : "l"(a), "l"(b)); return r; }

// unpack bf16x2 word -> f32x2 (low bf16 = even element)
__device__ __forceinline__ ull unpk(unsigned w){
    unsigned lo = w << 16;
    unsigned hi = w & 0xFFFF0000u;
    ull r; asm("mov.b64 %0, {%1,%2};" : "=l"(r) : "r"(lo), "r"(hi));
    return r;
}
__device__ __forceinline__ unsigned bf1(float f){
    unsigned b = __float_as_uint(f);
    return (b + 0x7FFFu + ((b >> 16) & 1u)) >> 16;   // RNE
}
__device__ __forceinline__ unsigned bfpair(float e, float o){ return bf1(e) | (bf1(o) << 16); }

__device__ __forceinline__ ull shfl_xor64(ull v, int m){
    unsigned lo = (unsigned)v, hi = (unsigned)(v >> 32);
    lo = __shfl_xor_sync(0xFFFFFFFFu, lo, m);
    hi = __shfl_xor_sync(0xFFFFFFFFu, hi, m);
    return ((ull)hi << 32) | lo;
}

// column permutation: semantic gate-major n (= g*128+c)  <->  stored col' = 4c+g
__device__ __forceinline__ int invperm(int cp){ return (cp & 3)*128 + (cp >> 2); }

// ---------------- scratch (device globals; no allocation allowed) ----------
__device__ __align__(256) float g_xpre[(size_t)M_ROWS*512];
__device__ __align__(256) float g_h1[(size_t)M_ROWS*128];
__device__ __align__(256) float g_h2last[NNODE*128];
__device__ __align__(256) float g_vm[2*128];
__device__ __align__(256) float g_flag[1];
__device__ __align__(256) float g_n[NNODE*256];
__device__ __align__(256) float g_Pa[NNODE*192];
__device__ __align__(256) float g_Pb[NNODE*192];
__device__ __align__(256) float g_Qa[NNODE*256];
__device__ __align__(256) float g_Qb[NNODE*256];
__device__ __align__(256) float g_Ra[NNODE*256];
__device__ __align__(256) float g_Rb[NNODE*256];
__device__ __align__(256) float g_alpha[NNODE*NNODE];
__device__ __align__(256) float g_G[4*128*128];

__device__ __forceinline__ float leaky(float z){ return z >= 0.f ? z : 0.01f*z; }

// ---------------- GEMM: C(M,512) = A(M,128) @ W(512,128)^T + b1 + b2 -------
#define GP2 132
#define GEMM_SMEM (2*128*GP2*4)

__global__ void __launch_bounds__(256) gemm_k(const float* __restrict__ A,
                                              const float* __restrict__ W,
                                              const float* __restrict__ b1,
                                              const float* __restrict__ b2,
                                              float* __restrict__ C)
{
    extern __shared__ float sm[];
    float* As = sm;               // [k][m] pad GP2
    float* Ws = sm + 128*GP2;     // [k][n'] pad GP2
    const int tid = threadIdx.x;
    const int mbase = blockIdx.y * 128;
    const int nbase = blockIdx.x * 128;
    const int l = tid & 31;
    const int w = tid >> 5;

    const float4* A4 = (const float4*)(A + (size_t)mbase*128);
    const float4* W4 = (const float4*)W;
    #pragma unroll
    for (int r = 0; r < 16; r++) {
        int row = 8*w + (l & 7) + 64*(r >> 3);     // 0..127
        int kg  = 4*(r & 7) + (l >> 3);            // 0..31
        float4 va = A4[row*32 + kg];
        As[(4*kg+0)*GP2 + row] = va.x;
        As[(4*kg+1)*GP2 + row] = va.y;
        As[(4*kg+2)*GP2 + row] = va.z;
        As[(4*kg+3)*GP2 + row] = va.w;
        int srow = invperm(nbase + row);           // permuted W row source
        float4 vw = W4[srow*32 + kg];
        Ws[(4*kg+0)*GP2 + row] = vw.x;
        Ws[(4*kg+1)*GP2 + row] = vw.y;
        Ws[(4*kg+2)*GP2 + row] = vw.z;
        Ws[(4*kg+3)*GP2 + row] = vw.w;
    }
    __syncthreads();

    const int tx = tid & 15;   // n micro
    const int ty = tid >> 4;   // m micro
    const int m0 = ty*8, n0 = tx*8;

    F2U acc[4][8];
    #pragma unroll
    for (int p = 0; p < 4; p++)
        #pragma unroll
        for (int j = 0; j < 8; j++) acc[p][j].u = 0ull;

    #pragma unroll 8
    for (int k = 0; k < 128; k++) {
        const float4 a0 = *(const float4*)(As + k*GP2 + m0);
        const float4 a1 = *(const float4*)(As + k*GP2 + m0 + 4);
        const float4 w0 = *(const float4*)(Ws + k*GP2 + n0);
        const float4 w1 = *(const float4*)(Ws + k*GP2 + n0 + 4);
        ull ap0 = pk2(a0.x, a0.y), ap1 = pk2(a0.z, a0.w);
        ull ap2 = pk2(a1.x, a1.y), ap3 = pk2(a1.z, a1.w);
        ull wd;
        wd = dupf(w0.x); fma2(acc[0][0].u, ap0, wd); fma2(acc[1][0].u, ap1, wd); fma2(acc[2][0].u, ap2, wd); fma2(acc[3][0].u, ap3, wd);
        wd = dupf(w0.y); fma2(acc[0][1].u, ap0, wd); fma2(acc[1][1].u, ap1, wd); fma2(acc[2][1].u, ap2, wd); fma2(acc[3][1].u, ap3, wd);
        wd = dupf(w0.z); fma2(acc[0][2].u, ap0, wd); fma2(acc[1][2].u, ap1, wd); fma2(acc[2][2].u, ap2, wd); fma2(acc[3][2].u, ap3, wd);
        wd = dupf(w0.w); fma2(acc[0][3].u, ap0, wd); fma2(acc[1][3].u, ap1, wd); fma2(acc[2][3].u, ap2, wd); fma2(acc[3][3].u, ap3, wd);
        wd = dupf(w1.x); fma2(acc[0][4].u, ap0, wd); fma2(acc[1][4].u, ap1, wd); fma2(acc[2][4].u, ap2, wd); fma2(acc[3][4].u, ap3, wd);
        wd = dupf(w1.y); fma2(acc[0][5].u, ap0, wd); fma2(acc[1][5].u, ap1, wd); fma2(acc[2][5].u, ap2, wd); fma2(acc[3][5].u, ap3, wd);
        wd = dupf(w1.z); fma2(acc[0][6].u, ap0, wd); fma2(acc[1][6].u, ap1, wd); fma2(acc[2][6].u, ap2, wd); fma2(acc[3][6].u, ap3, wd);
        wd = dupf(w1.w); fma2(acc[0][7].u, ap0, wd); fma2(acc[1][7].u, ap1, wd); fma2(acc[2][7].u, ap2, wd); fma2(acc[3][7].u, ap3, wd);
    }

    const int col = nbase + n0;
    float bias[8];
    #pragma unroll
    for (int c = 0; c < 8; c++) {
        int src = invperm(col + c);
        bias[c] = b1[src] + b2[src];
    }

    #pragma unroll
    for (int p = 0; p < 4; p++) {
        float4 o;
        float* r0 = C + (size_t)(mbase + m0 + 2*p)*512 + col;
        float* r1 = r0 + 512;
        o.x = acc[p][0].f.x + bias[0]; o.y = acc[p][1].f.x + bias[1];
        o.z = acc[p][2].f.x + bias[2]; o.w = acc[p][3].f.x + bias[3];
        *(float4*)(r0) = o;
        o.x = acc[p][4].f.x + bias[4]; o.y = acc[p][5].f.x + bias[5];
        o.z = acc[p][6].f.x + bias[6]; o.w = acc[p][7].f.x + bias[7];
        *(float4*)(r0 + 4) = o;
        o.x = acc[p][0].f.y + bias[0]; o.y = acc[p][1].f.y + bias[1];
        o.z = acc[p][2].f.y + bias[2]; o.w = acc[p][3].f.y + bias[3];
        *(float4*)(r1) = o;
        o.x = acc[p][4].f.y + bias[4]; o.y = acc[p][5].f.y + bias[5];
        o.z = acc[p][6].f.y + bias[6]; o.w = acc[p][7].f.y + bias[7];
        *(float4*)(r1 + 4) = o;
    }
}

// ---------------- LSTM recurrence: one block per node ----------------------
// Quad-k-split: the 4 lanes of a quad (= 4 gates of cell) each take k-slice
// [32q, 32q+32) and compute partials for ALL 4 gate rows over that slice;
// a 2-round shfl_xor transpose-reduce gives lane q the full dot for gate q.
// h stored in smem with per-slice-block rotation (8q words) so the 4 slice
// addresses hit disjoint bank groups -> 1 wavefront per h load instruction.
// Weights: gates 0..2 fp32 in regs (96 regs), gate 3 bf16 in smem.
template<int WRITE_ALL>
__global__ void __launch_bounds__(512, 1) lstm_rec(const float* __restrict__ xpre,
                                                   const float* __restrict__ Whh,
                                                   float* __restrict__ hout)
{
    __shared__ __align__(16) float hs[2][128];
    __shared__ __align__(16) uint4 wsb[4*512];   // 32 KB bf16 gate-3 weights

    const int j = threadIdx.x;
    const int n = blockIdx.x;
    const int l = j & 31;
    const int w = j >> 5;
    const int q = l & 3;                          // gate index AND k-slice index
    const int cell = w*8 + (l >> 2);

    // weights: rows g*128+cell, k-slice [32q, 32q+32)
    ull wr[48];                                   // g = 0..2
    #pragma unroll
    for (int g = 0; g < 3; g++) {
        const float* wp = Whh + (g*128 + cell)*128 + 32*q;
        #pragma unroll
        for (int i = 0; i < 8; i++) {
            float4 v = *(const float4*)(wp + 4*i);
            wr[g*16 + 2*i]     = pk2(v.x, v.y);
            wr[g*16 + 2*i + 1] = pk2(v.z, v.w);
        }
    }
    {
        const float* wp = Whh + (3*128 + cell)*128 + 32*q;
        #pragma unroll
        for (int s = 0; s < 4; s++) {
            uint4 pkv;
            pkv.x = bfpair(wp[8*s+0], wp[8*s+1]);
            pkv.y = bfpair(wp[8*s+2], wp[8*s+3]);
            pkv.z = bfpair(wp[8*s+4], wp[8*s+5]);
            pkv.w = bfpair(wp[8*s+6], wp[8*s+7]);
            wsb[s*512 + j] = pkv;
        }
    }

    if (j < 128) { hs[0][j] = 0.f; hs[1][j] = 0.f; }
    float c = 0.f;
    __syncthreads();

    const float* xp = xpre + (size_t)n*TT*512 + j;   // coalesced (permuted layout)
    float xnext = xp[0];
    float* hw = hout + (WRITE_ALL ? ((size_t)n*TT*128 + cell) : ((size_t)n*128 + cell));

    // swizzled write slot for this thread's h (only gate-0 lanes use it)
    const int wblk = cell >> 5;
    const int wslot = wblk*32 + (((cell & 31) + 8*wblk) & 31);

    int p = 0;
    for (int t = 0; t < TT; t++) {
        F2U A0, A1, A2, A3;
        A0.u = 0ull; A1.u = 0ull; A2.u = 0ull; A3.u = 0ull;
        float xcur = xnext;
        if (t + 1 < TT) xnext = xp[(size_t)(t+1)*512];

        const float* hb = hs[p] + q*32;
        #pragma unroll
        for (int s = 0; s < 4; s++) {
            uint4 wv = wsb[s*512 + j];
            // chunk i = 2s
            {
                int off = (8*s + 8*q) & 31;
                ulonglong2 hv = *(const ulonglong2*)(hb + off);
                fma2(A0.u, wr[4*s],      hv.x); fma2(A0.u, wr[4*s+1],      hv.y);
                fma2(A1.u, wr[16+4*s],   hv.x); fma2(A1.u, wr[16+4*s+1],   hv.y);
                fma2(A2.u, wr[32+4*s],   hv.x); fma2(A2.u, wr[32+4*s+1],   hv.y);
                fma2(A3.u, unpk(wv.x),   hv.x); fma2(A3.u, unpk(wv.y),     hv.y);
            }
            // chunk i = 2s+1
            {
                int off = (8*s + 4 + 8*q) & 31;
                ulonglong2 hv = *(const ulonglong2*)(hb + off);
                fma2(A0.u, wr[4*s+2],    hv.x); fma2(A0.u, wr[4*s+3],      hv.y);
                fma2(A1.u, wr[16+4*s+2], hv.x); fma2(A1.u, wr[16+4*s+3],   hv.y);
                fma2(A2.u, wr[32+4*s+2], hv.x); fma2(A2.u, wr[32+4*s+3],   hv.y);
                fma2(A3.u, unpk(wv.z),   hv.x); fma2(A3.u, unpk(wv.w),     hv.y);
            }
        }

        float p0 = A0.f.x + A0.f.y;
        float p1 = A1.f.x + A1.f.y;
        float p2 = A2.f.x + A2.f.y;
        float p3 = A3.f.x + A3.f.y;

        // quad transpose-reduce: lane q ends with full dot for gate q
        ull lo = pk2(p0, p1), hi = pk2(p2, p3);
        ull send = (l & 2) ? lo : hi;
        ull recv = shfl_xor64(send, 2);
        ull keep = (l & 2) ? hi : lo;
        F2U s2; s2.u = add2(keep, recv);
        float mine  = (l & 1) ? s2.f.y : s2.f.x;
        float sendf = (l & 1) ? s2.f.x : s2.f.y;
        float other = __shfl_xor_sync(0xFFFFFFFFu, sendf, 1);
        float acc = mine + other + xcur;

        // branch-free activation: sigmoid for i,f,o; tanh = 2*sig(2x)-1 for g
        const bool isg = (q == 2);
        float u  = isg ? 2.f*acc : acc;
        float e  = __expf(-u);
        float s_ = __fdividef(1.f, 1.f + e);
        float a  = isg ? (2.f*s_ - 1.f) : s_;

        const int base = l & ~3;
        float iv = __shfl_sync(0xFFFFFFFFu, a, base);
        float fv = __shfl_sync(0xFFFFFFFFu, a, base + 1);
        float gv = __shfl_sync(0xFFFFFFFFu, a, base + 2);
        float ov = __shfl_sync(0xFFFFFFFFu, a, base + 3);
        c = fv*c + iv*gv;
        float e2 = __expf(-2.f*c);
        float th = __fdividef(2.f, 1.f + e2) - 1.f;
        float hv = ov * th;
        p ^= 1;
        if (q == 0) {
            hs[p][wslot] = hv;
            if (WRITE_ALL)      hw[(size_t)t*128] = hv;
            else if (t == TT-1) hw[0] = hv;
        }
        __syncthreads();
    }
}

// ---------------- E0: pseudo-message projections + direct outputs ----------
__global__ void prep_kernel(const float* __restrict__ x_tag,
                            const float* __restrict__ pm,
                            const float* __restrict__ Wvm,
                            float* __restrict__ out, int osz)
{
    const int tid = threadIdx.x;  // 128
    __shared__ float pms[768];
    for (int i = tid; i < 768; i += 128) pms[i] = pm[i];
    __syncthreads();

    float base = 0.f;
    for (int k = 0; k < 768; k++) base += pms[k]*Wvm[k*128 + tid];
    g_vm[tid]       = leaky(base);
    g_vm[128 + tid] = leaky(base + Wvm[768*128 + tid]);

    if (tid < NNODE) {
        int o;
        o = 236 + tid*2 + 0; if (o < osz) out[o] = x_tag[tid*3+0];
        o = 236 + tid*2 + 1; if (o < osz) out[o] = x_tag[tid*3+1];
        float a = x_tag[tid*3+2];
        o = 474 + tid; if (o < osz) out[o] = (a == 0.f) ? 1.f : 0.f;
        o = 592 + tid; if (o < osz) out[o] = (a == 1.f) ? 1.f : 0.f;
    }
    if (tid == 0) {
        int cnt = 0;
        for (int i = 0; i < NNODE; i++) if (x_tag[i*3+2] == 0.f) cnt++;
        g_flag[0] = (cnt > 0) ? 1.f : 0.f;
    }
}

// ---------------- Gram matrices for l_ort -----------------------------
__global__ void gram_kernel(const float* __restrict__ Wum, const float* __restrict__ Wvm,
                            const float* __restrict__ Wup, const float* __restrict__ Wvp)
{
    const int bid = blockIdx.x;
    const int mat = bid >> 7;
    const int k   = bid & 127;
    const int l   = threadIdx.x;  // 128
    const float* W; int rows;
    if      (mat == 0) { W = Wum; rows = 769; }
    else if (mat == 1) { W = Wvm; rows = 769; }
    else if (mat == 2) { W = Wup; rows = 128; }
    else               { W = Wvp; rows = 128; }
    float acc = 0.f;
    for (int i = 0; i < rows; i++) acc += W[i*128 + k] * W[i*128 + l];
    g_G[mat*16384 + k*128 + l] = acc;
}

// ---------------- E1: per-node MLP chain -> n -------------------------
__global__ void node_kernel(const float* __restrict__ x_tag,
                            const float* __restrict__ Wup,
                            const float* __restrict__ W_hyb, const float* __restrict__ b_hyb,
                            const float* __restrict__ W_act, const float* __restrict__ b_act,
                            const float* __restrict__ W_inact, const float* __restrict__ b_inact)
{
    const int n = blockIdx.x, tid = threadIdx.x;  // 256
    __shared__ float p[128], up[128], vm_s[128], hh[256];
    const float act = x_tag[n*3+2];
    if (tid < 128) {
        p[tid]    = leaky(g_h2last[n*128 + tid]);
        vm_s[tid] = (act == 1.f) ? g_vm[128 + tid] : g_vm[tid];
    }
    __syncthreads();
    if (tid < 128) {
        float a = 0.f;
        for (int k = 0; k < 128; k++) a += p[k]*Wup[k*128 + tid];
        up[tid] = leaky(a);
    }
    __syncthreads();
    {
        float a = b_hyb[tid];
        for (int k = 0; k < 128; k++) {
            float u_ = up[k], v_ = vm_s[k];
            a += u_*W_hyb[k*256 + tid] + (u_ + v_)*W_hyb[(128+k)*256 + tid] + v_*W_hyb[(256+k)*256 + tid];
        }
        hh[tid] = leaky(a);
    }
    __syncthreads();
    {
        float na = b_act[tid], ni = b_inact[tid];
        for (int k = 0; k < 256; k++) {
            float h_ = hh[k];
            na += h_*W_act[k*256 + tid];
            ni += h_*W_inact[k*256 + tid];
        }
        na += x_tag[n*3+0]*W_act[256*256 + tid] + x_tag[n*3+1]*W_act[257*256 + tid];
        g_n[n*256 + tid] = leaky(na*(1.f - act) + ni*act);
    }
}

// ---------------- E2: per-node pair projections -----------------------
__global__ void proj_kernel(const float* __restrict__ Wphin,
                            const float* __restrict__ Won,
                            const float* __restrict__ Weo)
{
    const int n = blockIdx.x, tid = threadIdx.x;  // 256
    __shared__ float nn_s[256];
    nn_s[tid] = g_n[n*256 + tid];
    __syncthreads();
    if (tid < 192) {
        float pb = 0.f, pa = 0.f;
        for (int k = 0; k < 256; k++) {
            float v = nn_s[k];
            pb += v*Wphin[k*192 + tid];
            pa += v*Wphin[(256+k)*192 + tid];
        }
        g_Pb[n*192 + tid] = pb;
        g_Pa[n*192 + tid] = pa;
    }
    float qb = 0.f, qa = 0.f, rb = 0.f, ra = 0.f;
    for (int k = 0; k < 256; k++) {
        float v = nn_s[k];
        qb += v*Won[k*256 + tid];
        qa += v*Won[(256+k)*256 + tid];
        rb += v*Weo[(256+k)*256 + tid];
        ra += v*Weo[(512+k)*256 + tid];
    }
    g_Qb[n*256 + tid] = qb;
    g_Qa[n*256 + tid] = qa;
    g_Rb[n*256 + tid] = rb;
    g_Ra[n*256 + tid] = ra;
}

// ---------------- E3: phi column + masked softmaxes -> alpha ----------
__device__ __forceinline__ float blockmax128(float v, float* red){
    int tid = threadIdx.x; red[tid] = v; __syncthreads();
    #pragma unroll
    for (int s = 64; s > 0; s >>= 1) { if (tid < s) red[tid] = fmaxf(red[tid], red[tid+s]); __syncthreads(); }
    float r = red[0]; __syncthreads(); return r;
}
__device__ __forceinline__ float blocksum128(float v, float* red){
    int tid = threadIdx.x; red[tid] = v; __syncthreads();
    #pragma unroll
    for (int s = 64; s > 0; s >>= 1) { if (tid < s) red[tid] += red[tid+s]; __syncthreads(); }
    float r = red[0]; __syncthreads(); return r;
}

__global__ void phi_alpha_kernel(const float* __restrict__ x_tag,
                                 const float* __restrict__ aphi)
{
    const int b = blockIdx.x;
    const int tid = threadIdx.x;  // 128
    __shared__ float pb_s[192], ap_s[192], red[128];
    for (int i = tid; i < 192; i += 128) { pb_s[i] = g_Pb[b*192 + i]; ap_s[i] = aphi[i]; }
    __syncthreads();

    float ph = 0.f, v1 = 0.f;
    if (tid < NNODE) {
        const float* pa = g_Pa + tid*192;
        #pragma unroll 8
        for (int d = 0; d < 192; d++) ph += leaky(pb_s[d] + pa[d]) * ap_s[d];
        v1 = (x_tag[tid*3+2] == 0.f) ? 1.f : 0.f;
    }

    const float NEG = -1000000000.f;
    float m1 = (tid < NNODE) ? (v1 > 0.f ? ph : NEG) : -INFINITY;
    float m0 = (tid < NNODE) ? (v1 > 0.f ? NEG : ph) : -INFINITY;
    float ma = (tid < NNODE) ? ph : -INFINITY;

    float mx = blockmax128(m1, red);
    float e  = (tid < NNODE) ? __expf(m1 - mx) : 0.f;
    float s  = blocksum128(e, red);
    float sm1 = e / s;

    mx = blockmax128(m0, red);
    e  = (tid < NNODE) ? __expf(m0 - mx) : 0.f;
    s  = blocksum128(e, red);
    float sm0 = e / s;

    mx = blockmax128(ma, red);
    e  = (tid < NNODE) ? __expf(ma - mx) : 0.f;
    s  = blocksum128(e, red);
    float sma = e / s;

    if (tid < NNODE) {
        float a = (g_flag[0] > 0.f) ? (v1 > 0.f ? sm1 : sm0) : sma;
        g_alpha[tid*NNODE + b] = a;
    }
}

// ---------------- E4: hyper messages + y_hat --------------------------
__global__ void hyper_kernel(const float* __restrict__ x_tag,
                             const float* __restrict__ Weo,
                             const float* __restrict__ Wi,
                             const float* __restrict__ bi,
                             float* __restrict__ out, int osz)
{
    const int n = blockIdx.x, tid = threadIdx.x;  // 256
    __shared__ float qa[256], ra[256], nn_s[256], u[256], al[NNODE], red[256];
    qa[tid]   = g_Qa[n*256 + tid];
    ra[tid]   = g_Ra[n*256 + tid];
    nn_s[tid] = g_n[n*256 + tid];
    if (tid < NNODE) al[tid] = g_alpha[n*NNODE + tid];
    __syncthreads();

    float uacc = 0.f, racc = 0.f, alsum = 0.f;
    const float qad = qa[tid];
    for (int j = 0; j < NNODE; j++) {
        float a_ = al[j];
        uacc  += a_ * leaky(g_Qb[j*256 + tid] + qad);
        racc  += a_ * g_Rb[j*256 + tid];
        alsum += a_;
    }
    u[tid] = uacc;
    __syncthreads();

    float T = racc + alsum*ra[tid];
    for (int k = 0; k < 256; k++) T += u[k]*Weo[k*256 + tid];

    const float act = x_tag[n*3+2];
    float hm0 = leaky(act*T);
    float hm1 = leaky((1.f - act)*T);

    const float* Win = Wi + (size_t)n*768*2;
    float p0 = nn_s[tid]*Win[tid*2+0] + hm0*Win[(256+tid)*2+0] + hm1*Win[(512+tid)*2+0];
    float p1 = nn_s[tid]*Win[tid*2+1] + hm0*Win[(256+tid)*2+1] + hm1*Win[(512+tid)*2+1];

    red[tid] = p0; __syncthreads();
    #pragma unroll
    for (int s = 128; s > 0; s >>= 1) { if (tid < s) red[tid] += red[tid+s]; __syncthreads(); }
    float y0 = red[0] + bi[n*2+0]; __syncthreads();

    red[tid] = p1; __syncthreads();
    #pragma unroll
    for (int s = 128; s > 0; s >>= 1) { if (tid < s) red[tid] += red[tid+s]; __syncthreads(); }
    float y1 = red[0] + bi[n*2+1];

    if (tid == 0) {
        float mx = fmaxf(y0, y1);
        float e0 = __expf(y0 - mx), e1 = __expf(y1 - mx);
        int o;
        o = n*2+0; if (o < osz) out[o] = e0/(e0+e1);
        o = n*2+1; if (o < osz) out[o] = e1/(e0+e1);
    }
}

// ---------------- E5: l_ort + l_pol -----------------------------------
__global__ void finals_kernel(const float* __restrict__ x_tag,
                              float* __restrict__ out, int osz)
{
    const int tid = threadIdx.x;  // 256
    __shared__ float red[256], w[NNODE];

    float s1 = 0.f, s2 = 0.f;
    for (int i = tid; i < 16384; i += 256) {
        s1 += g_G[i]          * g_G[16384 + i];
        s2 += g_G[32768 + i]  * g_G[49152 + i];
    }
    red[tid] = s1; __syncthreads();
    #pragma unroll
    for (int s = 128; s > 0; s >>= 1) { if (tid < s) red[tid] += red[tid+s]; __syncthreads(); }
    float S1 = red[0]; __syncthreads();
    red[tid] = s2; __syncthreads();
    #pragma unroll
    for (int s = 128; s > 0; s >>= 1) { if (tid < s) red[tid] += red[tid+s]; __syncthreads(); }
    float S2 = red[0]; __syncthreads();
    if (tid == 0 && 472 < osz) out[472] = sqrtf(S1) + sqrtf(S2);

    if (tid < NNODE) {
        float nr = 0.f;
        const float* np = g_n + tid*256;
        for (int d = 0; d < 256; d++) nr += np[d]*np[d];
        nr = fmaxf(sqrtf(nr), 1e-8f);
        float diff = x_tag[tid*3+1] - x_tag[tid*3+0];
        float sg = (diff > 0.f ? 1.f : (diff < 0.f ? -1.f : 0.f));
        sg *= (x_tag[tid*3+2] == 0.f) ? 1.f : 0.f;
        w[tid] = sg / nr;
    }
    __syncthreads();
    float v = 0.f;
    for (int i = 0; i < NNODE; i++) v += w[i]*g_n[i*256 + tid];
    red[tid] = v*v; __syncthreads();
    #pragma unroll
    for (int s = 128; s > 0; s >>= 1) { if (tid < s) red[tid] += red[tid+s]; __syncthreads(); }
    if (tid == 0 && 473 < osz) out[473] = red[0];
}

// ---------------- launch ----------------------------------------------
extern "C" void kernel_launch(void* const* d_in, const int* in_sizes, int n_in,
                              void* d_out, int out_size)
{
    const float* x       = (const float*)d_in[0];
    const float* x_tag   = (const float*)d_in[1];
    const float* W_ih0   = (const float*)d_in[2];
    const float* W_hh0   = (const float*)d_in[3];
    const float* b_ih0   = (const float*)d_in[4];
    const float* b_hh0   = (const float*)d_in[5];
    const float* W_ih1   = (const float*)d_in[6];
    const float* W_hh1   = (const float*)d_in[7];
    const float* b_ih1   = (const float*)d_in[8];
    const float* b_hh1   = (const float*)d_in[9];
    const float* pm      = (const float*)d_in[10];
    const float* Wum     = (const float*)d_in[11];
    const float* Wvm     = (const float*)d_in[12];
    const float* Wup     = (const float*)d_in[13];
    const float* Wvp     = (const float*)d_in[14];
    const float* W_hyb   = (const float*)d_in[15];
    const float* b_hyb   = (const float*)d_in[16];
    const float* W_act   = (const float*)d_in[17];
    const float* b_act   = (const float*)d_in[18];
    const float* W_inact = (const float*)d_in[19];
    const float* b_inact = (const float*)d_in[20];
    const float* Wphin   = (const float*)d_in[21];
    const float* aphi    = (const float*)d_in[22];
    const float* Won     = (const float*)d_in[23];
    const float* Weo     = (const float*)d_in[24];
    const float* Wi      = (const float*)d_in[25];
    const float* bi      = (const float*)d_in[26];
    float* out = (float*)d_out;

    float *xpre = nullptr, *h1 = nullptr, *h2last = nullptr;
    cudaGetSymbolAddress((void**)&xpre,   g_xpre);
    cudaGetSymbolAddress((void**)&h1,     g_h1);
    cudaGetSymbolAddress((void**)&h2last, g_h2last);

    cudaFuncSetAttribute(gemm_k, cudaFuncAttributeMaxDynamicSharedMemorySize, GEMM_SMEM);

    dim3 gg(4, M_ROWS/128);

    // layer 0
    gemm_k<<<gg, 256, GEMM_SMEM>>>(x, W_ih0, b_ih0, b_hh0, xpre);
    lstm_rec<1><<<NNODE, 512>>>(xpre, W_hh0, h1);
    // layer 1
    gemm_k<<<gg, 256, GEMM_SMEM>>>(h1, W_ih1, b_ih1, b_hh1, xpre);
    lstm_rec<0><<<NNODE, 512>>>(xpre, W_hh1, h2last);

    // epilogue
    prep_kernel<<<1, 128>>>(x_tag, pm, Wvm, out, out_size);
    gram_kernel<<<512, 128>>>(Wum, Wvm, Wup, Wvp);
    node_kernel<<<NNODE, 256>>>(x_tag, Wup, W_hyb, b_hyb, W_act, b_act, W_inact, b_inact);
    proj_kernel<<<NNODE, 256>>>(Wphin, Won, Weo);
    phi_alpha_kernel<<<NNODE, 128>>>(x_tag, aphi);
    hyper_kernel<<<NNODE, 256>>>(x_tag, Weo, Wi, bi, out, out_size);
    finals_kernel<<<1, 256>>>(x_tag, out, out_size);
}

// round 11
// speedup vs baseline: 1.2516x; 1.0120x over previous
#include <cuda_runtime.h>
#include <math.h>

#define NNODE 118
#define TT 2048
#define M_ROWS (NNODE*TT)

typedef unsigned long long ull;
union F2U { ull u; float2 f; };

__device__ __forceinline__ ull pk2(float x, float y){ ull r; asm("mov.b64 %0, {%1,%2};" : "=l"(r) : "f"(x), "f"(y)); return r; }
__device__ __forceinline__ ull dupf(float x){ ull r; asm("mov.b64 %0, {%1,%1};" : "=l"(r) : "f"(x)); return r; }
__device__ __forceinline__ void fma2(ull& d, ull a, ull b){ asm("fma.rn.f32x2 %0, %1, %2, %0;" : "+l"(d) : "l"(a), "l"(b)); }
__device__ __forceinline__ ull add2(ull a, ull b){ ull r; asm("add.rn.f32x2 %0, %1, %2;" : "=l"(r) : "l"(a), "l"(b)); return r; }
__device__ __forceinline__ float tanh_ap(float x){ float r; asm("tanh.approx.f32 %0, %1;" : "=f"(r) : "f"(x)); return r; }

// unpack bf16x2 word -> f32x2 (low bf16 = even element)
__device__ __forceinline__ ull unpk(unsigned w){
    unsigned lo = w << 16;
    unsigned hi = w & 0xFFFF0000u;
    ull r; asm("mov.b64 %0, {%1,%2};" : "=l"(r) : "r"(lo), "r"(hi));
    return r;
}
__device__ __forceinline__ unsigned bf1(float f){
    unsigned b = __float_as_uint(f);
    return (b + 0x7FFFu + ((b >> 16) & 1u)) >> 16;   // RNE
}
__device__ __forceinline__ unsigned bfpair(float e, float o){ return bf1(e) | (bf1(o) << 16); }

__device__ __forceinline__ ull shfl_xor64(ull v, int m){
    unsigned lo = (unsigned)v, hi = (unsigned)(v >> 32);
    lo = __shfl_xor_sync(0xFFFFFFFFu, lo, m);
    hi = __shfl_xor_sync(0xFFFFFFFFu, hi, m);
    return ((ull)hi << 32) | lo;
}

// column permutation: semantic gate-major n (= g*128+c)  <->  stored col' = 4c+g
__device__ __forceinline__ int invperm(int cp){ return (cp & 3)*128 + (cp >> 2); }

// ---------------- scratch (device globals; no allocation allowed) ----------
__device__ __align__(256) float g_xpre[(size_t)M_ROWS*512];
__device__ __align__(256) float g_h1[(size_t)M_ROWS*128];
__device__ __align__(256) float g_h2last[NNODE*128];
__device__ __align__(256) float g_vm[2*128];
__device__ __align__(256) float g_flag[1];
__device__ __align__(256) float g_n[NNODE*256];
__device__ __align__(256) float g_Pa[NNODE*192];
__device__ __align__(256) float g_Pb[NNODE*192];
__device__ __align__(256) float g_Qa[NNODE*256];
__device__ __align__(256) float g_Qb[NNODE*256];
__device__ __align__(256) float g_Ra[NNODE*256];
__device__ __align__(256) float g_Rb[NNODE*256];
__device__ __align__(256) float g_alpha[NNODE*NNODE];
__device__ __align__(256) float g_G[4*128*128];

__device__ __forceinline__ float leaky(float z){ return z >= 0.f ? z : 0.01f*z; }

// ---------------- GEMM: C(M,512) = A(M,128) @ W(512,128)^T + b1 + b2 -------
#define GP2 132
#define GEMM_SMEM (2*128*GP2*4)

__global__ void __launch_bounds__(256) gemm_k(const float* __restrict__ A,
                                              const float* __restrict__ W,
                                              const float* __restrict__ b1,
                                              const float* __restrict__ b2,
                                              float* __restrict__ C)
{
    extern __shared__ float sm[];
    float* As = sm;               // [k][m] pad GP2
    float* Ws = sm + 128*GP2;     // [k][n'] pad GP2
    const int tid = threadIdx.x;
    const int mbase = blockIdx.y * 128;
    const int nbase = blockIdx.x * 128;
    const int l = tid & 31;
    const int w = tid >> 5;

    const float4* A4 = (const float4*)(A + (size_t)mbase*128);
    const float4* W4 = (const float4*)W;
    #pragma unroll
    for (int r = 0; r < 16; r++) {
        int row = 8*w + (l & 7) + 64*(r >> 3);     // 0..127
        int kg  = 4*(r & 7) + (l >> 3);            // 0..31
        float4 va = A4[row*32 + kg];
        As[(4*kg+0)*GP2 + row] = va.x;
        As[(4*kg+1)*GP2 + row] = va.y;
        As[(4*kg+2)*GP2 + row] = va.z;
        As[(4*kg+3)*GP2 + row] = va.w;
        int srow = invperm(nbase + row);           // permuted W row source
        float4 vw = W4[srow*32 + kg];
        Ws[(4*kg+0)*GP2 + row] = vw.x;
        Ws[(4*kg+1)*GP2 + row] = vw.y;
        Ws[(4*kg+2)*GP2 + row] = vw.z;
        Ws[(4*kg+3)*GP2 + row] = vw.w;
    }
    __syncthreads();

    const int tx = tid & 15;   // n micro
    const int ty = tid >> 4;   // m micro
    const int m0 = ty*8, n0 = tx*8;

    F2U acc[4][8];
    #pragma unroll
    for (int p = 0; p < 4; p++)
        #pragma unroll
        for (int j = 0; j < 8; j++) acc[p][j].u = 0ull;

    #pragma unroll 8
    for (int k = 0; k < 128; k++) {
        const float4 a0 = *(const float4*)(As + k*GP2 + m0);
        const float4 a1 = *(const float4*)(As + k*GP2 + m0 + 4);
        const float4 w0 = *(const float4*)(Ws + k*GP2 + n0);
        const float4 w1 = *(const float4*)(Ws + k*GP2 + n0 + 4);
        ull ap0 = pk2(a0.x, a0.y), ap1 = pk2(a0.z, a0.w);
        ull ap2 = pk2(a1.x, a1.y), ap3 = pk2(a1.z, a1.w);
        ull wd;
        wd = dupf(w0.x); fma2(acc[0][0].u, ap0, wd); fma2(acc[1][0].u, ap1, wd); fma2(acc[2][0].u, ap2, wd); fma2(acc[3][0].u, ap3, wd);
        wd = dupf(w0.y); fma2(acc[0][1].u, ap0, wd); fma2(acc[1][1].u, ap1, wd); fma2(acc[2][1].u, ap2, wd); fma2(acc[3][1].u, ap3, wd);
        wd = dupf(w0.z); fma2(acc[0][2].u, ap0, wd); fma2(acc[1][2].u, ap1, wd); fma2(acc[2][2].u, ap2, wd); fma2(acc[3][2].u, ap3, wd);
        wd = dupf(w0.w); fma2(acc[0][3].u, ap0, wd); fma2(acc[1][3].u, ap1, wd); fma2(acc[2][3].u, ap2, wd); fma2(acc[3][3].u, ap3, wd);
        wd = dupf(w1.x); fma2(acc[0][4].u, ap0, wd); fma2(acc[1][4].u, ap1, wd); fma2(acc[2][4].u, ap2, wd); fma2(acc[3][4].u, ap3, wd);
        wd = dupf(w1.y); fma2(acc[0][5].u, ap0, wd); fma2(acc[1][5].u, ap1, wd); fma2(acc[2][5].u, ap2, wd); fma2(acc[3][5].u, ap3, wd);
        wd = dupf(w1.z); fma2(acc[0][6].u, ap0, wd); fma2(acc[1][6].u, ap1, wd); fma2(acc[2][6].u, ap2, wd); fma2(acc[3][6].u, ap3, wd);
        wd = dupf(w1.w); fma2(acc[0][7].u, ap0, wd); fma2(acc[1][7].u, ap1, wd); fma2(acc[2][7].u, ap2, wd); fma2(acc[3][7].u, ap3, wd);
    }

    const int col = nbase + n0;
    float bias[8];
    #pragma unroll
    for (int c = 0; c < 8; c++) {
        int src = invperm(col + c);
        bias[c] = b1[src] + b2[src];
    }

    #pragma unroll
    for (int p = 0; p < 4; p++) {
        float4 o;
        float* r0 = C + (size_t)(mbase + m0 + 2*p)*512 + col;
        float* r1 = r0 + 512;
        o.x = acc[p][0].f.x + bias[0]; o.y = acc[p][1].f.x + bias[1];
        o.z = acc[p][2].f.x + bias[2]; o.w = acc[p][3].f.x + bias[3];
        *(float4*)(r0) = o;
        o.x = acc[p][4].f.x + bias[4]; o.y = acc[p][5].f.x + bias[5];
        o.z = acc[p][6].f.x + bias[6]; o.w = acc[p][7].f.x + bias[7];
        *(float4*)(r0 + 4) = o;
        o.x = acc[p][0].f.y + bias[0]; o.y = acc[p][1].f.y + bias[1];
        o.z = acc[p][2].f.y + bias[2]; o.w = acc[p][3].f.y + bias[3];
        *(float4*)(r1) = o;
        o.x = acc[p][4].f.y + bias[4]; o.y = acc[p][5].f.y + bias[5];
        o.z = acc[p][6].f.y + bias[6]; o.w = acc[p][7].f.y + bias[7];
        *(float4*)(r1 + 4) = o;
    }
}

// ---------------- LSTM recurrence: one block per node ----------------------
// Quad-k-split (R10) + single-MUFU activations via tanh.approx (R11):
//   sigmoid(x) = 0.5 + 0.5*tanh(x/2), tanh direct.
template<int WRITE_ALL>
__global__ void __launch_bounds__(512, 1) lstm_rec(const float* __restrict__ xpre,
                                                   const float* __restrict__ Whh,
                                                   float* __restrict__ hout)
{
    __shared__ __align__(16) float hs[2][128];
    __shared__ __align__(16) uint4 wsb[4*512];   // 32 KB bf16 gate-3 weights

    const int j = threadIdx.x;
    const int n = blockIdx.x;
    const int l = j & 31;
    const int w = j >> 5;
    const int q = l & 3;                          // gate index AND k-slice index
    const int cell = w*8 + (l >> 2);

    // weights: rows g*128+cell, k-slice [32q, 32q+32)
    ull wr[48];                                   // g = 0..2
    #pragma unroll
    for (int g = 0; g < 3; g++) {
        const float* wp = Whh + (g*128 + cell)*128 + 32*q;
        #pragma unroll
        for (int i = 0; i < 8; i++) {
            float4 v = *(const float4*)(wp + 4*i);
            wr[g*16 + 2*i]     = pk2(v.x, v.y);
            wr[g*16 + 2*i + 1] = pk2(v.z, v.w);
        }
    }
    {
        const float* wp = Whh + (3*128 + cell)*128 + 32*q;
        #pragma unroll
        for (int s = 0; s < 4; s++) {
            uint4 pkv;
            pkv.x = bfpair(wp[8*s+0], wp[8*s+1]);
            pkv.y = bfpair(wp[8*s+2], wp[8*s+3]);
            pkv.z = bfpair(wp[8*s+4], wp[8*s+5]);
            pkv.w = bfpair(wp[8*s+6], wp[8*s+7]);
            wsb[s*512 + j] = pkv;
        }
    }

    if (j < 128) { hs[0][j] = 0.f; hs[1][j] = 0.f; }
    float c = 0.f;
    __syncthreads();

    const float* xp = xpre + (size_t)n*TT*512 + j;   // coalesced (permuted layout)
    float xnext = xp[0];
    float* hw = hout + (WRITE_ALL ? ((size_t)n*TT*128 + cell) : ((size_t)n*128 + cell));

    // swizzled write slot for this thread's h (only gate-0 lanes use it)
    const int wblk = cell >> 5;
    const int wslot = wblk*32 + (((cell & 31) + 8*wblk) & 31);

    int p = 0;
    for (int t = 0; t < TT; t++) {
        F2U A0, A1, A2, A3;
        A0.u = 0ull; A1.u = 0ull; A2.u = 0ull; A3.u = 0ull;
        float xcur = xnext;
        if (t + 1 < TT) xnext = xp[(size_t)(t+1)*512];

        const float* hb = hs[p] + q*32;
        #pragma unroll
        for (int s = 0; s < 4; s++) {
            uint4 wv = wsb[s*512 + j];
            // chunk i = 2s
            {
                int off = (8*s + 8*q) & 31;
                ulonglong2 hv = *(const ulonglong2*)(hb + off);
                fma2(A0.u, wr[4*s],      hv.x); fma2(A0.u, wr[4*s+1],      hv.y);
                fma2(A1.u, wr[16+4*s],   hv.x); fma2(A1.u, wr[16+4*s+1],   hv.y);
                fma2(A2.u, wr[32+4*s],   hv.x); fma2(A2.u, wr[32+4*s+1],   hv.y);
                fma2(A3.u, unpk(wv.x),   hv.x); fma2(A3.u, unpk(wv.y),     hv.y);
            }
            // chunk i = 2s+1
            {
                int off = (8*s + 4 + 8*q) & 31;
                ulonglong2 hv = *(const ulonglong2*)(hb + off);
                fma2(A0.u, wr[4*s+2],    hv.x); fma2(A0.u, wr[4*s+3],      hv.y);
                fma2(A1.u, wr[16+4*s+2], hv.x); fma2(A1.u, wr[16+4*s+3],   hv.y);
                fma2(A2.u, wr[32+4*s+2], hv.x); fma2(A2.u, wr[32+4*s+3],   hv.y);
                fma2(A3.u, unpk(wv.z),   hv.x); fma2(A3.u, unpk(wv.w),     hv.y);
            }
        }

        float p0 = A0.f.x + A0.f.y;
        float p1 = A1.f.x + A1.f.y;
        float p2 = A2.f.x + A2.f.y;
        float p3 = A3.f.x + A3.f.y;

        // quad transpose-reduce: lane q ends with full dot for gate q
        ull lo = pk2(p0, p1), hi = pk2(p2, p3);
        ull send = (l & 2) ? lo : hi;
        ull recv = shfl_xor64(send, 2);
        ull keep = (l & 2) ? hi : lo;
        F2U s2; s2.u = add2(keep, recv);
        float mine  = (l & 1) ? s2.f.y : s2.f.x;
        float sendf = (l & 1) ? s2.f.x : s2.f.y;
        float other = __shfl_xor_sync(0xFFFFFFFFu, sendf, 1);
        float acc = mine + other + xcur;

        // single-MUFU activations: sigmoid(x) = 0.5 + 0.5*tanh(x/2)
        const bool isg = (q == 2);
        float u  = isg ? acc : 0.5f*acc;
        float th = tanh_ap(u);
        float a  = isg ? th : fmaf(0.5f, th, 0.5f);

        const int base = l & ~3;
        float iv = __shfl_sync(0xFFFFFFFFu, a, base);
        float fv = __shfl_sync(0xFFFFFFFFu, a, base + 1);
        float gv = __shfl_sync(0xFFFFFFFFu, a, base + 2);
        float ov = __shfl_sync(0xFFFFFFFFu, a, base + 3);
        c = fv*c + iv*gv;
        float hv = ov * tanh_ap(c);
        p ^= 1;
        if (q == 0) {
            hs[p][wslot] = hv;
            if (WRITE_ALL)      hw[(size_t)t*128] = hv;
            else if (t == TT-1) hw[0] = hv;
        }
        __syncthreads();
    }
}

// ---------------- E0: pseudo-message projections + direct outputs ----------
__global__ void prep_kernel(const float* __restrict__ x_tag,
                            const float* __restrict__ pm,
                            const float* __restrict__ Wvm,
                            float* __restrict__ out, int osz)
{
    const int tid = threadIdx.x;  // 128
    __shared__ float pms[768];
    for (int i = tid; i < 768; i += 128) pms[i] = pm[i];
    __syncthreads();

    float base = 0.f;
    for (int k = 0; k < 768; k++) base += pms[k]*Wvm[k*128 + tid];
    g_vm[tid]       = leaky(base);
    g_vm[128 + tid] = leaky(base + Wvm[768*128 + tid]);

    if (tid < NNODE) {
        int o;
        o = 236 + tid*2 + 0; if (o < osz) out[o] = x_tag[tid*3+0];
        o = 236 + tid*2 + 1; if (o < osz) out[o] = x_tag[tid*3+1];
        float a = x_tag[tid*3+2];
        o = 474 + tid; if (o < osz) out[o] = (a == 0.f) ? 1.f : 0.f;
        o = 592 + tid; if (o < osz) out[o] = (a == 1.f) ? 1.f : 0.f;
    }
    if (tid == 0) {
        int cnt = 0;
        for (int i = 0; i < NNODE; i++) if (x_tag[i*3+2] == 0.f) cnt++;
        g_flag[0] = (cnt > 0) ? 1.f : 0.f;
    }
}

// ---------------- Gram matrices for l_ort -----------------------------
__global__ void gram_kernel(const float* __restrict__ Wum, const float* __restrict__ Wvm,
                            const float* __restrict__ Wup, const float* __restrict__ Wvp)
{
    const int bid = blockIdx.x;
    const int mat = bid >> 7;
    const int k   = bid & 127;
    const int l   = threadIdx.x;  // 128
    const float* W; int rows;
    if      (mat == 0) { W = Wum; rows = 769; }
    else if (mat == 1) { W = Wvm; rows = 769; }
    else if (mat == 2) { W = Wup; rows = 128; }
    else               { W = Wvp; rows = 128; }
    float acc = 0.f;
    for (int i = 0; i < rows; i++) acc += W[i*128 + k] * W[i*128 + l];
    g_G[mat*16384 + k*128 + l] = acc;
}

// ---------------- E1: per-node MLP chain -> n -------------------------
__global__ void node_kernel(const float* __restrict__ x_tag,
                            const float* __restrict__ Wup,
                            const float* __restrict__ W_hyb, const float* __restrict__ b_hyb,
                            const float* __restrict__ W_act, const float* __restrict__ b_act,
                            const float* __restrict__ W_inact, const float* __restrict__ b_inact)
{
    const int n = blockIdx.x, tid = threadIdx.x;  // 256
    __shared__ float p[128], up[128], vm_s[128], hh[256];
    const float act = x_tag[n*3+2];
    if (tid < 128) {
        p[tid]    = leaky(g_h2last[n*128 + tid]);
        vm_s[tid] = (act == 1.f) ? g_vm[128 + tid] : g_vm[tid];
    }
    __syncthreads();
    if (tid < 128) {
        float a = 0.f;
        for (int k = 0; k < 128; k++) a += p[k]*Wup[k*128 + tid];
        up[tid] = leaky(a);
    }
    __syncthreads();
    {
        float a = b_hyb[tid];
        for (int k = 0; k < 128; k++) {
            float u_ = up[k], v_ = vm_s[k];
            a += u_*W_hyb[k*256 + tid] + (u_ + v_)*W_hyb[(128+k)*256 + tid] + v_*W_hyb[(256+k)*256 + tid];
        }
        hh[tid] = leaky(a);
    }
    __syncthreads();
    {
        float na = b_act[tid], ni = b_inact[tid];
        for (int k = 0; k < 256; k++) {
            float h_ = hh[k];
            na += h_*W_act[k*256 + tid];
            ni += h_*W_inact[k*256 + tid];
        }
        na += x_tag[n*3+0]*W_act[256*256 + tid] + x_tag[n*3+1]*W_act[257*256 + tid];
        g_n[n*256 + tid] = leaky(na*(1.f - act) + ni*act);
    }
}

// ---------------- E2: per-node pair projections -----------------------
__global__ void proj_kernel(const float* __restrict__ Wphin,
                            const float* __restrict__ Won,
                            const float* __restrict__ Weo)
{
    const int n = blockIdx.x, tid = threadIdx.x;  // 256
    __shared__ float nn_s[256];
    nn_s[tid] = g_n[n*256 + tid];
    __syncthreads();
    if (tid < 192) {
        float pb = 0.f, pa = 0.f;
        for (int k = 0; k < 256; k++) {
            float v = nn_s[k];
            pb += v*Wphin[k*192 + tid];
            pa += v*Wphin[(256+k)*192 + tid];
        }
        g_Pb[n*192 + tid] = pb;
        g_Pa[n*192 + tid] = pa;
    }
    float qb = 0.f, qa = 0.f, rb = 0.f, ra = 0.f;
    for (int k = 0; k < 256; k++) {
        float v = nn_s[k];
        qb += v*Won[k*256 + tid];
        qa += v*Won[(256+k)*256 + tid];
        rb += v*Weo[(256+k)*256 + tid];
        ra += v*Weo[(512+k)*256 + tid];
    }
    g_Qb[n*256 + tid] = qb;
    g_Qa[n*256 + tid] = qa;
    g_Rb[n*256 + tid] = rb;
    g_Ra[n*256 + tid] = ra;
}

// ---------------- E3: phi column + masked softmaxes -> alpha ----------
__device__ __forceinline__ float blockmax128(float v, float* red){
    int tid = threadIdx.x; red[tid] = v; __syncthreads();
    #pragma unroll
    for (int s = 64; s > 0; s >>= 1) { if (tid < s) red[tid] = fmaxf(red[tid], red[tid+s]); __syncthreads(); }
    float r = red[0]; __syncthreads(); return r;
}
__device__ __forceinline__ float blocksum128(float v, float* red){
    int tid = threadIdx.x; red[tid] = v; __syncthreads();
    #pragma unroll
    for (int s = 64; s > 0; s >>= 1) { if (tid < s) red[tid] += red[tid+s]; __syncthreads(); }
    float r = red[0]; __syncthreads(); return r;
}

__global__ void phi_alpha_kernel(const float* __restrict__ x_tag,
                                 const float* __restrict__ aphi)
{
    const int b = blockIdx.x;
    const int tid = threadIdx.x;  // 128
    __shared__ float pb_s[192], ap_s[192], red[128];
    for (int i = tid; i < 192; i += 128) { pb_s[i] = g_Pb[b*192 + i]; ap_s[i] = aphi[i]; }
    __syncthreads();

    float ph = 0.f, v1 = 0.f;
    if (tid < NNODE) {
        const float* pa = g_Pa + tid*192;
        #pragma unroll 8
        for (int d = 0; d < 192; d++) ph += leaky(pb_s[d] + pa[d]) * ap_s[d];
        v1 = (x_tag[tid*3+2] == 0.f) ? 1.f : 0.f;
    }

    const float NEG = -1000000000.f;
    float m1 = (tid < NNODE) ? (v1 > 0.f ? ph : NEG) : -INFINITY;
    float m0 = (tid < NNODE) ? (v1 > 0.f ? NEG : ph) : -INFINITY;
    float ma = (tid < NNODE) ? ph : -INFINITY;

    float mx = blockmax128(m1, red);
    float e  = (tid < NNODE) ? __expf(m1 - mx) : 0.f;
    float s  = blocksum128(e, red);
    float sm1 = e / s;

    mx = blockmax128(m0, red);
    e  = (tid < NNODE) ? __expf(m0 - mx) : 0.f;
    s  = blocksum128(e, red);
    float sm0 = e / s;

    mx = blockmax128(ma, red);
    e  = (tid < NNODE) ? __expf(ma - mx) : 0.f;
    s  = blocksum128(e, red);
    float sma = e / s;

    if (tid < NNODE) {
        float a = (g_flag[0] > 0.f) ? (v1 > 0.f ? sm1 : sm0) : sma;
        g_alpha[tid*NNODE + b] = a;
    }
}

// ---------------- E4: hyper messages + y_hat --------------------------
__global__ void hyper_kernel(const float* __restrict__ x_tag,
                             const float* __restrict__ Weo,
                             const float* __restrict__ Wi,
                             const float* __restrict__ bi,
                             float* __restrict__ out, int osz)
{
    const int n = blockIdx.x, tid = threadIdx.x;  // 256
    __shared__ float qa[256], ra[256], nn_s[256], u[256], al[NNODE], red[256];
    qa[tid]   = g_Qa[n*256 + tid];
    ra[tid]   = g_Ra[n*256 + tid];
    nn_s[tid] = g_n[n*256 + tid];
    if (tid < NNODE) al[tid] = g_alpha[n*NNODE + tid];
    __syncthreads();

    float uacc = 0.f, racc = 0.f, alsum = 0.f;
    const float qad = qa[tid];
    for (int j = 0; j < NNODE; j++) {
        float a_ = al[j];
        uacc  += a_ * leaky(g_Qb[j*256 + tid] + qad);
        racc  += a_ * g_Rb[j*256 + tid];
        alsum += a_;
    }
    u[tid] = uacc;
    __syncthreads();

    float T = racc + alsum*ra[tid];
    for (int k = 0; k < 256; k++) T += u[k]*Weo[k*256 + tid];

    const float act = x_tag[n*3+2];
    float hm0 = leaky(act*T);
    float hm1 = leaky((1.f - act)*T);

    const float* Win = Wi + (size_t)n*768*2;
    float p0 = nn_s[tid]*Win[tid*2+0] + hm0*Win[(256+tid)*2+0] + hm1*Win[(512+tid)*2+0];
    float p1 = nn_s[tid]*Win[tid*2+1] + hm0*Win[(256+tid)*2+1] + hm1*Win[(512+tid)*2+1];

    red[tid] = p0; __syncthreads();
    #pragma unroll
    for (int s = 128; s > 0; s >>= 1) { if (tid < s) red[tid] += red[tid+s]; __syncthreads(); }
    float y0 = red[0] + bi[n*2+0]; __syncthreads();

    red[tid] = p1; __syncthreads();
    #pragma unroll
    for (int s = 128; s > 0; s >>= 1) { if (tid < s) red[tid] += red[tid+s]; __syncthreads(); }
    float y1 = red[0] + bi[n*2+1];

    if (tid == 0) {
        float mx = fmaxf(y0, y1);
        float e0 = __expf(y0 - mx), e1 = __expf(y1 - mx);
        int o;
        o = n*2+0; if (o < osz) out[o] = e0/(e0+e1);
        o = n*2+1; if (o < osz) out[o] = e1/(e0+e1);
    }
}

// ---------------- E5: l_ort + l_pol -----------------------------------
__global__ void finals_kernel(const float* __restrict__ x_tag,
                              float* __restrict__ out, int osz)
{
    const int tid = threadIdx.x;  // 256
    __shared__ float red[256], w[NNODE];

    float s1 = 0.f, s2 = 0.f;
    for (int i = tid; i < 16384; i += 256) {
        s1 += g_G[i]          * g_G[16384 + i];
        s2 += g_G[32768 + i]  * g_G[49152 + i];
    }
    red[tid] = s1; __syncthreads();
    #pragma unroll
    for (int s = 128; s > 0; s >>= 1) { if (tid < s) red[tid] += red[tid+s]; __syncthreads(); }
    float S1 = red[0]; __syncthreads();
    red[tid] = s2; __syncthreads();
    #pragma unroll
    for (int s = 128; s > 0; s >>= 1) { if (tid < s) red[tid] += red[tid+s]; __syncthreads(); }
    float S2 = red[0]; __syncthreads();
    if (tid == 0 && 472 < osz) out[472] = sqrtf(S1) + sqrtf(S2);

    if (tid < NNODE) {
        float nr = 0.f;
        const float* np = g_n + tid*256;
        for (int d = 0; d < 256; d++) nr += np[d]*np[d];
        nr = fmaxf(sqrtf(nr), 1e-8f);
        float diff = x_tag[tid*3+1] - x_tag[tid*3+0];
        float sg = (diff > 0.f ? 1.f : (diff < 0.f ? -1.f : 0.f));
        sg *= (x_tag[tid*3+2] == 0.f) ? 1.f : 0.f;
        w[tid] = sg / nr;
    }
    __syncthreads();
    float v = 0.f;
    for (int i = 0; i < NNODE; i++) v += w[i]*g_n[i*256 + tid];
    red[tid] = v*v; __syncthreads();
    #pragma unroll
    for (int s = 128; s > 0; s >>= 1) { if (tid < s) red[tid] += red[tid+s]; __syncthreads(); }
    if (tid == 0 && 473 < osz) out[473] = red[0];
}

// ---------------- launch ----------------------------------------------
extern "C" void kernel_launch(void* const* d_in, const int* in_sizes, int n_in,
                              void* d_out, int out_size)
{
    const float* x       = (const float*)d_in[0];
    const float* x_tag   = (const float*)d_in[1];
    const float* W_ih0   = (const float*)d_in[2];
    const float* W_hh0   = (const float*)d_in[3];
    const float* b_ih0   = (const float*)d_in[4];
    const float* b_hh0   = (const float*)d_in[5];
    const float* W_ih1   = (const float*)d_in[6];
    const float* W_hh1   = (const float*)d_in[7];
    const float* b_ih1   = (const float*)d_in[8];
    const float* b_hh1   = (const float*)d_in[9];
    const float* pm      = (const float*)d_in[10];
    const float* Wum     = (const float*)d_in[11];
    const float* Wvm     = (const float*)d_in[12];
    const float* Wup     = (const float*)d_in[13];
    const float* Wvp     = (const float*)d_in[14];
    const float* W_hyb   = (const float*)d_in[15];
    const float* b_hyb   = (const float*)d_in[16];
    const float* W_act   = (const float*)d_in[17];
    const float* b_act   = (const float*)d_in[18];
    const float* W_inact = (const float*)d_in[19];
    const float* b_inact = (const float*)d_in[20];
    const float* Wphin   = (const float*)d_in[21];
    const float* aphi    = (const float*)d_in[22];
    const float* Won     = (const float*)d_in[23];
    const float* Weo     = (const float*)d_in[24];
    const float* Wi      = (const float*)d_in[25];
    const float* bi      = (const float*)d_in[26];
    float* out = (float*)d_out;

    float *xpre = nullptr, *h1 = nullptr, *h2last = nullptr;
    cudaGetSymbolAddress((void**)&xpre,   g_xpre);
    cudaGetSymbolAddress((void**)&h1,     g_h1);
    cudaGetSymbolAddress((void**)&h2last, g_h2last);

    cudaFuncSetAttribute(gemm_k, cudaFuncAttributeMaxDynamicSharedMemorySize, GEMM_SMEM);

    dim3 gg(4, M_ROWS/128);

    // layer 0
    gemm_k<<<gg, 256, GEMM_SMEM>>>(x, W_ih0, b_ih0, b_hh0, xpre);
    lstm_rec<1><<<NNODE, 512>>>(xpre, W_hh0, h1);
    // layer 1
    gemm_k<<<gg, 256, GEMM_SMEM>>>(h1, W_ih1, b_ih1, b_hh1, xpre);
    lstm_rec<0><<<NNODE, 512>>>(xpre, W_hh1, h2last);

    // epilogue
    prep_kernel<<<1, 128>>>(x_tag, pm, Wvm, out, out_size);
    gram_kernel<<<512, 128>>>(Wum, Wvm, Wup, Wvp);
    node_kernel<<<NNODE, 256>>>(x_tag, Wup, W_hyb, b_hyb, W_act, b_act, W_inact, b_inact);
    proj_kernel<<<NNODE, 256>>>(Wphin, Won, Weo);
    phi_alpha_kernel<<<NNODE, 128>>>(x_tag, aphi);
    hyper_kernel<<<NNODE, 256>>>(x_tag, Weo, Wi, bi, out, out_size);
    finals_kernel<<<1, 256>>>(x_tag, out, out_size);
}

// round 12
// speedup vs baseline: 1.2523x; 1.0006x over previous
#include <cuda_runtime.h>
#include <math.h>

#define NNODE 118
#define TT 2048
#define M_ROWS (NNODE*TT)

typedef unsigned long long ull;
union F2U { ull u; float2 f; };

__device__ __forceinline__ ull pk2(float x, float y){ ull r; asm("mov.b64 %0, {%1,%2};" : "=l"(r) : "f"(x), "f"(y)); return r; }
__device__ __forceinline__ ull dupf(float x){ ull r; asm("mov.b64 %0, {%1,%1};" : "=l"(r) : "f"(x)); return r; }
__device__ __forceinline__ void fma2(ull& d, ull a, ull b){ asm("fma.rn.f32x2 %0, %1, %2, %0;" : "+l"(d) : "l"(a), "l"(b)); }
__device__ __forceinline__ ull add2(ull a, ull b){ ull r; asm("add.rn.f32x2 %0, %1, %2;" : "=l"(r) : "l"(a), "l"(b)); return r; }
__device__ __forceinline__ float tanh_ap(float x){ float r; asm("tanh.approx.f32 %0, %1;" : "=f"(r) : "f"(x)); return r; }

__device__ __forceinline__ ull shfl_xor64(ull v, int m){
    unsigned lo = (unsigned)v, hi = (unsigned)(v >> 32);
    lo = __shfl_xor_sync(0xFFFFFFFFu, lo, m);
    hi = __shfl_xor_sync(0xFFFFFFFFu, hi, m);
    return ((ull)hi << 32) | lo;
}

// column permutation: semantic gate-major n (= g*128+c)  <->  stored col' = 4c+g
__device__ __forceinline__ int invperm(int cp){ return (cp & 3)*128 + (cp >> 2); }

// ---------------- scratch (device globals; no allocation allowed) ----------
__device__ __align__(256) float g_xpre[(size_t)M_ROWS*512];
__device__ __align__(256) float g_h1[(size_t)M_ROWS*128];
__device__ __align__(256) float g_h2last[NNODE*128];
__device__ __align__(256) float g_vm[2*128];
__device__ __align__(256) float g_flag[1];
__device__ __align__(256) float g_n[NNODE*256];
__device__ __align__(256) float g_Pa[NNODE*192];
__device__ __align__(256) float g_Pb[NNODE*192];
__device__ __align__(256) float g_Qa[NNODE*256];
__device__ __align__(256) float g_Qb[NNODE*256];
__device__ __align__(256) float g_Ra[NNODE*256];
__device__ __align__(256) float g_Rb[NNODE*256];
__device__ __align__(256) float g_alpha[NNODE*NNODE];
__device__ __align__(256) float g_G[4*128*128];

__device__ __forceinline__ float leaky(float z){ return z >= 0.f ? z : 0.01f*z; }

// ---------------- GEMM: C(M,512) = A(M,128) @ W(512,128)^T + b1 + b2 -------
#define GP2 132
#define GEMM_SMEM (2*128*GP2*4)

__global__ void __launch_bounds__(256) gemm_k(const float* __restrict__ A,
                                              const float* __restrict__ W,
                                              const float* __restrict__ b1,
                                              const float* __restrict__ b2,
                                              float* __restrict__ C)
{
    extern __shared__ float sm[];
    float* As = sm;               // [k][m] pad GP2
    float* Ws = sm + 128*GP2;     // [k][n'] pad GP2
    const int tid = threadIdx.x;
    const int mbase = blockIdx.y * 128;
    const int nbase = blockIdx.x * 128;
    const int l = tid & 31;
    const int w = tid >> 5;

    const float4* A4 = (const float4*)(A + (size_t)mbase*128);
    const float4* W4 = (const float4*)W;
    #pragma unroll
    for (int r = 0; r < 16; r++) {
        int row = 8*w + (l & 7) + 64*(r >> 3);     // 0..127
        int kg  = 4*(r & 7) + (l >> 3);            // 0..31
        float4 va = A4[row*32 + kg];
        As[(4*kg+0)*GP2 + row] = va.x;
        As[(4*kg+1)*GP2 + row] = va.y;
        As[(4*kg+2)*GP2 + row] = va.z;
        As[(4*kg+3)*GP2 + row] = va.w;
        int srow = invperm(nbase + row);           // permuted W row source
        float4 vw = W4[srow*32 + kg];
        Ws[(4*kg+0)*GP2 + row] = vw.x;
        Ws[(4*kg+1)*GP2 + row] = vw.y;
        Ws[(4*kg+2)*GP2 + row] = vw.z;
        Ws[(4*kg+3)*GP2 + row] = vw.w;
    }
    __syncthreads();

    const int tx = tid & 15;   // n micro
    const int ty = tid >> 4;   // m micro
    const int m0 = ty*8, n0 = tx*8;

    F2U acc[4][8];
    #pragma unroll
    for (int p = 0; p < 4; p++)
        #pragma unroll
        for (int j = 0; j < 8; j++) acc[p][j].u = 0ull;

    #pragma unroll 8
    for (int k = 0; k < 128; k++) {
        const float4 a0 = *(const float4*)(As + k*GP2 + m0);
        const float4 a1 = *(const float4*)(As + k*GP2 + m0 + 4);
        const float4 w0 = *(const float4*)(Ws + k*GP2 + n0);
        const float4 w1 = *(const float4*)(Ws + k*GP2 + n0 + 4);
        ull ap0 = pk2(a0.x, a0.y), ap1 = pk2(a0.z, a0.w);
        ull ap2 = pk2(a1.x, a1.y), ap3 = pk2(a1.z, a1.w);
        ull wd;
        wd = dupf(w0.x); fma2(acc[0][0].u, ap0, wd); fma2(acc[1][0].u, ap1, wd); fma2(acc[2][0].u, ap2, wd); fma2(acc[3][0].u, ap3, wd);
        wd = dupf(w0.y); fma2(acc[0][1].u, ap0, wd); fma2(acc[1][1].u, ap1, wd); fma2(acc[2][1].u, ap2, wd); fma2(acc[3][1].u, ap3, wd);
        wd = dupf(w0.z); fma2(acc[0][2].u, ap0, wd); fma2(acc[1][2].u, ap1, wd); fma2(acc[2][2].u, ap2, wd); fma2(acc[3][2].u, ap3, wd);
        wd = dupf(w0.w); fma2(acc[0][3].u, ap0, wd); fma2(acc[1][3].u, ap1, wd); fma2(acc[2][3].u, ap2, wd); fma2(acc[3][3].u, ap3, wd);
        wd = dupf(w1.x); fma2(acc[0][4].u, ap0, wd); fma2(acc[1][4].u, ap1, wd); fma2(acc[2][4].u, ap2, wd); fma2(acc[3][4].u, ap3, wd);
        wd = dupf(w1.y); fma2(acc[0][5].u, ap0, wd); fma2(acc[1][5].u, ap1, wd); fma2(acc[2][5].u, ap2, wd); fma2(acc[3][5].u, ap3, wd);
        wd = dupf(w1.z); fma2(acc[0][6].u, ap0, wd); fma2(acc[1][6].u, ap1, wd); fma2(acc[2][6].u, ap2, wd); fma2(acc[3][6].u, ap3, wd);
        wd = dupf(w1.w); fma2(acc[0][7].u, ap0, wd); fma2(acc[1][7].u, ap1, wd); fma2(acc[2][7].u, ap2, wd); fma2(acc[3][7].u, ap3, wd);
    }

    const int col = nbase + n0;
    float bias[8];
    #pragma unroll
    for (int c = 0; c < 8; c++) {
        int src = invperm(col + c);
        bias[c] = b1[src] + b2[src];
    }

    #pragma unroll
    for (int p = 0; p < 4; p++) {
        float4 o;
        float* r0 = C + (size_t)(mbase + m0 + 2*p)*512 + col;
        float* r1 = r0 + 512;
        o.x = acc[p][0].f.x + bias[0]; o.y = acc[p][1].f.x + bias[1];
        o.z = acc[p][2].f.x + bias[2]; o.w = acc[p][3].f.x + bias[3];
        *(float4*)(r0) = o;
        o.x = acc[p][4].f.x + bias[4]; o.y = acc[p][5].f.x + bias[5];
        o.z = acc[p][6].f.x + bias[6]; o.w = acc[p][7].f.x + bias[7];
        *(float4*)(r0 + 4) = o;
        o.x = acc[p][0].f.y + bias[0]; o.y = acc[p][1].f.y + bias[1];
        o.z = acc[p][2].f.y + bias[2]; o.w = acc[p][3].f.y + bias[3];
        *(float4*)(r1) = o;
        o.x = acc[p][4].f.y + bias[4]; o.y = acc[p][5].f.y + bias[5];
        o.z = acc[p][6].f.y + bias[6]; o.w = acc[p][7].f.y + bias[7];
        *(float4*)(r1 + 4) = o;
    }
}

// ---------------- LSTM recurrence: one block per node ----------------------
// Quad-k-split (R10). Gate-3 weights now FP32 pairs in dynamic smem, laid out
// [chunk][thread] as ulonglong2 (conflict-free) -> zero unpack ALU in loop.
// Gates 0..2 fp32 in regs (96 regs). Single-MUFU activations (tanh.approx).
#define LSTM_SMEM (8*512*16 + 2*128*4 + 64)

template<int WRITE_ALL>
__global__ void __launch_bounds__(512, 1) lstm_rec(const float* __restrict__ xpre,
                                                   const float* __restrict__ Whh,
                                                   float* __restrict__ hout)
{
    extern __shared__ char smraw[];
    ulonglong2* ws3 = (ulonglong2*)smraw;              // [8][512] gate-3 f32 pairs
    float* hs0 = (float*)(smraw + 8*512*16);           // h double buffer
    float* hs1 = hs0 + 128;

    const int j = threadIdx.x;
    const int n = blockIdx.x;
    const int l = j & 31;
    const int w = j >> 5;
    const int q = l & 3;                          // gate index AND k-slice index
    const int cell = w*8 + (l >> 2);

    // weights: rows g*128+cell, k-slice [32q, 32q+32)
    ull wr[48];                                   // g = 0..2
    #pragma unroll
    for (int g = 0; g < 3; g++) {
        const float* wp = Whh + (g*128 + cell)*128 + 32*q;
        #pragma unroll
        for (int i = 0; i < 8; i++) {
            float4 v = *(const float4*)(wp + 4*i);
            wr[g*16 + 2*i]     = pk2(v.x, v.y);
            wr[g*16 + 2*i + 1] = pk2(v.z, v.w);
        }
    }
    {   // gate 3 -> smem as f32 pairs, chunk-major
        const float* wp = Whh + (3*128 + cell)*128 + 32*q;
        #pragma unroll
        for (int d = 0; d < 8; d++) {
            ulonglong2 pr;
            pr.x = pk2(wp[4*d+0], wp[4*d+1]);
            pr.y = pk2(wp[4*d+2], wp[4*d+3]);
            ws3[d*512 + j] = pr;
        }
    }

    if (j < 128) { hs0[j] = 0.f; hs1[j] = 0.f; }
    float c = 0.f;
    __syncthreads();

    const float* xp = xpre + (size_t)n*TT*512 + j;   // coalesced (permuted layout)
    float xnext = xp[0];
    float* hw = hout + (WRITE_ALL ? ((size_t)n*TT*128 + cell) : ((size_t)n*128 + cell));

    // swizzled write slot for this thread's h (only gate-0 lanes use it)
    const int wblk = cell >> 5;
    const int wslot = wblk*32 + (((cell & 31) + 8*wblk) & 31);

    int p = 0;
    for (int t = 0; t < TT; t++) {
        F2U A0, A1, A2, A3;
        A0.u = 0ull; A1.u = 0ull; A2.u = 0ull; A3.u = 0ull;
        float xcur = xnext;
        if (t + 1 < TT) xnext = xp[(size_t)(t+1)*512];

        const float* hb = (p ? hs1 : hs0) + q*32;
        #pragma unroll
        for (int s = 0; s < 4; s++) {
            // chunk d = 2s
            {
                ulonglong2 w3 = ws3[(2*s)*512 + j];
                int off = (8*s + 8*q) & 31;
                ulonglong2 hv = *(const ulonglong2*)(hb + off);
                fma2(A0.u, wr[4*s],      hv.x); fma2(A0.u, wr[4*s+1],      hv.y);
                fma2(A1.u, wr[16+4*s],   hv.x); fma2(A1.u, wr[16+4*s+1],   hv.y);
                fma2(A2.u, wr[32+4*s],   hv.x); fma2(A2.u, wr[32+4*s+1],   hv.y);
                fma2(A3.u, w3.x,         hv.x); fma2(A3.u, w3.y,           hv.y);
            }
            // chunk d = 2s+1
            {
                ulonglong2 w3 = ws3[(2*s+1)*512 + j];
                int off = (8*s + 4 + 8*q) & 31;
                ulonglong2 hv = *(const ulonglong2*)(hb + off);
                fma2(A0.u, wr[4*s+2],    hv.x); fma2(A0.u, wr[4*s+3],      hv.y);
                fma2(A1.u, wr[16+4*s+2], hv.x); fma2(A1.u, wr[16+4*s+3],   hv.y);
                fma2(A2.u, wr[32+4*s+2], hv.x); fma2(A2.u, wr[32+4*s+3],   hv.y);
                fma2(A3.u, w3.x,         hv.x); fma2(A3.u, w3.y,           hv.y);
            }
        }

        float p0 = A0.f.x + A0.f.y;
        float p1 = A1.f.x + A1.f.y;
        float p2 = A2.f.x + A2.f.y;
        float p3 = A3.f.x + A3.f.y;

        // quad transpose-reduce: lane q ends with full dot for gate q
        ull lo = pk2(p0, p1), hi = pk2(p2, p3);
        ull send = (l & 2) ? lo : hi;
        ull recv = shfl_xor64(send, 2);
        ull keep = (l & 2) ? hi : lo;
        F2U s2; s2.u = add2(keep, recv);
        float mine  = (l & 1) ? s2.f.y : s2.f.x;
        float sendf = (l & 1) ? s2.f.x : s2.f.y;
        float other = __shfl_xor_sync(0xFFFFFFFFu, sendf, 1);
        float acc = mine + other + xcur;

        // single-MUFU activations: sigmoid(x) = 0.5 + 0.5*tanh(x/2)
        const bool isg = (q == 2);
        float u  = isg ? acc : 0.5f*acc;
        float th = tanh_ap(u);
        float a  = isg ? th : fmaf(0.5f, th, 0.5f);

        const int base = l & ~3;
        float iv = __shfl_sync(0xFFFFFFFFu, a, base);
        float fv = __shfl_sync(0xFFFFFFFFu, a, base + 1);
        float gv = __shfl_sync(0xFFFFFFFFu, a, base + 2);
        float ov = __shfl_sync(0xFFFFFFFFu, a, base + 3);
        c = fv*c + iv*gv;
        float hv = ov * tanh_ap(c);
        p ^= 1;
        if (q == 0) {
            (p ? hs1 : hs0)[wslot] = hv;
            if (WRITE_ALL)      hw[(size_t)t*128] = hv;
            else if (t == TT-1) hw[0] = hv;
        }
        __syncthreads();
    }
}

// ---------------- E0: pseudo-message projections + direct outputs ----------
__global__ void prep_kernel(const float* __restrict__ x_tag,
                            const float* __restrict__ pm,
                            const float* __restrict__ Wvm,
                            float* __restrict__ out, int osz)
{
    const int tid = threadIdx.x;  // 128
    __shared__ float pms[768];
    for (int i = tid; i < 768; i += 128) pms[i] = pm[i];
    __syncthreads();

    float base = 0.f;
    for (int k = 0; k < 768; k++) base += pms[k]*Wvm[k*128 + tid];
    g_vm[tid]       = leaky(base);
    g_vm[128 + tid] = leaky(base + Wvm[768*128 + tid]);

    if (tid < NNODE) {
        int o;
        o = 236 + tid*2 + 0; if (o < osz) out[o] = x_tag[tid*3+0];
        o = 236 + tid*2 + 1; if (o < osz) out[o] = x_tag[tid*3+1];
        float a = x_tag[tid*3+2];
        o = 474 + tid; if (o < osz) out[o] = (a == 0.f) ? 1.f : 0.f;
        o = 592 + tid; if (o < osz) out[o] = (a == 1.f) ? 1.f : 0.f;
    }
    if (tid == 0) {
        int cnt = 0;
        for (int i = 0; i < NNODE; i++) if (x_tag[i*3+2] == 0.f) cnt++;
        g_flag[0] = (cnt > 0) ? 1.f : 0.f;
    }
}

// ---------------- Gram matrices for l_ort -----------------------------
__global__ void gram_kernel(const float* __restrict__ Wum, const float* __restrict__ Wvm,
                            const float* __restrict__ Wup, const float* __restrict__ Wvp)
{
    const int bid = blockIdx.x;
    const int mat = bid >> 7;
    const int k   = bid & 127;
    const int l   = threadIdx.x;  // 128
    const float* W; int rows;
    if      (mat == 0) { W = Wum; rows = 769; }
    else if (mat == 1) { W = Wvm; rows = 769; }
    else if (mat == 2) { W = Wup; rows = 128; }
    else               { W = Wvp; rows = 128; }
    float acc = 0.f;
    for (int i = 0; i < rows; i++) acc += W[i*128 + k] * W[i*128 + l];
    g_G[mat*16384 + k*128 + l] = acc;
}

// ---------------- E1: per-node MLP chain -> n -------------------------
__global__ void node_kernel(const float* __restrict__ x_tag,
                            const float* __restrict__ Wup,
                            const float* __restrict__ W_hyb, const float* __restrict__ b_hyb,
                            const float* __restrict__ W_act, const float* __restrict__ b_act,
                            const float* __restrict__ W_inact, const float* __restrict__ b_inact)
{
    const int n = blockIdx.x, tid = threadIdx.x;  // 256
    __shared__ float p[128], up[128], vm_s[128], hh[256];
    const float act = x_tag[n*3+2];
    if (tid < 128) {
        p[tid]    = leaky(g_h2last[n*128 + tid]);
        vm_s[tid] = (act == 1.f) ? g_vm[128 + tid] : g_vm[tid];
    }
    __syncthreads();
    if (tid < 128) {
        float a = 0.f;
        for (int k = 0; k < 128; k++) a += p[k]*Wup[k*128 + tid];
        up[tid] = leaky(a);
    }
    __syncthreads();
    {
        float a = b_hyb[tid];
        for (int k = 0; k < 128; k++) {
            float u_ = up[k], v_ = vm_s[k];
            a += u_*W_hyb[k*256 + tid] + (u_ + v_)*W_hyb[(128+k)*256 + tid] + v_*W_hyb[(256+k)*256 + tid];
        }
        hh[tid] = leaky(a);
    }
    __syncthreads();
    {
        float na = b_act[tid], ni = b_inact[tid];
        for (int k = 0; k < 256; k++) {
            float h_ = hh[k];
            na += h_*W_act[k*256 + tid];
            ni += h_*W_inact[k*256 + tid];
        }
        na += x_tag[n*3+0]*W_act[256*256 + tid] + x_tag[n*3+1]*W_act[257*256 + tid];
        g_n[n*256 + tid] = leaky(na*(1.f - act) + ni*act);
    }
}

// ---------------- E2: per-node pair projections -----------------------
__global__ void proj_kernel(const float* __restrict__ Wphin,
                            const float* __restrict__ Won,
                            const float* __restrict__ Weo)
{
    const int n = blockIdx.x, tid = threadIdx.x;  // 256
    __shared__ float nn_s[256];
    nn_s[tid] = g_n[n*256 + tid];
    __syncthreads();
    if (tid < 192) {
        float pb = 0.f, pa = 0.f;
        for (int k = 0; k < 256; k++) {
            float v = nn_s[k];
            pb += v*Wphin[k*192 + tid];
            pa += v*Wphin[(256+k)*192 + tid];
        }
        g_Pb[n*192 + tid] = pb;
        g_Pa[n*192 + tid] = pa;
    }
    float qb = 0.f, qa = 0.f, rb = 0.f, ra = 0.f;
    for (int k = 0; k < 256; k++) {
        float v = nn_s[k];
        qb += v*Won[k*256 + tid];
        qa += v*Won[(256+k)*256 + tid];
        rb += v*Weo[(256+k)*256 + tid];
        ra += v*Weo[(512+k)*256 + tid];
    }
    g_Qb[n*256 + tid] = qb;
    g_Qa[n*256 + tid] = qa;
    g_Rb[n*256 + tid] = rb;
    g_Ra[n*256 + tid] = ra;
}

// ---------------- E3: phi column + masked softmaxes -> alpha ----------
__device__ __forceinline__ float blockmax128(float v, float* red){
    int tid = threadIdx.x; red[tid] = v; __syncthreads();
    #pragma unroll
    for (int s = 64; s > 0; s >>= 1) { if (tid < s) red[tid] = fmaxf(red[tid], red[tid+s]); __syncthreads(); }
    float r = red[0]; __syncthreads(); return r;
}
__device__ __forceinline__ float blocksum128(float v, float* red){
    int tid = threadIdx.x; red[tid] = v; __syncthreads();
    #pragma unroll
    for (int s = 64; s > 0; s >>= 1) { if (tid < s) red[tid] += red[tid+s]; __syncthreads(); }
    float r = red[0]; __syncthreads(); return r;
}

__global__ void phi_alpha_kernel(const float* __restrict__ x_tag,
                                 const float* __restrict__ aphi)
{
    const int b = blockIdx.x;
    const int tid = threadIdx.x;  // 128
    __shared__ float pb_s[192], ap_s[192], red[128];
    for (int i = tid; i < 192; i += 128) { pb_s[i] = g_Pb[b*192 + i]; ap_s[i] = aphi[i]; }
    __syncthreads();

    float ph = 0.f, v1 = 0.f;
    if (tid < NNODE) {
        const float* pa = g_Pa + tid*192;
        #pragma unroll 8
        for (int d = 0; d < 192; d++) ph += leaky(pb_s[d] + pa[d]) * ap_s[d];
        v1 = (x_tag[tid*3+2] == 0.f) ? 1.f : 0.f;
    }

    const float NEG = -1000000000.f;
    float m1 = (tid < NNODE) ? (v1 > 0.f ? ph : NEG) : -INFINITY;
    float m0 = (tid < NNODE) ? (v1 > 0.f ? NEG : ph) : -INFINITY;
    float ma = (tid < NNODE) ? ph : -INFINITY;

    float mx = blockmax128(m1, red);
    float e  = (tid < NNODE) ? __expf(m1 - mx) : 0.f;
    float s  = blocksum128(e, red);
    float sm1 = e / s;

    mx = blockmax128(m0, red);
    e  = (tid < NNODE) ? __expf(m0 - mx) : 0.f;
    s  = blocksum128(e, red);
    float sm0 = e / s;

    mx = blockmax128(ma, red);
    e  = (tid < NNODE) ? __expf(ma - mx) : 0.f;
    s  = blocksum128(e, red);
    float sma = e / s;

    if (tid < NNODE) {
        float a = (g_flag[0] > 0.f) ? (v1 > 0.f ? sm1 : sm0) : sma;
        g_alpha[tid*NNODE + b] = a;
    }
}

// ---------------- E4: hyper messages + y_hat --------------------------
__global__ void hyper_kernel(const float* __restrict__ x_tag,
                             const float* __restrict__ Weo,
                             const float* __restrict__ Wi,
                             const float* __restrict__ bi,
                             float* __restrict__ out, int osz)
{
    const int n = blockIdx.x, tid = threadIdx.x;  // 256
    __shared__ float qa[256], ra[256], nn_s[256], u[256], al[NNODE], red[256];
    qa[tid]   = g_Qa[n*256 + tid];
    ra[tid]   = g_Ra[n*256 + tid];
    nn_s[tid] = g_n[n*256 + tid];
    if (tid < NNODE) al[tid] = g_alpha[n*NNODE + tid];
    __syncthreads();

    float uacc = 0.f, racc = 0.f, alsum = 0.f;
    const float qad = qa[tid];
    for (int j = 0; j < NNODE; j++) {
        float a_ = al[j];
        uacc  += a_ * leaky(g_Qb[j*256 + tid] + qad);
        racc  += a_ * g_Rb[j*256 + tid];
        alsum += a_;
    }
    u[tid] = uacc;
    __syncthreads();

    float T = racc + alsum*ra[tid];
    for (int k = 0; k < 256; k++) T += u[k]*Weo[k*256 + tid];

    const float act = x_tag[n*3+2];
    float hm0 = leaky(act*T);
    float hm1 = leaky((1.f - act)*T);

    const float* Win = Wi + (size_t)n*768*2;
    float p0 = nn_s[tid]*Win[tid*2+0] + hm0*Win[(256+tid)*2+0] + hm1*Win[(512+tid)*2+0];
    float p1 = nn_s[tid]*Win[tid*2+1] + hm0*Win[(256+tid)*2+1] + hm1*Win[(512+tid)*2+1];

    red[tid] = p0; __syncthreads();
    #pragma unroll
    for (int s = 128; s > 0; s >>= 1) { if (tid < s) red[tid] += red[tid+s]; __syncthreads(); }
    float y0 = red[0] + bi[n*2+0]; __syncthreads();

    red[tid] = p1; __syncthreads();
    #pragma unroll
    for (int s = 128; s > 0; s >>= 1) { if (tid < s) red[tid] += red[tid+s]; __syncthreads(); }
    float y1 = red[0] + bi[n*2+1];

    if (tid == 0) {
        float mx = fmaxf(y0, y1);
        float e0 = __expf(y0 - mx), e1 = __expf(y1 - mx);
        int o;
        o = n*2+0; if (o < osz) out[o] = e0/(e0+e1);
        o = n*2+1; if (o < osz) out[o] = e1/(e0+e1);
    }
}

// ---------------- E5: l_ort + l_pol -----------------------------------
__global__ void finals_kernel(const float* __restrict__ x_tag,
                              float* __restrict__ out, int osz)
{
    const int tid = threadIdx.x;  // 256
    __shared__ float red[256], w[NNODE];

    float s1 = 0.f, s2 = 0.f;
    for (int i = tid; i < 16384; i += 256) {
        s1 += g_G[i]          * g_G[16384 + i];
        s2 += g_G[32768 + i]  * g_G[49152 + i];
    }
    red[tid] = s1; __syncthreads();
    #pragma unroll
    for (int s = 128; s > 0; s >>= 1) { if (tid < s) red[tid] += red[tid+s]; __syncthreads(); }
    float S1 = red[0]; __syncthreads();
    red[tid] = s2; __syncthreads();
    #pragma unroll
    for (int s = 128; s > 0; s >>= 1) { if (tid < s) red[tid] += red[tid+s]; __syncthreads(); }
    float S2 = red[0]; __syncthreads();
    if (tid == 0 && 472 < osz) out[472] = sqrtf(S1) + sqrtf(S2);

    if (tid < NNODE) {
        float nr = 0.f;
        const float* np = g_n + tid*256;
        for (int d = 0; d < 256; d++) nr += np[d]*np[d];
        nr = fmaxf(sqrtf(nr), 1e-8f);
        float diff = x_tag[tid*3+1] - x_tag[tid*3+0];
        float sg = (diff > 0.f ? 1.f : (diff < 0.f ? -1.f : 0.f));
        sg *= (x_tag[tid*3+2] == 0.f) ? 1.f : 0.f;
        w[tid] = sg / nr;
    }
    __syncthreads();
    float v = 0.f;
    for (int i = 0; i < NNODE; i++) v += w[i]*g_n[i*256 + tid];
    red[tid] = v*v; __syncthreads();
    #pragma unroll
    for (int s = 128; s > 0; s >>= 1) { if (tid < s) red[tid] += red[tid+s]; __syncthreads(); }
    if (tid == 0 && 473 < osz) out[473] = red[0];
}

// ---------------- launch ----------------------------------------------
extern "C" void kernel_launch(void* const* d_in, const int* in_sizes, int n_in,
                              void* d_out, int out_size)
{
    const float* x       = (const float*)d_in[0];
    const float* x_tag   = (const float*)d_in[1];
    const float* W_ih0   = (const float*)d_in[2];
    const float* W_hh0   = (const float*)d_in[3];
    const float* b_ih0   = (const float*)d_in[4];
    const float* b_hh0   = (const float*)d_in[5];
    const float* W_ih1   = (const float*)d_in[6];
    const float* W_hh1   = (const float*)d_in[7];
    const float* b_ih1   = (const float*)d_in[8];
    const float* b_hh1   = (const float*)d_in[9];
    const float* pm      = (const float*)d_in[10];
    const float* Wum     = (const float*)d_in[11];
    const float* Wvm     = (const float*)d_in[12];
    const float* Wup     = (const float*)d_in[13];
    const float* Wvp     = (const float*)d_in[14];
    const float* W_hyb   = (const float*)d_in[15];
    const float* b_hyb   = (const float*)d_in[16];
    const float* W_act   = (const float*)d_in[17];
    const float* b_act   = (const float*)d_in[18];
    const float* W_inact = (const float*)d_in[19];
    const float* b_inact = (const float*)d_in[20];
    const float* Wphin   = (const float*)d_in[21];
    const float* aphi    = (const float*)d_in[22];
    const float* Won     = (const float*)d_in[23];
    const float* Weo     = (const float*)d_in[24];
    const float* Wi      = (const float*)d_in[25];
    const float* bi      = (const float*)d_in[26];
    float* out = (float*)d_out;

    float *xpre = nullptr, *h1 = nullptr, *h2last = nullptr;
    cudaGetSymbolAddress((void**)&xpre,   g_xpre);
    cudaGetSymbolAddress((void**)&h1,     g_h1);
    cudaGetSymbolAddress((void**)&h2last, g_h2last);

    cudaFuncSetAttribute(gemm_k, cudaFuncAttributeMaxDynamicSharedMemorySize, GEMM_SMEM);
    cudaFuncSetAttribute(lstm_rec<1>, cudaFuncAttributeMaxDynamicSharedMemorySize, LSTM_SMEM);
    cudaFuncSetAttribute(lstm_rec<0>, cudaFuncAttributeMaxDynamicSharedMemorySize, LSTM_SMEM);

    dim3 gg(4, M_ROWS/128);

    // layer 0
    gemm_k<<<gg, 256, GEMM_SMEM>>>(x, W_ih0, b_ih0, b_hh0, xpre);
    lstm_rec<1><<<NNODE, 512, LSTM_SMEM>>>(xpre, W_hh0, h1);
    // layer 1
    gemm_k<<<gg, 256, GEMM_SMEM>>>(h1, W_ih1, b_ih1, b_hh1, xpre);
    lstm_rec<0><<<NNODE, 512, LSTM_SMEM>>>(xpre, W_hh1, h2last);

    // epilogue
    prep_kernel<<<1, 128>>>(x_tag, pm, Wvm, out, out_size);
    gram_kernel<<<512, 128>>>(Wum, Wvm, Wup, Wvp);
    node_kernel<<<NNODE, 256>>>(x_tag, Wup, W_hyb, b_hyb, W_act, b_act, W_inact, b_inact);
    proj_kernel<<<NNODE, 256>>>(Wphin, Won, Weo);
    phi_alpha_kernel<<<NNODE, 128>>>(x_tag, aphi);
    hyper_kernel<<<NNODE, 256>>>(x_tag, Weo, Wi, bi, out, out_size);
    finals_kernel<<<1, 256>>>(x_tag, out, out_size);
}

// round 14
// speedup vs baseline: 1.5234x; 1.2164x over previous
#include <cuda_runtime.h>
#include <math.h>

#define NNODE 118
#define TT 2048
#define M_ROWS (NNODE*TT)

typedef unsigned long long ull;
typedef unsigned short u16;
union F2U { ull u; float2 f; };

__device__ __forceinline__ ull pk2(float x, float y){ ull r; asm("mov.b64 %0, {%1,%2};" : "=l"(r) : "f"(x), "f"(y)); return r; }
__device__ __forceinline__ void fma2(ull& d, ull a, ull b){ asm("fma.rn.f32x2 %0, %1, %2, %0;" : "+l"(d) : "l"(a), "l"(b)); }
__device__ __forceinline__ ull add2(ull a, ull b){ ull r; asm("add.rn.f32x2 %0, %1, %2;" : "=l"(r) : "l"(a), "l"(b)); return r; }
__device__ __forceinline__ float tanh_ap(float x){ float r; asm("tanh.approx.f32 %0, %1;" : "=f"(r) : "f"(x)); return r; }

__device__ __forceinline__ unsigned bf1(float f){
    unsigned b = __float_as_uint(f);
    return (b + 0x7FFFu + ((b >> 16) & 1u)) >> 16;   // RNE
}
__device__ __forceinline__ float bf2f(unsigned h){ return __uint_as_float(h << 16); }

__device__ __forceinline__ ull shfl_xor64(ull v, int m){
    unsigned lo = (unsigned)v, hi = (unsigned)(v >> 32);
    lo = __shfl_xor_sync(0xFFFFFFFFu, lo, m);
    hi = __shfl_xor_sync(0xFFFFFFFFu, hi, m);
    return ((ull)hi << 32) | lo;
}

// column permutation: semantic gate-major n (= g*128+c)  <->  stored col' = 4c+g
__device__ __forceinline__ int invperm(int cp){ return (cp & 3)*128 + (cp >> 2); }

__device__ __forceinline__ unsigned sm2u(const void* p){
    unsigned r; asm("{ .reg .u64 t; cvta.to.shared.u64 t, %1; cvt.u32.u64 %0, t; }" : "=r"(r) : "l"(p)); return r;
}

// ---------------- scratch (device globals; no allocation allowed) ----------
__device__ __align__(256) float g_xpre[(size_t)M_ROWS*512];
__device__ __align__(256) float g_h1[(size_t)M_ROWS*128];
__device__ __align__(256) u16   g_xh[(size_t)M_ROWS*128];
__device__ __align__(256) u16   g_xl[(size_t)M_ROWS*128];
__device__ __align__(256) u16   g_wh[512*128];
__device__ __align__(256) u16   g_wl[512*128];
__device__ __align__(256) float g_bias[512];
__device__ __align__(256) float g_h2last[NNODE*128];
__device__ __align__(256) float g_vm[2*128];
__device__ __align__(256) float g_flag[1];
__device__ __align__(256) float g_n[NNODE*256];
__device__ __align__(256) float g_Pa[NNODE*192];
__device__ __align__(256) float g_Pb[NNODE*192];
__device__ __align__(256) float g_Qa[NNODE*256];
__device__ __align__(256) float g_Qb[NNODE*256];
__device__ __align__(256) float g_Ra[NNODE*256];
__device__ __align__(256) float g_Rb[NNODE*256];
__device__ __align__(256) float g_alpha[NNODE*NNODE];
__device__ __align__(256) float g_G[4*128*128];

__device__ __forceinline__ float leaky(float z){ return z >= 0.f ? z : 0.01f*z; }

// ---------------- conversion kernels -------------------------------------
__global__ void convW(const float* __restrict__ W,
                      const float* __restrict__ b1,
                      const float* __restrict__ b2)
{
    const int r = threadIdx.x;            // stored row 0..511
    const int srow = invperm(r);
    g_bias[r] = b1[srow] + b2[srow];
    const float* wp = W + srow*128;
    for (int k = 0; k < 128; k++) {
        float w = wp[k];
        unsigned hb = bf1(w);
        float lo = w - bf2f(hb);
        g_wh[r*128 + k] = (u16)hb;
        g_wl[r*128 + k] = (u16)bf1(lo);
    }
}

__global__ void convX(const float* __restrict__ src)
{
    size_t n4 = (size_t)M_ROWS*128/4;
    size_t stride = (size_t)gridDim.x*blockDim.x;
    for (size_t i = blockIdx.x*(size_t)blockDim.x + threadIdx.x; i < n4; i += stride) {
        float4 v = ((const float4*)src)[i];
        ushort4 h, l;
        unsigned hb;
        hb = bf1(v.x); h.x = (u16)hb; l.x = (u16)bf1(v.x - bf2f(hb));
        hb = bf1(v.y); h.y = (u16)hb; l.y = (u16)bf1(v.y - bf2f(hb));
        hb = bf1(v.z); h.z = (u16)hb; l.z = (u16)bf1(v.z - bf2f(hb));
        hb = bf1(v.w); h.w = (u16)hb; l.w = (u16)bf1(v.w - bf2f(hb));
        ((ushort4*)g_xh)[i] = h;
        ((ushort4*)g_xl)[i] = l;
    }
}

// ---------------- mma.sync GEMM: C(M,512) = A @ W^T (bf16, 3-pass) ---------
// Per CTA: M-tile 128 resident (xh/xl smem), loop 4 N-tiles of W (hi/lo).
// 8 warps as 4x2; warp tile 32x64; mma.m16n8k16.row.col.f32.bf16.
// smem rows padded to 136 halfs (272 B) -> conflict-free ldmatrix.
#define MA_AH 0
#define MA_AL 34816
#define MA_WH 69632
#define MA_WL 104448
#define MA_BIAS 139264
#define MA_SMEM 139776

__device__ __forceinline__ void ldsm4(unsigned r[4], unsigned addr){
    asm volatile("ldmatrix.sync.aligned.m8n8.x4.shared.b16 {%0,%1,%2,%3}, [%4];"
        : "=r"(r[0]), "=r"(r[1]), "=r"(r[2]), "=r"(r[3]) : "r"(addr));
}
__device__ __forceinline__ void mma16816(float d[4], const unsigned a[4], unsigned b0, unsigned b1){
    asm volatile("mma.sync.aligned.m16n8k16.row.col.f32.bf16.bf16.f32 "
        "{%0,%1,%2,%3}, {%4,%5,%6,%7}, {%8,%9}, {%0,%1,%2,%3};"
        : "+f"(d[0]), "+f"(d[1]), "+f"(d[2]), "+f"(d[3])
        : "r"(a[0]), "r"(a[1]), "r"(a[2]), "r"(a[3]), "r"(b0), "r"(b1));
}

__global__ void __launch_bounds__(256) gemm_mma(const u16* __restrict__ xh,
                                                const u16* __restrict__ xl,
                                                float* __restrict__ C)
{
    extern __shared__ char sm[];
    const unsigned smb = sm2u(sm);
    float* bias_s = (float*)(sm + MA_BIAS);
    const int tid = threadIdx.x;
    const int lane = tid & 31;
    const int w = tid >> 5;
    const int wr = w & 3;          // warp row (32 m-rows)
    const int wc = w >> 2;         // warp col (64 n-cols)
    const int mbase = blockIdx.x * 128;

    // load A tiles (hi/lo), 8 uint4 per thread per tile
    #pragma unroll
    for (int i = 0; i < 8; i++) {
        int idx = tid + i*256;          // 0..2047
        int row = idx >> 4;
        int c16 = idx & 15;
        size_t src = ((size_t)(mbase + row))*16 + c16;
        *(uint4*)(sm + MA_AH + row*272 + c16*16) = ((const uint4*)xh)[src];
        *(uint4*)(sm + MA_AL + row*272 + c16*16) = ((const uint4*)xl)[src];
    }
    __syncthreads();

    // per-lane ldmatrix base offsets
    const unsigned baseA = (unsigned)((wr*32 + ((lane>>3)&1)*8 + (lane&7))*272 + (lane>>4)*16);
    const unsigned baseB = (unsigned)((wc*64 + (lane>>4)*8 + (lane&7))*272 + ((lane>>3)&1)*16);

    for (int nt = 0; nt < 4; nt++) {
        // load W tiles (hi/lo) for n-rows [128nt, 128nt+128)
        #pragma unroll
        for (int i = 0; i < 8; i++) {
            int idx = tid + i*256;
            int row = idx >> 4;
            int c16 = idx & 15;
            size_t src = ((size_t)(nt*128 + row))*16 + c16;
            *(uint4*)(sm + MA_WH + row*272 + c16*16) = ((const uint4*)g_wh)[src];
            *(uint4*)(sm + MA_WL + row*272 + c16*16) = ((const uint4*)g_wl)[src];
        }
        if (tid < 128) bias_s[tid] = g_bias[nt*128 + tid];
        __syncthreads();

        float acc[2][8][4];
        #pragma unroll
        for (int mi = 0; mi < 2; mi++)
            #pragma unroll
            for (int j = 0; j < 8; j++)
                #pragma unroll
                for (int e = 0; e < 4; e++) acc[mi][j][e] = 0.f;

        #pragma unroll
        for (int pass = 0; pass < 3; pass++) {
            const unsigned Ab = smb + ((pass == 2) ? MA_AL : MA_AH) + baseA;
            const unsigned Bb = smb + ((pass == 1) ? MA_WL : MA_WH) + baseB;
            #pragma unroll
            for (int ks = 0; ks < 8; ks++) {
                unsigned af[2][4], bf[4][4];
                ldsm4(af[0], Ab + ks*32);
                ldsm4(af[1], Ab + 4352 + ks*32);
                #pragma unroll
                for (int j = 0; j < 4; j++) ldsm4(bf[j], Bb + j*4352 + ks*32);
                #pragma unroll
                for (int mi = 0; mi < 2; mi++) {
                    #pragma unroll
                    for (int j = 0; j < 4; j++) {
                        mma16816(acc[mi][2*j],   af[mi], bf[j][0], bf[j][1]);
                        mma16816(acc[mi][2*j+1], af[mi], bf[j][2], bf[j][3]);
                    }
                }
            }
        }

        // store with bias
        const int r0 = mbase + wr*32 + (lane >> 2);
        #pragma unroll
        for (int mi = 0; mi < 2; mi++) {
            #pragma unroll
            for (int j = 0; j < 8; j++) {
                int cl = wc*64 + j*8 + (lane & 3)*2;
                float b0 = bias_s[cl], b1 = bias_s[cl+1];
                float* p0 = C + (size_t)(r0 + mi*16)*512 + nt*128 + cl;
                float2 v0 = { acc[mi][j][0] + b0, acc[mi][j][1] + b1 };
                float2 v1 = { acc[mi][j][2] + b0, acc[mi][j][3] + b1 };
                *(float2*)p0 = v0;
                *(float2*)(p0 + 8*512) = v1;
            }
        }
        __syncthreads();
    }
}

// ---------------- LSTM recurrence (unchanged from R12) ---------------------
#define LSTM_SMEM (8*512*16 + 2*128*4 + 64)

template<int WRITE_ALL>
__global__ void __launch_bounds__(512, 1) lstm_rec(const float* __restrict__ xpre,
                                                   const float* __restrict__ Whh,
                                                   float* __restrict__ hout)
{
    extern __shared__ char smraw[];
    ulonglong2* ws3 = (ulonglong2*)smraw;              // [8][512] gate-3 f32 pairs
    float* hs0 = (float*)(smraw + 8*512*16);           // h double buffer
    float* hs1 = hs0 + 128;

    const int j = threadIdx.x;
    const int n = blockIdx.x;
    const int l = j & 31;
    const int w = j >> 5;
    const int q = l & 3;
    const int cell = w*8 + (l >> 2);

    ull wr[48];
    #pragma unroll
    for (int g = 0; g < 3; g++) {
        const float* wp = Whh + (g*128 + cell)*128 + 32*q;
        #pragma unroll
        for (int i = 0; i < 8; i++) {
            float4 v = *(const float4*)(wp + 4*i);
            wr[g*16 + 2*i]     = pk2(v.x, v.y);
            wr[g*16 + 2*i + 1] = pk2(v.z, v.w);
        }
    }
    {
        const float* wp = Whh + (3*128 + cell)*128 + 32*q;
        #pragma unroll
        for (int d = 0; d < 8; d++) {
            ulonglong2 pr;
            pr.x = pk2(wp[4*d+0], wp[4*d+1]);
            pr.y = pk2(wp[4*d+2], wp[4*d+3]);
            ws3[d*512 + j] = pr;
        }
    }

    if (j < 128) { hs0[j] = 0.f; hs1[j] = 0.f; }
    float c = 0.f;
    __syncthreads();

    const float* xp = xpre + (size_t)n*TT*512 + j;
    float xnext = xp[0];
    float* hw = hout + (WRITE_ALL ? ((size_t)n*TT*128 + cell) : ((size_t)n*128 + cell));

    const int wblk = cell >> 5;
    const int wslot = wblk*32 + (((cell & 31) + 8*wblk) & 31);

    int p = 0;
    for (int t = 0; t < TT; t++) {
        F2U A0, A1, A2, A3;
        A0.u = 0ull; A1.u = 0ull; A2.u = 0ull; A3.u = 0ull;
        float xcur = xnext;
        if (t + 1 < TT) xnext = xp[(size_t)(t+1)*512];

        const float* hb = (p ? hs1 : hs0) + q*32;
        #pragma unroll
        for (int s = 0; s < 4; s++) {
            {
                ulonglong2 w3 = ws3[(2*s)*512 + j];
                int off = (8*s + 8*q) & 31;
                ulonglong2 hv = *(const ulonglong2*)(hb + off);
                fma2(A0.u, wr[4*s],      hv.x); fma2(A0.u, wr[4*s+1],      hv.y);
                fma2(A1.u, wr[16+4*s],   hv.x); fma2(A1.u, wr[16+4*s+1],   hv.y);
                fma2(A2.u, wr[32+4*s],   hv.x); fma2(A2.u, wr[32+4*s+1],   hv.y);
                fma2(A3.u, w3.x,         hv.x); fma2(A3.u, w3.y,           hv.y);
            }
            {
                ulonglong2 w3 = ws3[(2*s+1)*512 + j];
                int off = (8*s + 4 + 8*q) & 31;
                ulonglong2 hv = *(const ulonglong2*)(hb + off);
                fma2(A0.u, wr[4*s+2],    hv.x); fma2(A0.u, wr[4*s+3],      hv.y);
                fma2(A1.u, wr[16+4*s+2], hv.x); fma2(A1.u, wr[16+4*s+3],   hv.y);
                fma2(A2.u, wr[32+4*s+2], hv.x); fma2(A2.u, wr[32+4*s+3],   hv.y);
                fma2(A3.u, w3.x,         hv.x); fma2(A3.u, w3.y,           hv.y);
            }
        }

        float p0 = A0.f.x + A0.f.y;
        float p1 = A1.f.x + A1.f.y;
        float p2 = A2.f.x + A2.f.y;
        float p3 = A3.f.x + A3.f.y;

        ull lo = pk2(p0, p1), hi = pk2(p2, p3);
        ull send = (l & 2) ? lo : hi;
        ull recv = shfl_xor64(send, 2);
        ull keep = (l & 2) ? hi : lo;
        F2U s2; s2.u = add2(keep, recv);
        float mine  = (l & 1) ? s2.f.y : s2.f.x;
        float sendf = (l & 1) ? s2.f.x : s2.f.y;
        float other = __shfl_xor_sync(0xFFFFFFFFu, sendf, 1);
        float acc = mine + other + xcur;

        const bool isg = (q == 2);
        float u  = isg ? acc : 0.5f*acc;
        float th = tanh_ap(u);
        float a  = isg ? th : fmaf(0.5f, th, 0.5f);

        const int base = l & ~3;
        float iv = __shfl_sync(0xFFFFFFFFu, a, base);
        float fv = __shfl_sync(0xFFFFFFFFu, a, base + 1);
        float gv = __shfl_sync(0xFFFFFFFFu, a, base + 2);
        float ov = __shfl_sync(0xFFFFFFFFu, a, base + 3);
        c = fv*c + iv*gv;
        float hv = ov * tanh_ap(c);
        p ^= 1;
        if (q == 0) {
            (p ? hs1 : hs0)[wslot] = hv;
            if (WRITE_ALL)      hw[(size_t)t*128] = hv;
            else if (t == TT-1) hw[0] = hv;
        }
        __syncthreads();
    }
}

// ---------------- E0: pseudo-message projections + direct outputs ----------
__global__ void prep_kernel(const float* __restrict__ x_tag,
                            const float* __restrict__ pm,
                            const float* __restrict__ Wvm,
                            float* __restrict__ out, int osz)
{
    const int tid = threadIdx.x;  // 128
    __shared__ float pms[768];
    for (int i = tid; i < 768; i += 128) pms[i] = pm[i];
    __syncthreads();

    float base = 0.f;
    for (int k = 0; k < 768; k++) base += pms[k]*Wvm[k*128 + tid];
    g_vm[tid]       = leaky(base);
    g_vm[128 + tid] = leaky(base + Wvm[768*128 + tid]);

    if (tid < NNODE) {
        int o;
        o = 236 + tid*2 + 0; if (o < osz) out[o] = x_tag[tid*3+0];
        o = 236 + tid*2 + 1; if (o < osz) out[o] = x_tag[tid*3+1];
        float a = x_tag[tid*3+2];
        o = 474 + tid; if (o < osz) out[o] = (a == 0.f) ? 1.f : 0.f;
        o = 592 + tid; if (o < osz) out[o] = (a == 1.f) ? 1.f : 0.f;
    }
    if (tid == 0) {
        int cnt = 0;
        for (int i = 0; i < NNODE; i++) if (x_tag[i*3+2] == 0.f) cnt++;
        g_flag[0] = (cnt > 0) ? 1.f : 0.f;
    }
}

// ---------------- Gram matrices for l_ort -----------------------------
__global__ void gram_kernel(const float* __restrict__ Wum, const float* __restrict__ Wvm,
                            const float* __restrict__ Wup, const float* __restrict__ Wvp)
{
    const int bid = blockIdx.x;
    const int mat = bid >> 7;
    const int k   = bid & 127;
    const int l   = threadIdx.x;  // 128
    const float* W; int rows;
    if      (mat == 0) { W = Wum; rows = 769; }
    else if (mat == 1) { W = Wvm; rows = 769; }
    else if (mat == 2) { W = Wup; rows = 128; }
    else               { W = Wvp; rows = 128; }
    float acc = 0.f;
    for (int i = 0; i < rows; i++) acc += W[i*128 + k] * W[i*128 + l];
    g_G[mat*16384 + k*128 + l] = acc;
}

// ---------------- E1: per-node MLP chain -> n -------------------------
__global__ void node_kernel(const float* __restrict__ x_tag,
                            const float* __restrict__ Wup,
                            const float* __restrict__ W_hyb, const float* __restrict__ b_hyb,
                            const float* __restrict__ W_act, const float* __restrict__ b_act,
                            const float* __restrict__ W_inact, const float* __restrict__ b_inact)
{
    const int n = blockIdx.x, tid = threadIdx.x;  // 256
    __shared__ float p[128], up[128], vm_s[128], hh[256];
    const float act = x_tag[n*3+2];
    if (tid < 128) {
        p[tid]    = leaky(g_h2last[n*128 + tid]);
        vm_s[tid] = (act == 1.f) ? g_vm[128 + tid] : g_vm[tid];
    }
    __syncthreads();
    if (tid < 128) {
        float a = 0.f;
        for (int k = 0; k < 128; k++) a += p[k]*Wup[k*128 + tid];
        up[tid] = leaky(a);
    }
    __syncthreads();
    {
        float a = b_hyb[tid];
        for (int k = 0; k < 128; k++) {
            float u_ = up[k], v_ = vm_s[k];
            a += u_*W_hyb[k*256 + tid] + (u_ + v_)*W_hyb[(128+k)*256 + tid] + v_*W_hyb[(256+k)*256 + tid];
        }
        hh[tid] = leaky(a);
    }
    __syncthreads();
    {
        float na = b_act[tid], ni = b_inact[tid];
        for (int k = 0; k < 256; k++) {
            float h_ = hh[k];
            na += h_*W_act[k*256 + tid];
            ni += h_*W_inact[k*256 + tid];
        }
        na += x_tag[n*3+0]*W_act[256*256 + tid] + x_tag[n*3+1]*W_act[257*256 + tid];
        g_n[n*256 + tid] = leaky(na*(1.f - act) + ni*act);
    }
}

// ---------------- E2: per-node pair projections -----------------------
__global__ void proj_kernel(const float* __restrict__ Wphin,
                            const float* __restrict__ Won,
                            const float* __restrict__ Weo)
{
    const int n = blockIdx.x, tid = threadIdx.x;  // 256
    __shared__ float nn_s[256];
    nn_s[tid] = g_n[n*256 + tid];
    __syncthreads();
    if (tid < 192) {
        float pb = 0.f, pa = 0.f;
        for (int k = 0; k < 256; k++) {
            float v = nn_s[k];
            pb += v*Wphin[k*192 + tid];
            pa += v*Wphin[(256+k)*192 + tid];
        }
        g_Pb[n*192 + tid] = pb;
        g_Pa[n*192 + tid] = pa;
    }
    float qb = 0.f, qa = 0.f, rb = 0.f, ra = 0.f;
    for (int k = 0; k < 256; k++) {
        float v = nn_s[k];
        qb += v*Won[k*256 + tid];
        qa += v*Won[(256+k)*256 + tid];
        rb += v*Weo[(256+k)*256 + tid];
        ra += v*Weo[(512+k)*256 + tid];
    }
    g_Qb[n*256 + tid] = qb;
    g_Qa[n*256 + tid] = qa;
    g_Rb[n*256 + tid] = rb;
    g_Ra[n*256 + tid] = ra;
}

// ---------------- E3: phi column + masked softmaxes -> alpha ----------
__device__ __forceinline__ float blockmax128(float v, float* red){
    int tid = threadIdx.x; red[tid] = v; __syncthreads();
    #pragma unroll
    for (int s = 64; s > 0; s >>= 1) { if (tid < s) red[tid] = fmaxf(red[tid], red[tid+s]); __syncthreads(); }
    float r = red[0]; __syncthreads(); return r;
}
__device__ __forceinline__ float blocksum128(float v, float* red){
    int tid = threadIdx.x; red[tid] = v; __syncthreads();
    #pragma unroll
    for (int s = 64; s > 0; s >>= 1) { if (tid < s) red[tid] += red[tid+s]; __syncthreads(); }
    float r = red[0]; __syncthreads(); return r;
}

__global__ void phi_alpha_kernel(const float* __restrict__ x_tag,
                                 const float* __restrict__ aphi)
{
    const int b = blockIdx.x;
    const int tid = threadIdx.x;  // 128
    __shared__ float pb_s[192], ap_s[192], red[128];
    for (int i = tid; i < 192; i += 128) { pb_s[i] = g_Pb[b*192 + i]; ap_s[i] = aphi[i]; }
    __syncthreads();

    float ph = 0.f, v1 = 0.f;
    if (tid < NNODE) {
        const float* pa = g_Pa + tid*192;
        #pragma unroll 8
        for (int d = 0; d < 192; d++) ph += leaky(pb_s[d] + pa[d]) * ap_s[d];
        v1 = (x_tag[tid*3+2] == 0.f) ? 1.f : 0.f;
    }

    const float NEG = -1000000000.f;
    float m1 = (tid < NNODE) ? (v1 > 0.f ? ph : NEG) : -INFINITY;
    float m0 = (tid < NNODE) ? (v1 > 0.f ? NEG : ph) : -INFINITY;
    float ma = (tid < NNODE) ? ph : -INFINITY;

    float mx = blockmax128(m1, red);
    float e  = (tid < NNODE) ? __expf(m1 - mx) : 0.f;
    float s  = blocksum128(e, red);
    float sm1 = e / s;

    mx = blockmax128(m0, red);
    e  = (tid < NNODE) ? __expf(m0 - mx) : 0.f;
    s  = blocksum128(e, red);
    float sm0 = e / s;

    mx = blockmax128(ma, red);
    e  = (tid < NNODE) ? __expf(ma - mx) : 0.f;
    s  = blocksum128(e, red);
    float sma = e / s;

    if (tid < NNODE) {
        float a = (g_flag[0] > 0.f) ? (v1 > 0.f ? sm1 : sm0) : sma;
        g_alpha[tid*NNODE + b] = a;
    }
}

// ---------------- E4: hyper messages + y_hat --------------------------
__global__ void hyper_kernel(const float* __restrict__ x_tag,
                             const float* __restrict__ Weo,
                             const float* __restrict__ Wi,
                             const float* __restrict__ bi,
                             float* __restrict__ out, int osz)
{
    const int n = blockIdx.x, tid = threadIdx.x;  // 256
    __shared__ float qa[256], ra[256], nn_s[256], u[256], al[NNODE], red[256];
    qa[tid]   = g_Qa[n*256 + tid];
    ra[tid]   = g_Ra[n*256 + tid];
    nn_s[tid] = g_n[n*256 + tid];
    if (tid < NNODE) al[tid] = g_alpha[n*NNODE + tid];
    __syncthreads();

    float uacc = 0.f, racc = 0.f, alsum = 0.f;
    const float qad = qa[tid];
    for (int j = 0; j < NNODE; j++) {
        float a_ = al[j];
        uacc  += a_ * leaky(g_Qb[j*256 + tid] + qad);
        racc  += a_ * g_Rb[j*256 + tid];
        alsum += a_;
    }
    u[tid] = uacc;
    __syncthreads();

    float T = racc + alsum*ra[tid];
    for (int k = 0; k < 256; k++) T += u[k]*Weo[k*256 + tid];

    const float act = x_tag[n*3+2];
    float hm0 = leaky(act*T);
    float hm1 = leaky((1.f - act)*T);

    const float* Win = Wi + (size_t)n*768*2;
    float p0 = nn_s[tid]*Win[tid*2+0] + hm0*Win[(256+tid)*2+0] + hm1*Win[(512+tid)*2+0];
    float p1 = nn_s[tid]*Win[tid*2+1] + hm0*Win[(256+tid)*2+1] + hm1*Win[(512+tid)*2+1];

    red[tid] = p0; __syncthreads();
    #pragma unroll
    for (int s = 128; s > 0; s >>= 1) { if (tid < s) red[tid] += red[tid+s]; __syncthreads(); }
    float y0 = red[0] + bi[n*2+0]; __syncthreads();

    red[tid] = p1; __syncthreads();
    #pragma unroll
    for (int s = 128; s > 0; s >>= 1) { if (tid < s) red[tid] += red[tid+s]; __syncthreads(); }
    float y1 = red[0] + bi[n*2+1];

    if (tid == 0) {
        float mx = fmaxf(y0, y1);
        float e0 = __expf(y0 - mx), e1 = __expf(y1 - mx);
        int o;
        o = n*2+0; if (o < osz) out[o] = e0/(e0+e1);
        o = n*2+1; if (o < osz) out[o] = e1/(e0+e1);
    }
}

// ---------------- E5: l_ort + l_pol -----------------------------------
__global__ void finals_kernel(const float* __restrict__ x_tag,
                              float* __restrict__ out, int osz)
{
    const int tid = threadIdx.x;  // 256
    __shared__ float red[256], w[NNODE];

    float s1 = 0.f, s2 = 0.f;
    for (int i = tid; i < 16384; i += 256) {
        s1 += g_G[i]          * g_G[16384 + i];
        s2 += g_G[32768 + i]  * g_G[49152 + i];
    }
    red[tid] = s1; __syncthreads();
    #pragma unroll
    for (int s = 128; s > 0; s >>= 1) { if (tid < s) red[tid] += red[tid+s]; __syncthreads(); }
    float S1 = red[0]; __syncthreads();
    red[tid] = s2; __syncthreads();
    #pragma unroll
    for (int s = 128; s > 0; s >>= 1) { if (tid < s) red[tid] += red[tid+s]; __syncthreads(); }
    float S2 = red[0]; __syncthreads();
    if (tid == 0 && 472 < osz) out[472] = sqrtf(S1) + sqrtf(S2);

    if (tid < NNODE) {
        float nr = 0.f;
        const float* np = g_n + tid*256;
        for (int d = 0; d < 256; d++) nr += np[d]*np[d];
        nr = fmaxf(sqrtf(nr), 1e-8f);
        float diff = x_tag[tid*3+1] - x_tag[tid*3+0];
        float sg = (diff > 0.f ? 1.f : (diff < 0.f ? -1.f : 0.f));
        sg *= (x_tag[tid*3+2] == 0.f) ? 1.f : 0.f;
        w[tid] = sg / nr;
    }
    __syncthreads();
    float v = 0.f;
    for (int i = 0; i < NNODE; i++) v += w[i]*g_n[i*256 + tid];
    red[tid] = v*v; __syncthreads();
    #pragma unroll
    for (int s = 128; s > 0; s >>= 1) { if (tid < s) red[tid] += red[tid+s]; __syncthreads(); }
    if (tid == 0 && 473 < osz) out[473] = red[0];
}

// ---------------- launch ----------------------------------------------
extern "C" void kernel_launch(void* const* d_in, const int* in_sizes, int n_in,
                              void* d_out, int out_size)
{
    const float* x       = (const float*)d_in[0];
    const float* x_tag   = (const float*)d_in[1];
    const float* W_ih0   = (const float*)d_in[2];
    const float* W_hh0   = (const float*)d_in[3];
    const float* b_ih0   = (const float*)d_in[4];
    const float* b_hh0   = (const float*)d_in[5];
    const float* W_ih1   = (const float*)d_in[6];
    const float* W_hh1   = (const float*)d_in[7];
    const float* b_ih1   = (const float*)d_in[8];
    const float* b_hh1   = (const float*)d_in[9];
    const float* pm      = (const float*)d_in[10];
    const float* Wum     = (const float*)d_in[11];
    const float* Wvm     = (const float*)d_in[12];
    const float* Wup     = (const float*)d_in[13];
    const float* Wvp     = (const float*)d_in[14];
    const float* W_hyb   = (const float*)d_in[15];
    const float* b_hyb   = (const float*)d_in[16];
    const float* W_act   = (const float*)d_in[17];
    const float* b_act   = (const float*)d_in[18];
    const float* W_inact = (const float*)d_in[19];
    const float* b_inact = (const float*)d_in[20];
    const float* Wphin   = (const float*)d_in[21];
    const float* aphi    = (const float*)d_in[22];
    const float* Won     = (const float*)d_in[23];
    const float* Weo     = (const float*)d_in[24];
    const float* Wi      = (const float*)d_in[25];
    const float* bi      = (const float*)d_in[26];
    float* out = (float*)d_out;

    float *xpre = nullptr, *h1 = nullptr, *h2last = nullptr;
    u16 *xh = nullptr, *xl = nullptr;
    cudaGetSymbolAddress((void**)&xpre,   g_xpre);
    cudaGetSymbolAddress((void**)&h1,     g_h1);
    cudaGetSymbolAddress((void**)&h2last, g_h2last);
    cudaGetSymbolAddress((void**)&xh,     g_xh);
    cudaGetSymbolAddress((void**)&xl,     g_xl);

    cudaFuncSetAttribute(gemm_mma, cudaFuncAttributeMaxDynamicSharedMemorySize, MA_SMEM);
    cudaFuncSetAttribute(lstm_rec<1>, cudaFuncAttributeMaxDynamicSharedMemorySize, LSTM_SMEM);
    cudaFuncSetAttribute(lstm_rec<0>, cudaFuncAttributeMaxDynamicSharedMemorySize, LSTM_SMEM);

    // layer 0
    convW<<<1, 512>>>(W_ih0, b_ih0, b_hh0);
    convX<<<2048, 256>>>(x);
    gemm_mma<<<M_ROWS/128, 256, MA_SMEM>>>(xh, xl, xpre);
    lstm_rec<1><<<NNODE, 512, LSTM_SMEM>>>(xpre, W_hh0, h1);
    // layer 1
    convW<<<1, 512>>>(W_ih1, b_ih1, b_hh1);
    convX<<<2048, 256>>>(h1);
    gemm_mma<<<M_ROWS/128, 256, MA_SMEM>>>(xh, xl, xpre);
    lstm_rec<0><<<NNODE, 512, LSTM_SMEM>>>(xpre, W_hh1, h2last);

    // epilogue
    prep_kernel<<<1, 128>>>(x_tag, pm, Wvm, out, out_size);
    gram_kernel<<<512, 128>>>(Wum, Wvm, Wup, Wvp);
    node_kernel<<<NNODE, 256>>>(x_tag, Wup, W_hyb, b_hyb, W_act, b_act, W_inact, b_inact);
    proj_kernel<<<NNODE, 256>>>(Wphin, Won, Weo);
    phi_alpha_kernel<<<NNODE, 128>>>(x_tag, aphi);
    hyper_kernel<<<NNODE, 256>>>(x_tag, Weo, Wi, bi, out, out_size);
    finals_kernel<<<1, 256>>>(x_tag, out, out_size);
}

// round 15
// speedup vs baseline: 1.5322x; 1.0058x over previous
#include <cuda_runtime.h>
#include <math.h>

#define NNODE 118
#define TT 2048
#define M_ROWS (NNODE*TT)

typedef unsigned long long ull;
typedef unsigned short u16;
union F2U { ull u; float2 f; };

__device__ __forceinline__ ull pk2(float x, float y){ ull r; asm("mov.b64 %0, {%1,%2};" : "=l"(r) : "f"(x), "f"(y)); return r; }
__device__ __forceinline__ void fma2(ull& d, ull a, ull b){ asm("fma.rn.f32x2 %0, %1, %2, %0;" : "+l"(d) : "l"(a), "l"(b)); }
__device__ __forceinline__ ull add2(ull a, ull b){ ull r; asm("add.rn.f32x2 %0, %1, %2;" : "=l"(r) : "l"(a), "l"(b)); return r; }
__device__ __forceinline__ float tanh_ap(float x){ float r; asm("tanh.approx.f32 %0, %1;" : "=f"(r) : "f"(x)); return r; }

__device__ __forceinline__ unsigned bf1(float f){
    unsigned b = __float_as_uint(f);
    return (b + 0x7FFFu + ((b >> 16) & 1u)) >> 16;   // RNE
}
__device__ __forceinline__ float bf2f(unsigned h){ return __uint_as_float(h << 16); }

__device__ __forceinline__ ull shfl_xor64(ull v, int m){
    unsigned lo = (unsigned)v, hi = (unsigned)(v >> 32);
    lo = __shfl_xor_sync(0xFFFFFFFFu, lo, m);
    hi = __shfl_xor_sync(0xFFFFFFFFu, hi, m);
    return ((ull)hi << 32) | lo;
}

// column permutation: semantic gate-major n (= g*128+c)  <->  stored col' = 4c+g
__device__ __forceinline__ int invperm(int cp){ return (cp & 3)*128 + (cp >> 2); }

__device__ __forceinline__ unsigned sm2u(const void* p){
    unsigned r; asm("{ .reg .u64 t; cvta.to.shared.u64 t, %1; cvt.u32.u64 %0, t; }" : "=r"(r) : "l"(p)); return r;
}

// ---------------- scratch (device globals; no allocation allowed) ----------
__device__ __align__(256) float g_xpre[(size_t)M_ROWS*512];
__device__ __align__(256) float g_h1[(size_t)M_ROWS*128];
__device__ __align__(256) u16   g_wh[512*128];
__device__ __align__(256) u16   g_wl[512*128];
__device__ __align__(256) float g_bias[512];
__device__ __align__(256) float g_h2last[NNODE*128];
__device__ __align__(256) float g_vm[2*128];
__device__ __align__(256) float g_flag[1];
__device__ __align__(256) float g_n[NNODE*256];
__device__ __align__(256) float g_Pa[NNODE*192];
__device__ __align__(256) float g_Pb[NNODE*192];
__device__ __align__(256) float g_Qa[NNODE*256];
__device__ __align__(256) float g_Qb[NNODE*256];
__device__ __align__(256) float g_Ra[NNODE*256];
__device__ __align__(256) float g_Rb[NNODE*256];
__device__ __align__(256) float g_alpha[NNODE*NNODE];
__device__ __align__(256) float g_G[4*128*128];

__device__ __forceinline__ float leaky(float z){ return z >= 0.f ? z : 0.01f*z; }

// ---------------- convW: W -> bf16 hi/lo (permuted rows) + bias ------------
__global__ void convW(const float* __restrict__ W,
                      const float* __restrict__ b1,
                      const float* __restrict__ b2)
{
    const int r = threadIdx.x;            // stored row 0..511
    const int srow = invperm(r);
    g_bias[r] = b1[srow] + b2[srow];
    const float* wp = W + srow*128;
    for (int k = 0; k < 128; k++) {
        float w = wp[k];
        unsigned hb = bf1(w);
        float lo = w - bf2f(hb);
        g_wh[r*128 + k] = (u16)hb;
        g_wl[r*128 + k] = (u16)bf1(lo);
    }
}

// ---------------- mma.sync GEMM: C(M,512) = A @ W^T (bf16, 3-pass) ---------
// A read as FP32 and split to bf16 hi/lo during the smem tile store (convX
// fused away). Per CTA: M-tile 128 resident, loop 4 N-tiles of W (hi/lo).
// 8 warps as 4x2; warp tile 32x64; mma.m16n8k16.row.col.f32.bf16.
// smem rows padded to 136 halfs (272 B) -> conflict-free ldmatrix.
#define MA_AH 0
#define MA_AL 34816
#define MA_WH 69632
#define MA_WL 104448
#define MA_BIAS 139264
#define MA_SMEM 139776

__device__ __forceinline__ void ldsm4(unsigned r[4], unsigned addr){
    asm volatile("ldmatrix.sync.aligned.m8n8.x4.shared.b16 {%0,%1,%2,%3}, [%4];"
        : "=r"(r[0]), "=r"(r[1]), "=r"(r[2]), "=r"(r[3]) : "r"(addr));
}
__device__ __forceinline__ void mma16816(float d[4], const unsigned a[4], unsigned b0, unsigned b1){
    asm volatile("mma.sync.aligned.m16n8k16.row.col.f32.bf16.bf16.f32 "
        "{%0,%1,%2,%3}, {%4,%5,%6,%7}, {%8,%9}, {%0,%1,%2,%3};"
        : "+f"(d[0]), "+f"(d[1]), "+f"(d[2]), "+f"(d[3])
        : "r"(a[0]), "r"(a[1]), "r"(a[2]), "r"(a[3]), "r"(b0), "r"(b1));
}
__device__ __forceinline__ unsigned bfpair(float e, float o){ return bf1(e) | (bf1(o) << 16); }

__global__ void __launch_bounds__(256) gemm_mma(const float* __restrict__ A,
                                                float* __restrict__ C)
{
    extern __shared__ char sm[];
    const unsigned smb = sm2u(sm);
    float* bias_s = (float*)(sm + MA_BIAS);
    const int tid = threadIdx.x;
    const int lane = tid & 31;
    const int w = tid >> 5;
    const int wr = w & 3;          // warp row (32 m-rows)
    const int wc = w >> 2;         // warp col (64 n-cols)
    const int mbase = blockIdx.x * 128;

    // load A tile as fp32, split to bf16 hi/lo into smem
    #pragma unroll
    for (int i = 0; i < 16; i++) {
        int idx = tid + i*256;          // 0..4095
        int row = idx >> 5;             // 0..127
        int c4  = idx & 31;             // float4 index 0..31
        float4 v = ((const float4*)(A + (size_t)(mbase + row)*128))[c4];
        unsigned hx = bf1(v.x), hy = bf1(v.y), hz = bf1(v.z), hw_ = bf1(v.w);
        ull hi = ((ull)(hx | (hy << 16))) | ((ull)(hz | (hw_ << 16)) << 32);
        ull lo = ((ull)(bf1(v.x - bf2f(hx)) | (bf1(v.y - bf2f(hy)) << 16)))
               | ((ull)(bf1(v.z - bf2f(hz)) | (bf1(v.w - bf2f(hw_)) << 16)) << 32);
        *(ull*)(sm + MA_AH + row*272 + c4*8) = hi;
        *(ull*)(sm + MA_AL + row*272 + c4*8) = lo;
    }
    __syncthreads();

    // per-lane ldmatrix base offsets
    const unsigned baseA = (unsigned)((wr*32 + ((lane>>3)&1)*8 + (lane&7))*272 + (lane>>4)*16);
    const unsigned baseB = (unsigned)((wc*64 + (lane>>4)*8 + (lane&7))*272 + ((lane>>3)&1)*16);

    for (int nt = 0; nt < 4; nt++) {
        // load W tiles (hi/lo) for n-rows [128nt, 128nt+128)
        #pragma unroll
        for (int i = 0; i < 8; i++) {
            int idx = tid + i*256;
            int row = idx >> 4;
            int c16 = idx & 15;
            size_t src = ((size_t)(nt*128 + row))*16 + c16;
            *(uint4*)(sm + MA_WH + row*272 + c16*16) = ((const uint4*)g_wh)[src];
            *(uint4*)(sm + MA_WL + row*272 + c16*16) = ((const uint4*)g_wl)[src];
        }
        if (tid < 128) bias_s[tid] = g_bias[nt*128 + tid];
        __syncthreads();

        float acc[2][8][4];
        #pragma unroll
        for (int mi = 0; mi < 2; mi++)
            #pragma unroll
            for (int j = 0; j < 8; j++)
                #pragma unroll
                for (int e = 0; e < 4; e++) acc[mi][j][e] = 0.f;

        #pragma unroll
        for (int pass = 0; pass < 3; pass++) {
            const unsigned Ab = smb + ((pass == 2) ? MA_AL : MA_AH) + baseA;
            const unsigned Bb = smb + ((pass == 1) ? MA_WL : MA_WH) + baseB;
            #pragma unroll
            for (int ks = 0; ks < 8; ks++) {
                unsigned af[2][4], bf[4][4];
                ldsm4(af[0], Ab + ks*32);
                ldsm4(af[1], Ab + 4352 + ks*32);
                #pragma unroll
                for (int j = 0; j < 4; j++) ldsm4(bf[j], Bb + j*4352 + ks*32);
                #pragma unroll
                for (int mi = 0; mi < 2; mi++) {
                    #pragma unroll
                    for (int j = 0; j < 4; j++) {
                        mma16816(acc[mi][2*j],   af[mi], bf[j][0], bf[j][1]);
                        mma16816(acc[mi][2*j+1], af[mi], bf[j][2], bf[j][3]);
                    }
                }
            }
        }

        // store with bias
        const int r0 = mbase + wr*32 + (lane >> 2);
        #pragma unroll
        for (int mi = 0; mi < 2; mi++) {
            #pragma unroll
            for (int j = 0; j < 8; j++) {
                int cl = wc*64 + j*8 + (lane & 3)*2;
                float b0 = bias_s[cl], b1 = bias_s[cl+1];
                float* p0 = C + (size_t)(r0 + mi*16)*512 + nt*128 + cl;
                float2 v0 = { acc[mi][j][0] + b0, acc[mi][j][1] + b1 };
                float2 v1 = { acc[mi][j][2] + b0, acc[mi][j][3] + b1 };
                *(float2*)p0 = v0;
                *(float2*)(p0 + 8*512) = v1;
            }
        }
        __syncthreads();
    }
}

// ---------------- LSTM recurrence (unchanged from R12) ---------------------
#define LSTM_SMEM (8*512*16 + 2*128*4 + 64)

template<int WRITE_ALL>
__global__ void __launch_bounds__(512, 1) lstm_rec(const float* __restrict__ xpre,
                                                   const float* __restrict__ Whh,
                                                   float* __restrict__ hout)
{
    extern __shared__ char smraw[];
    ulonglong2* ws3 = (ulonglong2*)smraw;              // [8][512] gate-3 f32 pairs
    float* hs0 = (float*)(smraw + 8*512*16);           // h double buffer
    float* hs1 = hs0 + 128;

    const int j = threadIdx.x;
    const int n = blockIdx.x;
    const int l = j & 31;
    const int w = j >> 5;
    const int q = l & 3;
    const int cell = w*8 + (l >> 2);

    ull wr[48];
    #pragma unroll
    for (int g = 0; g < 3; g++) {
        const float* wp = Whh + (g*128 + cell)*128 + 32*q;
        #pragma unroll
        for (int i = 0; i < 8; i++) {
            float4 v = *(const float4*)(wp + 4*i);
            wr[g*16 + 2*i]     = pk2(v.x, v.y);
            wr[g*16 + 2*i + 1] = pk2(v.z, v.w);
        }
    }
    {
        const float* wp = Whh + (3*128 + cell)*128 + 32*q;
        #pragma unroll
        for (int d = 0; d < 8; d++) {
            ulonglong2 pr;
            pr.x = pk2(wp[4*d+0], wp[4*d+1]);
            pr.y = pk2(wp[4*d+2], wp[4*d+3]);
            ws3[d*512 + j] = pr;
        }
    }

    if (j < 128) { hs0[j] = 0.f; hs1[j] = 0.f; }
    float c = 0.f;
    __syncthreads();

    const float* xp = xpre + (size_t)n*TT*512 + j;
    float xnext = xp[0];
    float* hw = hout + (WRITE_ALL ? ((size_t)n*TT*128 + cell) : ((size_t)n*128 + cell));

    const int wblk = cell >> 5;
    const int wslot = wblk*32 + (((cell & 31) + 8*wblk) & 31);

    int p = 0;
    for (int t = 0; t < TT; t++) {
        F2U A0, A1, A2, A3;
        A0.u = 0ull; A1.u = 0ull; A2.u = 0ull; A3.u = 0ull;
        float xcur = xnext;
        if (t + 1 < TT) xnext = xp[(size_t)(t+1)*512];

        const float* hb = (p ? hs1 : hs0) + q*32;
        #pragma unroll
        for (int s = 0; s < 4; s++) {
            {
                ulonglong2 w3 = ws3[(2*s)*512 + j];
                int off = (8*s + 8*q) & 31;
                ulonglong2 hv = *(const ulonglong2*)(hb + off);
                fma2(A0.u, wr[4*s],      hv.x); fma2(A0.u, wr[4*s+1],      hv.y);
                fma2(A1.u, wr[16+4*s],   hv.x); fma2(A1.u, wr[16+4*s+1],   hv.y);
                fma2(A2.u, wr[32+4*s],   hv.x); fma2(A2.u, wr[32+4*s+1],   hv.y);
                fma2(A3.u, w3.x,         hv.x); fma2(A3.u, w3.y,           hv.y);
            }
            {
                ulonglong2 w3 = ws3[(2*s+1)*512 + j];
                int off = (8*s + 4 + 8*q) & 31;
                ulonglong2 hv = *(const ulonglong2*)(hb + off);
                fma2(A0.u, wr[4*s+2],    hv.x); fma2(A0.u, wr[4*s+3],      hv.y);
                fma2(A1.u, wr[16+4*s+2], hv.x); fma2(A1.u, wr[16+4*s+3],   hv.y);
                fma2(A2.u, wr[32+4*s+2], hv.x); fma2(A2.u, wr[32+4*s+3],   hv.y);
                fma2(A3.u, w3.x,         hv.x); fma2(A3.u, w3.y,           hv.y);
            }
        }

        float p0 = A0.f.x + A0.f.y;
        float p1 = A1.f.x + A1.f.y;
        float p2 = A2.f.x + A2.f.y;
        float p3 = A3.f.x + A3.f.y;

        ull lo = pk2(p0, p1), hi = pk2(p2, p3);
        ull send = (l & 2) ? lo : hi;
        ull recv = shfl_xor64(send, 2);
        ull keep = (l & 2) ? hi : lo;
        F2U s2; s2.u = add2(keep, recv);
        float mine  = (l & 1) ? s2.f.y : s2.f.x;
        float sendf = (l & 1) ? s2.f.x : s2.f.y;
        float other = __shfl_xor_sync(0xFFFFFFFFu, sendf, 1);
        float acc = mine + other + xcur;

        const bool isg = (q == 2);
        float u  = isg ? acc : 0.5f*acc;
        float th = tanh_ap(u);
        float a  = isg ? th : fmaf(0.5f, th, 0.5f);

        const int base = l & ~3;
        float iv = __shfl_sync(0xFFFFFFFFu, a, base);
        float fv = __shfl_sync(0xFFFFFFFFu, a, base + 1);
        float gv = __shfl_sync(0xFFFFFFFFu, a, base + 2);
        float ov = __shfl_sync(0xFFFFFFFFu, a, base + 3);
        c = fv*c + iv*gv;
        float hv = ov * tanh_ap(c);
        p ^= 1;
        if (q == 0) {
            (p ? hs1 : hs0)[wslot] = hv;
            if (WRITE_ALL)      hw[(size_t)t*128] = hv;
            else if (t == TT-1) hw[0] = hv;
        }
        __syncthreads();
    }
}

// ---------------- E0: pseudo-message projections + direct outputs ----------
__global__ void prep_kernel(const float* __restrict__ x_tag,
                            const float* __restrict__ pm,
                            const float* __restrict__ Wvm,
                            float* __restrict__ out, int osz)
{
    const int tid = threadIdx.x;  // 128
    __shared__ float pms[768];
    for (int i = tid; i < 768; i += 128) pms[i] = pm[i];
    __syncthreads();

    float base = 0.f;
    for (int k = 0; k < 768; k++) base += pms[k]*Wvm[k*128 + tid];
    g_vm[tid]       = leaky(base);
    g_vm[128 + tid] = leaky(base + Wvm[768*128 + tid]);

    if (tid < NNODE) {
        int o;
        o = 236 + tid*2 + 0; if (o < osz) out[o] = x_tag[tid*3+0];
        o = 236 + tid*2 + 1; if (o < osz) out[o] = x_tag[tid*3+1];
        float a = x_tag[tid*3+2];
        o = 474 + tid; if (o < osz) out[o] = (a == 0.f) ? 1.f : 0.f;
        o = 592 + tid; if (o < osz) out[o] = (a == 1.f) ? 1.f : 0.f;
    }
    if (tid == 0) {
        int cnt = 0;
        for (int i = 0; i < NNODE; i++) if (x_tag[i*3+2] == 0.f) cnt++;
        g_flag[0] = (cnt > 0) ? 1.f : 0.f;
    }
}

// ---------------- Gram matrices for l_ort -----------------------------
__global__ void gram_kernel(const float* __restrict__ Wum, const float* __restrict__ Wvm,
                            const float* __restrict__ Wup, const float* __restrict__ Wvp)
{
    const int bid = blockIdx.x;
    const int mat = bid >> 7;
    const int k   = bid & 127;
    const int l   = threadIdx.x;  // 128
    const float* W; int rows;
    if      (mat == 0) { W = Wum; rows = 769; }
    else if (mat == 1) { W = Wvm; rows = 769; }
    else if (mat == 2) { W = Wup; rows = 128; }
    else               { W = Wvp; rows = 128; }
    float acc = 0.f;
    for (int i = 0; i < rows; i++) acc += W[i*128 + k] * W[i*128 + l];
    g_G[mat*16384 + k*128 + l] = acc;
}

// ---------------- E1: per-node MLP chain -> n -------------------------
__global__ void node_kernel(const float* __restrict__ x_tag,
                            const float* __restrict__ Wup,
                            const float* __restrict__ W_hyb, const float* __restrict__ b_hyb,
                            const float* __restrict__ W_act, const float* __restrict__ b_act,
                            const float* __restrict__ W_inact, const float* __restrict__ b_inact)
{
    const int n = blockIdx.x, tid = threadIdx.x;  // 256
    __shared__ float p[128], up[128], vm_s[128], hh[256];
    const float act = x_tag[n*3+2];
    if (tid < 128) {
        p[tid]    = leaky(g_h2last[n*128 + tid]);
        vm_s[tid] = (act == 1.f) ? g_vm[128 + tid] : g_vm[tid];
    }
    __syncthreads();
    if (tid < 128) {
        float a = 0.f;
        for (int k = 0; k < 128; k++) a += p[k]*Wup[k*128 + tid];
        up[tid] = leaky(a);
    }
    __syncthreads();
    {
        float a = b_hyb[tid];
        for (int k = 0; k < 128; k++) {
            float u_ = up[k], v_ = vm_s[k];
            a += u_*W_hyb[k*256 + tid] + (u_ + v_)*W_hyb[(128+k)*256 + tid] + v_*W_hyb[(256+k)*256 + tid];
        }
        hh[tid] = leaky(a);
    }
    __syncthreads();
    {
        float na = b_act[tid], ni = b_inact[tid];
        for (int k = 0; k < 256; k++) {
            float h_ = hh[k];
            na += h_*W_act[k*256 + tid];
            ni += h_*W_inact[k*256 + tid];
        }
        na += x_tag[n*3+0]*W_act[256*256 + tid] + x_tag[n*3+1]*W_act[257*256 + tid];
        g_n[n*256 + tid] = leaky(na*(1.f - act) + ni*act);
    }
}

// ---------------- E2: per-node pair projections -----------------------
__global__ void proj_kernel(const float* __restrict__ Wphin,
                            const float* __restrict__ Won,
                            const float* __restrict__ Weo)
{
    const int n = blockIdx.x, tid = threadIdx.x;  // 256
    __shared__ float nn_s[256];
    nn_s[tid] = g_n[n*256 + tid];
    __syncthreads();
    if (tid < 192) {
        float pb = 0.f, pa = 0.f;
        for (int k = 0; k < 256; k++) {
            float v = nn_s[k];
            pb += v*Wphin[k*192 + tid];
            pa += v*Wphin[(256+k)*192 + tid];
        }
        g_Pb[n*192 + tid] = pb;
        g_Pa[n*192 + tid] = pa;
    }
    float qb = 0.f, qa = 0.f, rb = 0.f, ra = 0.f;
    for (int k = 0; k < 256; k++) {
        float v = nn_s[k];
        qb += v*Won[k*256 + tid];
        qa += v*Won[(256+k)*256 + tid];
        rb += v*Weo[(256+k)*256 + tid];
        ra += v*Weo[(512+k)*256 + tid];
    }
    g_Qb[n*256 + tid] = qb;
    g_Qa[n*256 + tid] = qa;
    g_Rb[n*256 + tid] = rb;
    g_Ra[n*256 + tid] = ra;
}

// ---------------- E3: phi column + masked softmaxes -> alpha ----------
__device__ __forceinline__ float blockmax128(float v, float* red){
    int tid = threadIdx.x; red[tid] = v; __syncthreads();
    #pragma unroll
    for (int s = 64; s > 0; s >>= 1) { if (tid < s) red[tid] = fmaxf(red[tid], red[tid+s]); __syncthreads(); }
    float r = red[0]; __syncthreads(); return r;
}
__device__ __forceinline__ float blocksum128(float v, float* red){
    int tid = threadIdx.x; red[tid] = v; __syncthreads();
    #pragma unroll
    for (int s = 64; s > 0; s >>= 1) { if (tid < s) red[tid] += red[tid+s]; __syncthreads(); }
    float r = red[0]; __syncthreads(); return r;
}

__global__ void phi_alpha_kernel(const float* __restrict__ x_tag,
                                 const float* __restrict__ aphi)
{
    const int b = blockIdx.x;
    const int tid = threadIdx.x;  // 128
    __shared__ float pb_s[192], ap_s[192], red[128];
    for (int i = tid; i < 192; i += 128) { pb_s[i] = g_Pb[b*192 + i]; ap_s[i] = aphi[i]; }
    __syncthreads();

    float ph = 0.f, v1 = 0.f;
    if (tid < NNODE) {
        const float* pa = g_Pa + tid*192;
        #pragma unroll 8
        for (int d = 0; d < 192; d++) ph += leaky(pb_s[d] + pa[d]) * ap_s[d];
        v1 = (x_tag[tid*3+2] == 0.f) ? 1.f : 0.f;
    }

    const float NEG = -1000000000.f;
    float m1 = (tid < NNODE) ? (v1 > 0.f ? ph : NEG) : -INFINITY;
    float m0 = (tid < NNODE) ? (v1 > 0.f ? NEG : ph) : -INFINITY;
    float ma = (tid < NNODE) ? ph : -INFINITY;

    float mx = blockmax128(m1, red);
    float e  = (tid < NNODE) ? __expf(m1 - mx) : 0.f;
    float s  = blocksum128(e, red);
    float sm1 = e / s;

    mx = blockmax128(m0, red);
    e  = (tid < NNODE) ? __expf(m0 - mx) : 0.f;
    s  = blocksum128(e, red);
    float sm0 = e / s;

    mx = blockmax128(ma, red);
    e  = (tid < NNODE) ? __expf(ma - mx) : 0.f;
    s  = blocksum128(e, red);
    float sma = e / s;

    if (tid < NNODE) {
        float a = (g_flag[0] > 0.f) ? (v1 > 0.f ? sm1 : sm0) : sma;
        g_alpha[tid*NNODE + b] = a;
    }
}

// ---------------- E4: hyper messages + y_hat --------------------------
__global__ void hyper_kernel(const float* __restrict__ x_tag,
                             const float* __restrict__ Weo,
                             const float* __restrict__ Wi,
                             const float* __restrict__ bi,
                             float* __restrict__ out, int osz)
{
    const int n = blockIdx.x, tid = threadIdx.x;  // 256
    __shared__ float qa[256], ra[256], nn_s[256], u[256], al[NNODE], red[256];
    qa[tid]   = g_Qa[n*256 + tid];
    ra[tid]   = g_Ra[n*256 + tid];
    nn_s[tid] = g_n[n*256 + tid];
    if (tid < NNODE) al[tid] = g_alpha[n*NNODE + tid];
    __syncthreads();

    float uacc = 0.f, racc = 0.f, alsum = 0.f;
    const float qad = qa[tid];
    for (int j = 0; j < NNODE; j++) {
        float a_ = al[j];
        uacc  += a_ * leaky(g_Qb[j*256 + tid] + qad);
        racc  += a_ * g_Rb[j*256 + tid];
        alsum += a_;
    }
    u[tid] = uacc;
    __syncthreads();

    float T = racc + alsum*ra[tid];
    for (int k = 0; k < 256; k++) T += u[k]*Weo[k*256 + tid];

    const float act = x_tag[n*3+2];
    float hm0 = leaky(act*T);
    float hm1 = leaky((1.f - act)*T);

    const float* Win = Wi + (size_t)n*768*2;
    float p0 = nn_s[tid]*Win[tid*2+0] + hm0*Win[(256+tid)*2+0] + hm1*Win[(512+tid)*2+0];
    float p1 = nn_s[tid]*Win[tid*2+1] + hm0*Win[(256+tid)*2+1] + hm1*Win[(512+tid)*2+1];

    red[tid] = p0; __syncthreads();
    #pragma unroll
    for (int s = 128; s > 0; s >>= 1) { if (tid < s) red[tid] += red[tid+s]; __syncthreads(); }
    float y0 = red[0] + bi[n*2+0]; __syncthreads();

    red[tid] = p1; __syncthreads();
    #pragma unroll
    for (int s = 128; s > 0; s >>= 1) { if (tid < s) red[tid] += red[tid+s]; __syncthreads(); }
    float y1 = red[0] + bi[n*2+1];

    if (tid == 0) {
        float mx = fmaxf(y0, y1);
        float e0 = __expf(y0 - mx), e1 = __expf(y1 - mx);
        int o;
        o = n*2+0; if (o < osz) out[o] = e0/(e0+e1);
        o = n*2+1; if (o < osz) out[o] = e1/(e0+e1);
    }
}

// ---------------- E5: l_ort + l_pol -----------------------------------
__global__ void finals_kernel(const float* __restrict__ x_tag,
                              float* __restrict__ out, int osz)
{
    const int tid = threadIdx.x;  // 256
    __shared__ float red[256], w[NNODE];

    float s1 = 0.f, s2 = 0.f;
    for (int i = tid; i < 16384; i += 256) {
        s1 += g_G[i]          * g_G[16384 + i];
        s2 += g_G[32768 + i]  * g_G[49152 + i];
    }
    red[tid] = s1; __syncthreads();
    #pragma unroll
    for (int s = 128; s > 0; s >>= 1) { if (tid < s) red[tid] += red[tid+s]; __syncthreads(); }
    float S1 = red[0]; __syncthreads();
    red[tid] = s2; __syncthreads();
    #pragma unroll
    for (int s = 128; s > 0; s >>= 1) { if (tid < s) red[tid] += red[tid+s]; __syncthreads(); }
    float S2 = red[0]; __syncthreads();
    if (tid == 0 && 472 < osz) out[472] = sqrtf(S1) + sqrtf(S2);

    if (tid < NNODE) {
        float nr = 0.f;
        const float* np = g_n + tid*256;
        for (int d = 0; d < 256; d++) nr += np[d]*np[d];
        nr = fmaxf(sqrtf(nr), 1e-8f);
        float diff = x_tag[tid*3+1] - x_tag[tid*3+0];
        float sg = (diff > 0.f ? 1.f : (diff < 0.f ? -1.f : 0.f));
        sg *= (x_tag[tid*3+2] == 0.f) ? 1.f : 0.f;
        w[tid] = sg / nr;
    }
    __syncthreads();
    float v = 0.f;
    for (int i = 0; i < NNODE; i++) v += w[i]*g_n[i*256 + tid];
    red[tid] = v*v; __syncthreads();
    #pragma unroll
    for (int s = 128; s > 0; s >>= 1) { if (tid < s) red[tid] += red[tid+s]; __syncthreads(); }
    if (tid == 0 && 473 < osz) out[473] = red[0];
}

// ---------------- launch ----------------------------------------------
extern "C" void kernel_launch(void* const* d_in, const int* in_sizes, int n_in,
                              void* d_out, int out_size)
{
    const float* x       = (const float*)d_in[0];
    const float* x_tag   = (const float*)d_in[1];
    const float* W_ih0   = (const float*)d_in[2];
    const float* W_hh0   = (const float*)d_in[3];
    const float* b_ih0   = (const float*)d_in[4];
    const float* b_hh0   = (const float*)d_in[5];
    const float* W_ih1   = (const float*)d_in[6];
    const float* W_hh1   = (const float*)d_in[7];
    const float* b_ih1   = (const float*)d_in[8];
    const float* b_hh1   = (const float*)d_in[9];
    const float* pm      = (const float*)d_in[10];
    const float* Wum     = (const float*)d_in[11];
    const float* Wvm     = (const float*)d_in[12];
    const float* Wup     = (const float*)d_in[13];
    const float* Wvp     = (const float*)d_in[14];
    const float* W_hyb   = (const float*)d_in[15];
    const float* b_hyb   = (const float*)d_in[16];
    const float* W_act   = (const float*)d_in[17];
    const float* b_act   = (const float*)d_in[18];
    const float* W_inact = (const float*)d_in[19];
    const float* b_inact = (const float*)d_in[20];
    const float* Wphin   = (const float*)d_in[21];
    const float* aphi    = (const float*)d_in[22];
    const float* Won     = (const float*)d_in[23];
    const float* Weo     = (const float*)d_in[24];
    const float* Wi      = (const float*)d_in[25];
    const float* bi      = (const float*)d_in[26];
    float* out = (float*)d_out;

    float *xpre = nullptr, *h1 = nullptr, *h2last = nullptr;
    cudaGetSymbolAddress((void**)&xpre,   g_xpre);
    cudaGetSymbolAddress((void**)&h1,     g_h1);
    cudaGetSymbolAddress((void**)&h2last, g_h2last);

    cudaFuncSetAttribute(gemm_mma, cudaFuncAttributeMaxDynamicSharedMemorySize, MA_SMEM);
    cudaFuncSetAttribute(lstm_rec<1>, cudaFuncAttributeMaxDynamicSharedMemorySize, LSTM_SMEM);
    cudaFuncSetAttribute(lstm_rec<0>, cudaFuncAttributeMaxDynamicSharedMemorySize, LSTM_SMEM);

    // layer 0
    convW<<<1, 512>>>(W_ih0, b_ih0, b_hh0);
    gemm_mma<<<M_ROWS/128, 256, MA_SMEM>>>(x, xpre);
    lstm_rec<1><<<NNODE, 512, LSTM_SMEM>>>(xpre, W_hh0, h1);
    // layer 1
    convW<<<1, 512>>>(W_ih1, b_ih1, b_hh1);
    gemm_mma<<<M_ROWS/128, 256, MA_SMEM>>>(h1, xpre);
    lstm_rec<0><<<NNODE, 512, LSTM_SMEM>>>(xpre, W_hh1, h2last);

    // epilogue
    prep_kernel<<<1, 128>>>(x_tag, pm, Wvm, out, out_size);
    gram_kernel<<<512, 128>>>(Wum, Wvm, Wup, Wvp);
    node_kernel<<<NNODE, 256>>>(x_tag, Wup, W_hyb, b_hyb, W_act, b_act, W_inact, b_inact);
    proj_kernel<<<NNODE, 256>>>(Wphin, Won, Weo);
    phi_alpha_kernel<<<NNODE, 128>>>(x_tag, aphi);
    hyper_kernel<<<NNODE, 256>>>(x_tag, Weo, Wi, bi, out, out_size);
    finals_kernel<<<1, 256>>>(x_tag, out, out_size);
}

// round 16
// speedup vs baseline: 1.5654x; 1.0216x over previous
#include <cuda_runtime.h>
#include <math.h>

#define NNODE 118
#define TT 2048
#define M_ROWS (NNODE*TT)

typedef unsigned long long ull;
typedef unsigned short u16;
union F2U { ull u; float2 f; };

__device__ __forceinline__ ull pk2(float x, float y){ ull r; asm("mov.b64 %0, {%1,%2};" : "=l"(r) : "f"(x), "f"(y)); return r; }
__device__ __forceinline__ void fma2(ull& d, ull a, ull b){ asm("fma.rn.f32x2 %0, %1, %2, %0;" : "+l"(d) : "l"(a), "l"(b)); }
__device__ __forceinline__ ull add2(ull a, ull b){ ull r; asm("add.rn.f32x2 %0, %1, %2;" : "=l"(r) : "l"(a), "l"(b)); return r; }
__device__ __forceinline__ float tanh_ap(float x){ float r; asm("tanh.approx.f32 %0, %1;" : "=f"(r) : "f"(x)); return r; }

__device__ __forceinline__ unsigned bf1(float f){
    unsigned b = __float_as_uint(f);
    return (b + 0x7FFFu + ((b >> 16) & 1u)) >> 16;   // RNE
}
__device__ __forceinline__ float bf2f(unsigned h){ return __uint_as_float(h << 16); }

__device__ __forceinline__ ull shfl_xor64(ull v, int m){
    unsigned lo = (unsigned)v, hi = (unsigned)(v >> 32);
    lo = __shfl_xor_sync(0xFFFFFFFFu, lo, m);
    hi = __shfl_xor_sync(0xFFFFFFFFu, hi, m);
    return ((ull)hi << 32) | lo;
}

// column permutation: semantic gate-major n (= g*128+c)  <->  stored col' = 4c+g
__device__ __forceinline__ int invperm(int cp){ return (cp & 3)*128 + (cp >> 2); }

__device__ __forceinline__ unsigned sm2u(const void* p){
    unsigned r; asm("{ .reg .u64 t; cvta.to.shared.u64 t, %1; cvt.u32.u64 %0, t; }" : "=r"(r) : "l"(p)); return r;
}

// ---------------- scratch (device globals; no allocation allowed) ----------
__device__ __align__(256) float g_xpre[(size_t)M_ROWS*512];
__device__ __align__(256) float g_h1[(size_t)M_ROWS*128];
__device__ __align__(256) u16   g_wh[512*128];
__device__ __align__(256) u16   g_wl[512*128];
__device__ __align__(256) float g_bias[512];
__device__ __align__(256) float g_h2last[NNODE*128];
__device__ __align__(256) float g_vm[2*128];
__device__ __align__(256) float g_flag[1];
__device__ __align__(256) float g_n[NNODE*256];
__device__ __align__(256) float g_Pa[NNODE*192];
__device__ __align__(256) float g_Pb[NNODE*192];
__device__ __align__(256) float g_Qa[NNODE*256];
__device__ __align__(256) float g_Qb[NNODE*256];
__device__ __align__(256) float g_Ra[NNODE*256];
__device__ __align__(256) float g_Rb[NNODE*256];
__device__ __align__(256) float g_alpha[NNODE*NNODE];
__device__ __align__(256) float g_G[4*128*128];

__device__ __forceinline__ float leaky(float z){ return z >= 0.f ? z : 0.01f*z; }

// ---------------- convW: W -> bf16 hi/lo (permuted rows) + bias ------------
// 512 blocks x 128 threads: one element per thread (was 1 block, 58 us).
__global__ void convW(const float* __restrict__ W,
                      const float* __restrict__ b1,
                      const float* __restrict__ b2)
{
    const int r = blockIdx.x;             // stored row 0..511
    const int k = threadIdx.x;            // 0..127
    const int srow = invperm(r);
    if (k == 0) g_bias[r] = b1[srow] + b2[srow];
    float w = W[srow*128 + k];
    unsigned hb = bf1(w);
    g_wh[r*128 + k] = (u16)hb;
    g_wl[r*128 + k] = (u16)bf1(w - bf2f(hb));
}

// ---------------- mma.sync GEMM: C(M,512) = A @ W^T (bf16, 3-pass) ---------
// A read as FP32 and split to bf16 hi/lo during the smem tile store.
// Per CTA: M-tile 128 resident, loop 4 N-tiles of W (hi/lo).
// 8 warps as 4x2; warp tile 32x64; mma.m16n8k16.row.col.f32.bf16.
// smem rows padded to 136 halfs (272 B) -> conflict-free ldmatrix.
#define MA_AH 0
#define MA_AL 34816
#define MA_WH 69632
#define MA_WL 104448
#define MA_BIAS 139264
#define MA_SMEM 139776

__device__ __forceinline__ void ldsm4(unsigned r[4], unsigned addr){
    asm volatile("ldmatrix.sync.aligned.m8n8.x4.shared.b16 {%0,%1,%2,%3}, [%4];"
        : "=r"(r[0]), "=r"(r[1]), "=r"(r[2]), "=r"(r[3]) : "r"(addr));
}
__device__ __forceinline__ void mma16816(float d[4], const unsigned a[4], unsigned b0, unsigned b1){
    asm volatile("mma.sync.aligned.m16n8k16.row.col.f32.bf16.bf16.f32 "
        "{%0,%1,%2,%3}, {%4,%5,%6,%7}, {%8,%9}, {%0,%1,%2,%3};"
        : "+f"(d[0]), "+f"(d[1]), "+f"(d[2]), "+f"(d[3])
        : "r"(a[0]), "r"(a[1]), "r"(a[2]), "r"(a[3]), "r"(b0), "r"(b1));
}

__global__ void __launch_bounds__(256) gemm_mma(const float* __restrict__ A,
                                                float* __restrict__ C)
{
    extern __shared__ char sm[];
    const unsigned smb = sm2u(sm);
    float* bias_s = (float*)(sm + MA_BIAS);
    const int tid = threadIdx.x;
    const int lane = tid & 31;
    const int w = tid >> 5;
    const int wr = w & 3;          // warp row (32 m-rows)
    const int wc = w >> 2;         // warp col (64 n-cols)
    const int mbase = blockIdx.x * 128;

    // load A tile as fp32, split to bf16 hi/lo into smem
    #pragma unroll
    for (int i = 0; i < 16; i++) {
        int idx = tid + i*256;          // 0..4095
        int row = idx >> 5;             // 0..127
        int c4  = idx & 31;             // float4 index 0..31
        float4 v = ((const float4*)(A + (size_t)(mbase + row)*128))[c4];
        unsigned hx = bf1(v.x), hy = bf1(v.y), hz = bf1(v.z), hw_ = bf1(v.w);
        ull hi = ((ull)(hx | (hy << 16))) | ((ull)(hz | (hw_ << 16)) << 32);
        ull lo = ((ull)(bf1(v.x - bf2f(hx)) | (bf1(v.y - bf2f(hy)) << 16)))
               | ((ull)(bf1(v.z - bf2f(hz)) | (bf1(v.w - bf2f(hw_)) << 16)) << 32);
        *(ull*)(sm + MA_AH + row*272 + c4*8) = hi;
        *(ull*)(sm + MA_AL + row*272 + c4*8) = lo;
    }
    __syncthreads();

    // per-lane ldmatrix base offsets
    const unsigned baseA = (unsigned)((wr*32 + ((lane>>3)&1)*8 + (lane&7))*272 + (lane>>4)*16);
    const unsigned baseB = (unsigned)((wc*64 + (lane>>4)*8 + (lane&7))*272 + ((lane>>3)&1)*16);

    for (int nt = 0; nt < 4; nt++) {
        // load W tiles (hi/lo) for n-rows [128nt, 128nt+128)
        #pragma unroll
        for (int i = 0; i < 8; i++) {
            int idx = tid + i*256;
            int row = idx >> 4;
            int c16 = idx & 15;
            size_t src = ((size_t)(nt*128 + row))*16 + c16;
            *(uint4*)(sm + MA_WH + row*272 + c16*16) = ((const uint4*)g_wh)[src];
            *(uint4*)(sm + MA_WL + row*272 + c16*16) = ((const uint4*)g_wl)[src];
        }
        if (tid < 128) bias_s[tid] = g_bias[nt*128 + tid];
        __syncthreads();

        float acc[2][8][4];
        #pragma unroll
        for (int mi = 0; mi < 2; mi++)
            #pragma unroll
            for (int j = 0; j < 8; j++)
                #pragma unroll
                for (int e = 0; e < 4; e++) acc[mi][j][e] = 0.f;

        #pragma unroll
        for (int pass = 0; pass < 3; pass++) {
            const unsigned Ab = smb + ((pass == 2) ? MA_AL : MA_AH) + baseA;
            const unsigned Bb = smb + ((pass == 1) ? MA_WL : MA_WH) + baseB;
            #pragma unroll
            for (int ks = 0; ks < 8; ks++) {
                unsigned af[2][4], bf[4][4];
                ldsm4(af[0], Ab + ks*32);
                ldsm4(af[1], Ab + 4352 + ks*32);
                #pragma unroll
                for (int j = 0; j < 4; j++) ldsm4(bf[j], Bb + j*4352 + ks*32);
                #pragma unroll
                for (int mi = 0; mi < 2; mi++) {
                    #pragma unroll
                    for (int j = 0; j < 4; j++) {
                        mma16816(acc[mi][2*j],   af[mi], bf[j][0], bf[j][1]);
                        mma16816(acc[mi][2*j+1], af[mi], bf[j][2], bf[j][3]);
                    }
                }
            }
        }

        // store with bias
        const int r0 = mbase + wr*32 + (lane >> 2);
        #pragma unroll
        for (int mi = 0; mi < 2; mi++) {
            #pragma unroll
            for (int j = 0; j < 8; j++) {
                int cl = wc*64 + j*8 + (lane & 3)*2;
                float b0 = bias_s[cl], b1 = bias_s[cl+1];
                float* p0 = C + (size_t)(r0 + mi*16)*512 + nt*128 + cl;
                float2 v0 = { acc[mi][j][0] + b0, acc[mi][j][1] + b1 };
                float2 v1 = { acc[mi][j][2] + b0, acc[mi][j][3] + b1 };
                *(float2*)p0 = v0;
                *(float2*)(p0 + 8*512) = v1;
            }
        }
        __syncthreads();
    }
}

// ---------------- LSTM recurrence (unchanged from R12) ---------------------
#define LSTM_SMEM (8*512*16 + 2*128*4 + 64)

template<int WRITE_ALL>
__global__ void __launch_bounds__(512, 1) lstm_rec(const float* __restrict__ xpre,
                                                   const float* __restrict__ Whh,
                                                   float* __restrict__ hout)
{
    extern __shared__ char smraw[];
    ulonglong2* ws3 = (ulonglong2*)smraw;              // [8][512] gate-3 f32 pairs
    float* hs0 = (float*)(smraw + 8*512*16);           // h double buffer
    float* hs1 = hs0 + 128;

    const int j = threadIdx.x;
    const int n = blockIdx.x;
    const int l = j & 31;
    const int w = j >> 5;
    const int q = l & 3;
    const int cell = w*8 + (l >> 2);

    ull wr[48];
    #pragma unroll
    for (int g = 0; g < 3; g++) {
        const float* wp = Whh + (g*128 + cell)*128 + 32*q;
        #pragma unroll
        for (int i = 0; i < 8; i++) {
            float4 v = *(const float4*)(wp + 4*i);
            wr[g*16 + 2*i]     = pk2(v.x, v.y);
            wr[g*16 + 2*i + 1] = pk2(v.z, v.w);
        }
    }
    {
        const float* wp = Whh + (3*128 + cell)*128 + 32*q;
        #pragma unroll
        for (int d = 0; d < 8; d++) {
            ulonglong2 pr;
            pr.x = pk2(wp[4*d+0], wp[4*d+1]);
            pr.y = pk2(wp[4*d+2], wp[4*d+3]);
            ws3[d*512 + j] = pr;
        }
    }

    if (j < 128) { hs0[j] = 0.f; hs1[j] = 0.f; }
    float c = 0.f;
    __syncthreads();

    const float* xp = xpre + (size_t)n*TT*512 + j;
    float xnext = xp[0];
    float* hw = hout + (WRITE_ALL ? ((size_t)n*TT*128 + cell) : ((size_t)n*128 + cell));

    const int wblk = cell >> 5;
    const int wslot = wblk*32 + (((cell & 31) + 8*wblk) & 31);

    int p = 0;
    for (int t = 0; t < TT; t++) {
        F2U A0, A1, A2, A3;
        A0.u = 0ull; A1.u = 0ull; A2.u = 0ull; A3.u = 0ull;
        float xcur = xnext;
        if (t + 1 < TT) xnext = xp[(size_t)(t+1)*512];

        const float* hb = (p ? hs1 : hs0) + q*32;
        #pragma unroll
        for (int s = 0; s < 4; s++) {
            {
                ulonglong2 w3 = ws3[(2*s)*512 + j];
                int off = (8*s + 8*q) & 31;
                ulonglong2 hv = *(const ulonglong2*)(hb + off);
                fma2(A0.u, wr[4*s],      hv.x); fma2(A0.u, wr[4*s+1],      hv.y);
                fma2(A1.u, wr[16+4*s],   hv.x); fma2(A1.u, wr[16+4*s+1],   hv.y);
                fma2(A2.u, wr[32+4*s],   hv.x); fma2(A2.u, wr[32+4*s+1],   hv.y);
                fma2(A3.u, w3.x,         hv.x); fma2(A3.u, w3.y,           hv.y);
            }
            {
                ulonglong2 w3 = ws3[(2*s+1)*512 + j];
                int off = (8*s + 4 + 8*q) & 31;
                ulonglong2 hv = *(const ulonglong2*)(hb + off);
                fma2(A0.u, wr[4*s+2],    hv.x); fma2(A0.u, wr[4*s+3],      hv.y);
                fma2(A1.u, wr[16+4*s+2], hv.x); fma2(A1.u, wr[16+4*s+3],   hv.y);
                fma2(A2.u, wr[32+4*s+2], hv.x); fma2(A2.u, wr[32+4*s+3],   hv.y);
                fma2(A3.u, w3.x,         hv.x); fma2(A3.u, w3.y,           hv.y);
            }
        }

        float p0 = A0.f.x + A0.f.y;
        float p1 = A1.f.x + A1.f.y;
        float p2 = A2.f.x + A2.f.y;
        float p3 = A3.f.x + A3.f.y;

        ull lo = pk2(p0, p1), hi = pk2(p2, p3);
        ull send = (l & 2) ? lo : hi;
        ull recv = shfl_xor64(send, 2);
        ull keep = (l & 2) ? hi : lo;
        F2U s2; s2.u = add2(keep, recv);
        float mine  = (l & 1) ? s2.f.y : s2.f.x;
        float sendf = (l & 1) ? s2.f.x : s2.f.y;
        float other = __shfl_xor_sync(0xFFFFFFFFu, sendf, 1);
        float acc = mine + other + xcur;

        const bool isg = (q == 2);
        float u  = isg ? acc : 0.5f*acc;
        float th = tanh_ap(u);
        float a  = isg ? th : fmaf(0.5f, th, 0.5f);

        const int base = l & ~3;
        float iv = __shfl_sync(0xFFFFFFFFu, a, base);
        float fv = __shfl_sync(0xFFFFFFFFu, a, base + 1);
        float gv = __shfl_sync(0xFFFFFFFFu, a, base + 2);
        float ov = __shfl_sync(0xFFFFFFFFu, a, base + 3);
        c = fv*c + iv*gv;
        float hv = ov * tanh_ap(c);
        p ^= 1;
        if (q == 0) {
            (p ? hs1 : hs0)[wslot] = hv;
            if (WRITE_ALL)      hw[(size_t)t*128] = hv;
            else if (t == TT-1) hw[0] = hv;
        }
        __syncthreads();
    }
}

// ---------------- E0: pseudo-message projections + direct outputs ----------
__global__ void prep_kernel(const float* __restrict__ x_tag,
                            const float* __restrict__ pm,
                            const float* __restrict__ Wvm,
                            float* __restrict__ out, int osz)
{
    const int tid = threadIdx.x;  // 128
    __shared__ float pms[768];
    for (int i = tid; i < 768; i += 128) pms[i] = pm[i];
    __syncthreads();

    float base = 0.f;
    for (int k = 0; k < 768; k++) base += pms[k]*Wvm[k*128 + tid];
    g_vm[tid]       = leaky(base);
    g_vm[128 + tid] = leaky(base + Wvm[768*128 + tid]);

    if (tid < NNODE) {
        int o;
        o = 236 + tid*2 + 0; if (o < osz) out[o] = x_tag[tid*3+0];
        o = 236 + tid*2 + 1; if (o < osz) out[o] = x_tag[tid*3+1];
        float a = x_tag[tid*3+2];
        o = 474 + tid; if (o < osz) out[o] = (a == 0.f) ? 1.f : 0.f;
        o = 592 + tid; if (o < osz) out[o] = (a == 1.f) ? 1.f : 0.f;
    }
    if (tid == 0) {
        int cnt = 0;
        for (int i = 0; i < NNODE; i++) if (x_tag[i*3+2] == 0.f) cnt++;
        g_flag[0] = (cnt > 0) ? 1.f : 0.f;
    }
}

// ---------------- Gram matrices for l_ort -----------------------------
__global__ void gram_kernel(const float* __restrict__ Wum, const float* __restrict__ Wvm,
                            const float* __restrict__ Wup, const float* __restrict__ Wvp)
{
    const int bid = blockIdx.x;
    const int mat = bid >> 7;
    const int k   = bid & 127;
    const int l   = threadIdx.x;  // 128
    const float* W; int rows;
    if      (mat == 0) { W = Wum; rows = 769; }
    else if (mat == 1) { W = Wvm; rows = 769; }
    else if (mat == 2) { W = Wup; rows = 128; }
    else               { W = Wvp; rows = 128; }
    float acc = 0.f;
    for (int i = 0; i < rows; i++) acc += W[i*128 + k] * W[i*128 + l];
    g_G[mat*16384 + k*128 + l] = acc;
}

// ---------------- E1: per-node MLP chain -> n -------------------------
__global__ void node_kernel(const float* __restrict__ x_tag,
                            const float* __restrict__ Wup,
                            const float* __restrict__ W_hyb, const float* __restrict__ b_hyb,
                            const float* __restrict__ W_act, const float* __restrict__ b_act,
                            const float* __restrict__ W_inact, const float* __restrict__ b_inact)
{
    const int n = blockIdx.x, tid = threadIdx.x;  // 256
    __shared__ float p[128], up[128], vm_s[128], hh[256];
    const float act = x_tag[n*3+2];
    if (tid < 128) {
        p[tid]    = leaky(g_h2last[n*128 + tid]);
        vm_s[tid] = (act == 1.f) ? g_vm[128 + tid] : g_vm[tid];
    }
    __syncthreads();
    if (tid < 128) {
        float a = 0.f;
        for (int k = 0; k < 128; k++) a += p[k]*Wup[k*128 + tid];
        up[tid] = leaky(a);
    }
    __syncthreads();
    {
        float a = b_hyb[tid];
        for (int k = 0; k < 128; k++) {
            float u_ = up[k], v_ = vm_s[k];
            a += u_*W_hyb[k*256 + tid] + (u_ + v_)*W_hyb[(128+k)*256 + tid] + v_*W_hyb[(256+k)*256 + tid];
        }
        hh[tid] = leaky(a);
    }
    __syncthreads();
    {
        float na = b_act[tid], ni = b_inact[tid];
        for (int k = 0; k < 256; k++) {
            float h_ = hh[k];
            na += h_*W_act[k*256 + tid];
            ni += h_*W_inact[k*256 + tid];
        }
        na += x_tag[n*3+0]*W_act[256*256 + tid] + x_tag[n*3+1]*W_act[257*256 + tid];
        g_n[n*256 + tid] = leaky(na*(1.f - act) + ni*act);
    }
}

// ---------------- E2: per-node pair projections -----------------------
__global__ void proj_kernel(const float* __restrict__ Wphin,
                            const float* __restrict__ Won,
                            const float* __restrict__ Weo)
{
    const int n = blockIdx.x, tid = threadIdx.x;  // 256
    __shared__ float nn_s[256];
    nn_s[tid] = g_n[n*256 + tid];
    __syncthreads();
    if (tid < 192) {
        float pb = 0.f, pa = 0.f;
        for (int k = 0; k < 256; k++) {
            float v = nn_s[k];
            pb += v*Wphin[k*192 + tid];
            pa += v*Wphin[(256+k)*192 + tid];
        }
        g_Pb[n*192 + tid] = pb;
        g_Pa[n*192 + tid] = pa;
    }
    float qb = 0.f, qa = 0.f, rb = 0.f, ra = 0.f;
    for (int k = 0; k < 256; k++) {
        float v = nn_s[k];
        qb += v*Won[k*256 + tid];
        qa += v*Won[(256+k)*256 + tid];
        rb += v*Weo[(256+k)*256 + tid];
        ra += v*Weo[(512+k)*256 + tid];
    }
    g_Qb[n*256 + tid] = qb;
    g_Qa[n*256 + tid] = qa;
    g_Rb[n*256 + tid] = rb;
    g_Ra[n*256 + tid] = ra;
}

// ---------------- E3: phi column + masked softmaxes -> alpha ----------
__device__ __forceinline__ float blockmax128(float v, float* red){
    int tid = threadIdx.x; red[tid] = v; __syncthreads();
    #pragma unroll
    for (int s = 64; s > 0; s >>= 1) { if (tid < s) red[tid] = fmaxf(red[tid], red[tid+s]); __syncthreads(); }
    float r = red[0]; __syncthreads(); return r;
}
__device__ __forceinline__ float blocksum128(float v, float* red){
    int tid = threadIdx.x; red[tid] = v; __syncthreads();
    #pragma unroll
    for (int s = 64; s > 0; s >>= 1) { if (tid < s) red[tid] += red[tid+s]; __syncthreads(); }
    float r = red[0]; __syncthreads(); return r;
}

__global__ void phi_alpha_kernel(const float* __restrict__ x_tag,
                                 const float* __restrict__ aphi)
{
    const int b = blockIdx.x;
    const int tid = threadIdx.x;  // 128
    __shared__ float pb_s[192], ap_s[192], red[128];
    for (int i = tid; i < 192; i += 128) { pb_s[i] = g_Pb[b*192 + i]; ap_s[i] = aphi[i]; }
    __syncthreads();

    float ph = 0.f, v1 = 0.f;
    if (tid < NNODE) {
        const float* pa = g_Pa + tid*192;
        #pragma unroll 8
        for (int d = 0; d < 192; d++) ph += leaky(pb_s[d] + pa[d]) * ap_s[d];
        v1 = (x_tag[tid*3+2] == 0.f) ? 1.f : 0.f;
    }

    const float NEG = -1000000000.f;
    float m1 = (tid < NNODE) ? (v1 > 0.f ? ph : NEG) : -INFINITY;
    float m0 = (tid < NNODE) ? (v1 > 0.f ? NEG : ph) : -INFINITY;
    float ma = (tid < NNODE) ? ph : -INFINITY;

    float mx = blockmax128(m1, red);
    float e  = (tid < NNODE) ? __expf(m1 - mx) : 0.f;
    float s  = blocksum128(e, red);
    float sm1 = e / s;

    mx = blockmax128(m0, red);
    e  = (tid < NNODE) ? __expf(m0 - mx) : 0.f;
    s  = blocksum128(e, red);
    float sm0 = e / s;

    mx = blockmax128(ma, red);
    e  = (tid < NNODE) ? __expf(ma - mx) : 0.f;
    s  = blocksum128(e, red);
    float sma = e / s;

    if (tid < NNODE) {
        float a = (g_flag[0] > 0.f) ? (v1 > 0.f ? sm1 : sm0) : sma;
        g_alpha[tid*NNODE + b] = a;
    }
}

// ---------------- E4: hyper messages + y_hat --------------------------
__global__ void hyper_kernel(const float* __restrict__ x_tag,
                             const float* __restrict__ Weo,
                             const float* __restrict__ Wi,
                             const float* __restrict__ bi,
                             float* __restrict__ out, int osz)
{
    const int n = blockIdx.x, tid = threadIdx.x;  // 256
    __shared__ float qa[256], ra[256], nn_s[256], u[256], al[NNODE], red[256];
    qa[tid]   = g_Qa[n*256 + tid];
    ra[tid]   = g_Ra[n*256 + tid];
    nn_s[tid] = g_n[n*256 + tid];
    if (tid < NNODE) al[tid] = g_alpha[n*NNODE + tid];
    __syncthreads();

    float uacc = 0.f, racc = 0.f, alsum = 0.f;
    const float qad = qa[tid];
    for (int j = 0; j < NNODE; j++) {
        float a_ = al[j];
        uacc  += a_ * leaky(g_Qb[j*256 + tid] + qad);
        racc  += a_ * g_Rb[j*256 + tid];
        alsum += a_;
    }
    u[tid] = uacc;
    __syncthreads();

    float T = racc + alsum*ra[tid];
    for (int k = 0; k < 256; k++) T += u[k]*Weo[k*256 + tid];

    const float act = x_tag[n*3+2];
    float hm0 = leaky(act*T);
    float hm1 = leaky((1.f - act)*T);

    const float* Win = Wi + (size_t)n*768*2;
    float p0 = nn_s[tid]*Win[tid*2+0] + hm0*Win[(256+tid)*2+0] + hm1*Win[(512+tid)*2+0];
    float p1 = nn_s[tid]*Win[tid*2+1] + hm0*Win[(256+tid)*2+1] + hm1*Win[(512+tid)*2+1];

    red[tid] = p0; __syncthreads();
    #pragma unroll
    for (int s = 128; s > 0; s >>= 1) { if (tid < s) red[tid] += red[tid+s]; __syncthreads(); }
    float y0 = red[0] + bi[n*2+0]; __syncthreads();

    red[tid] = p1; __syncthreads();
    #pragma unroll
    for (int s = 128; s > 0; s >>= 1) { if (tid < s) red[tid] += red[tid+s]; __syncthreads(); }
    float y1 = red[0] + bi[n*2+1];

    if (tid == 0) {
        float mx = fmaxf(y0, y1);
        float e0 = __expf(y0 - mx), e1 = __expf(y1 - mx);
        int o;
        o = n*2+0; if (o < osz) out[o] = e0/(e0+e1);
        o = n*2+1; if (o < osz) out[o] = e1/(e0+e1);
    }
}

// ---------------- E5: l_ort + l_pol -----------------------------------
__global__ void finals_kernel(const float* __restrict__ x_tag,
                              float* __restrict__ out, int osz)
{
    const int tid = threadIdx.x;  // 256
    __shared__ float red[256], w[NNODE];

    float s1 = 0.f, s2 = 0.f;
    for (int i = tid; i < 16384; i += 256) {
        s1 += g_G[i]          * g_G[16384 + i];
        s2 += g_G[32768 + i]  * g_G[49152 + i];
    }
    red[tid] = s1; __syncthreads();
    #pragma unroll
    for (int s = 128; s > 0; s >>= 1) { if (tid < s) red[tid] += red[tid+s]; __syncthreads(); }
    float S1 = red[0]; __syncthreads();
    red[tid] = s2; __syncthreads();
    #pragma unroll
    for (int s = 128; s > 0; s >>= 1) { if (tid < s) red[tid] += red[tid+s]; __syncthreads(); }
    float S2 = red[0]; __syncthreads();
    if (tid == 0 && 472 < osz) out[472] = sqrtf(S1) + sqrtf(S2);

    if (tid < NNODE) {
        float nr = 0.f;
        const float* np = g_n + tid*256;
        for (int d = 0; d < 256; d++) nr += np[d]*np[d];
        nr = fmaxf(sqrtf(nr), 1e-8f);
        float diff = x_tag[tid*3+1] - x_tag[tid*3+0];
        float sg = (diff > 0.f ? 1.f : (diff < 0.f ? -1.f : 0.f));
        sg *= (x_tag[tid*3+2] == 0.f) ? 1.f : 0.f;
        w[tid] = sg / nr;
    }
    __syncthreads();
    float v = 0.f;
    for (int i = 0; i < NNODE; i++) v += w[i]*g_n[i*256 + tid];
    red[tid] = v*v; __syncthreads();
    #pragma unroll
    for (int s = 128; s > 0; s >>= 1) { if (tid < s) red[tid] += red[tid+s]; __syncthreads(); }
    if (tid == 0 && 473 < osz) out[473] = red[0];
}

// ---------------- launch ----------------------------------------------
extern "C" void kernel_launch(void* const* d_in, const int* in_sizes, int n_in,
                              void* d_out, int out_size)
{
    const float* x       = (const float*)d_in[0];
    const float* x_tag   = (const float*)d_in[1];
    const float* W_ih0   = (const float*)d_in[2];
    const float* W_hh0   = (const float*)d_in[3];
    const float* b_ih0   = (const float*)d_in[4];
    const float* b_hh0   = (const float*)d_in[5];
    const float* W_ih1   = (const float*)d_in[6];
    const float* W_hh1   = (const float*)d_in[7];
    const float* b_ih1   = (const float*)d_in[8];
    const float* b_hh1   = (const float*)d_in[9];
    const float* pm      = (const float*)d_in[10];
    const float* Wum     = (const float*)d_in[11];
    const float* Wvm     = (const float*)d_in[12];
    const float* Wup     = (const float*)d_in[13];
    const float* Wvp     = (const float*)d_in[14];
    const float* W_hyb   = (const float*)d_in[15];
    const float* b_hyb   = (const float*)d_in[16];
    const float* W_act   = (const float*)d_in[17];
    const float* b_act   = (const float*)d_in[18];
    const float* W_inact = (const float*)d_in[19];
    const float* b_inact = (const float*)d_in[20];
    const float* Wphin   = (const float*)d_in[21];
    const float* aphi    = (const float*)d_in[22];
    const float* Won     = (const float*)d_in[23];
    const float* Weo     = (const float*)d_in[24];
    const float* Wi      = (const float*)d_in[25];
    const float* bi      = (const float*)d_in[26];
    float* out = (float*)d_out;

    float *xpre = nullptr, *h1 = nullptr, *h2last = nullptr;
    cudaGetSymbolAddress((void**)&xpre,   g_xpre);
    cudaGetSymbolAddress((void**)&h1,     g_h1);
    cudaGetSymbolAddress((void**)&h2last, g_h2last);

    cudaFuncSetAttribute(gemm_mma, cudaFuncAttributeMaxDynamicSharedMemorySize, MA_SMEM);
    cudaFuncSetAttribute(lstm_rec<1>, cudaFuncAttributeMaxDynamicSharedMemorySize, LSTM_SMEM);
    cudaFuncSetAttribute(lstm_rec<0>, cudaFuncAttributeMaxDynamicSharedMemorySize, LSTM_SMEM);

    // layer 0
    convW<<<512, 128>>>(W_ih0, b_ih0, b_hh0);
    gemm_mma<<<M_ROWS/128, 256, MA_SMEM>>>(x, xpre);
    lstm_rec<1><<<NNODE, 512, LSTM_SMEM>>>(xpre, W_hh0, h1);
    // layer 1
    convW<<<512, 128>>>(W_ih1, b_ih1, b_hh1);
    gemm_mma<<<M_ROWS/128, 256, MA_SMEM>>>(h1, xpre);
    lstm_rec<0><<<NNODE, 512, LSTM_SMEM>>>(xpre, W_hh1, h2last);

    // epilogue
    prep_kernel<<<1, 128>>>(x_tag, pm, Wvm, out, out_size);
    gram_kernel<<<512, 128>>>(Wum, Wvm, Wup, Wvp);
    node_kernel<<<NNODE, 256>>>(x_tag, Wup, W_hyb, b_hyb, W_act, b_act, W_inact, b_inact);
    proj_kernel<<<NNODE, 256>>>(Wphin, Won, Weo);
    phi_alpha_kernel<<<NNODE, 128>>>(x_tag, aphi);
    hyper_kernel<<<NNODE, 256>>>(x_tag, Weo, Wi, bi, out, out_size);
    finals_kernel<<<1, 256>>>(x_tag, out, out_size);
}

// round 17
// speedup vs baseline: 1.7180x; 1.0975x over previous
#include <cuda_runtime.h>
#include <math.h>

#define NNODE 118
#define TT 2048
#define M_ROWS (NNODE*TT)

typedef unsigned long long ull;
typedef unsigned short u16;
union F2U { ull u; float2 f; };

__device__ __forceinline__ ull pk2(float x, float y){ ull r; asm("mov.b64 %0, {%1,%2};" : "=l"(r) : "f"(x), "f"(y)); return r; }
__device__ __forceinline__ void fma2(ull& d, ull a, ull b){ asm("fma.rn.f32x2 %0, %1, %2, %0;" : "+l"(d) : "l"(a), "l"(b)); }
__device__ __forceinline__ ull add2(ull a, ull b){ ull r; asm("add.rn.f32x2 %0, %1, %2;" : "=l"(r) : "l"(a), "l"(b)); return r; }
__device__ __forceinline__ float tanh_ap(float x){ float r; asm("tanh.approx.f32 %0, %1;" : "=f"(r) : "f"(x)); return r; }

__device__ __forceinline__ unsigned bf1(float f){
    unsigned b = __float_as_uint(f);
    return (b + 0x7FFFu + ((b >> 16) & 1u)) >> 16;   // RNE
}

__device__ __forceinline__ ull shfl_xor64(ull v, int m){
    unsigned lo = (unsigned)v, hi = (unsigned)(v >> 32);
    lo = __shfl_xor_sync(0xFFFFFFFFu, lo, m);
    hi = __shfl_xor_sync(0xFFFFFFFFu, hi, m);
    return ((ull)hi << 32) | lo;
}

// column permutation: semantic gate-major n (= g*128+c)  <->  stored col' = 4c+g
__device__ __forceinline__ int invperm(int cp){ return (cp & 3)*128 + (cp >> 2); }

__device__ __forceinline__ unsigned sm2u(const void* p){
    unsigned r; asm("{ .reg .u64 t; cvta.to.shared.u64 t, %1; cvt.u32.u64 %0, t; }" : "=r"(r) : "l"(p)); return r;
}

// ---------------- scratch (device globals; no allocation allowed) ----------
__device__ __align__(256) float g_xpre[(size_t)M_ROWS*512];
__device__ __align__(256) float g_h1[(size_t)M_ROWS*128];
__device__ __align__(256) u16   g_wh[512*128];
__device__ __align__(256) float g_bias[512];
__device__ __align__(256) float g_h2last[NNODE*128];
__device__ __align__(256) float g_vm[2*128];
__device__ __align__(256) float g_flag[1];
__device__ __align__(256) float g_n[NNODE*256];
__device__ __align__(256) float g_Pa[NNODE*192];
__device__ __align__(256) float g_Pb[NNODE*192];
__device__ __align__(256) float g_Qa[NNODE*256];
__device__ __align__(256) float g_Qb[NNODE*256];
__device__ __align__(256) float g_Ra[NNODE*256];
__device__ __align__(256) float g_Rb[NNODE*256];
__device__ __align__(256) float g_alpha[NNODE*NNODE];
__device__ __align__(256) float g_G[4*128*128];

__device__ __forceinline__ float leaky(float z){ return z >= 0.f ? z : 0.01f*z; }

// ---------------- convW: W -> bf16 (permuted rows) + bias ------------------
__global__ void convW(const float* __restrict__ W,
                      const float* __restrict__ b1,
                      const float* __restrict__ b2)
{
    const int r = blockIdx.x;             // stored row 0..511
    const int k = threadIdx.x;            // 0..127
    const int srow = invperm(r);
    if (k == 0) g_bias[r] = b1[srow] + b2[srow];
    g_wh[r*128 + k] = (u16)bf1(W[srow*128 + k]);
}

// ---------------- mma.sync GEMM: C(M,512) = A @ W^T (bf16, 1-pass) ---------
// A read as FP32, rounded to bf16 in the smem tile store. Per CTA: M-tile 128
// resident, loop 4 N-tiles of W. 8 warps as 4x2; warp tile 32x64;
// mma.m16n8k16.row.col.f32.bf16. Rows padded to 272 B -> conflict-free.
#define MA_AH 0
#define MA_WH 34816
#define MA_BIAS 69632
#define MA_SMEM 70144

__device__ __forceinline__ void ldsm4(unsigned r[4], unsigned addr){
    asm volatile("ldmatrix.sync.aligned.m8n8.x4.shared.b16 {%0,%1,%2,%3}, [%4];"
        : "=r"(r[0]), "=r"(r[1]), "=r"(r[2]), "=r"(r[3]) : "r"(addr));
}
__device__ __forceinline__ void mma16816(float d[4], const unsigned a[4], unsigned b0, unsigned b1){
    asm volatile("mma.sync.aligned.m16n8k16.row.col.f32.bf16.bf16.f32 "
        "{%0,%1,%2,%3}, {%4,%5,%6,%7}, {%8,%9}, {%0,%1,%2,%3};"
        : "+f"(d[0]), "+f"(d[1]), "+f"(d[2]), "+f"(d[3])
        : "r"(a[0]), "r"(a[1]), "r"(a[2]), "r"(a[3]), "r"(b0), "r"(b1));
}

__global__ void __launch_bounds__(256) gemm_mma(const float* __restrict__ A,
                                                float* __restrict__ C)
{
    extern __shared__ char sm[];
    const unsigned smb = sm2u(sm);
    float* bias_s = (float*)(sm + MA_BIAS);
    const int tid = threadIdx.x;
    const int lane = tid & 31;
    const int w = tid >> 5;
    const int wr = w & 3;          // warp row (32 m-rows)
    const int wc = w >> 2;         // warp col (64 n-cols)
    const int mbase = blockIdx.x * 128;

    // load A tile as fp32, round to bf16 into smem
    #pragma unroll
    for (int i = 0; i < 16; i++) {
        int idx = tid + i*256;          // 0..4095
        int row = idx >> 5;             // 0..127
        int c4  = idx & 31;             // float4 index 0..31
        float4 v = ((const float4*)(A + (size_t)(mbase + row)*128))[c4];
        ull hi = ((ull)(bf1(v.x) | (bf1(v.y) << 16)))
               | ((ull)(bf1(v.z) | (bf1(v.w) << 16)) << 32);
        *(ull*)(sm + MA_AH + row*272 + c4*8) = hi;
    }
    __syncthreads();

    // per-lane ldmatrix base offsets
    const unsigned baseA = (unsigned)((wr*32 + ((lane>>3)&1)*8 + (lane&7))*272 + (lane>>4)*16);
    const unsigned baseB = (unsigned)((wc*64 + (lane>>4)*8 + (lane&7))*272 + ((lane>>3)&1)*16);

    for (int nt = 0; nt < 4; nt++) {
        // load W tile for n-rows [128nt, 128nt+128)
        #pragma unroll
        for (int i = 0; i < 8; i++) {
            int idx = tid + i*256;
            int row = idx >> 4;
            int c16 = idx & 15;
            size_t src = ((size_t)(nt*128 + row))*16 + c16;
            *(uint4*)(sm + MA_WH + row*272 + c16*16) = ((const uint4*)g_wh)[src];
        }
        if (tid < 128) bias_s[tid] = g_bias[nt*128 + tid];
        __syncthreads();

        float acc[2][8][4];
        #pragma unroll
        for (int mi = 0; mi < 2; mi++)
            #pragma unroll
            for (int j = 0; j < 8; j++)
                #pragma unroll
                for (int e = 0; e < 4; e++) acc[mi][j][e] = 0.f;

        const unsigned Ab = smb + MA_AH + baseA;
        const unsigned Bb = smb + MA_WH + baseB;
        #pragma unroll
        for (int ks = 0; ks < 8; ks++) {
            unsigned af[2][4], bf[4][4];
            ldsm4(af[0], Ab + ks*32);
            ldsm4(af[1], Ab + 4352 + ks*32);
            #pragma unroll
            for (int j = 0; j < 4; j++) ldsm4(bf[j], Bb + j*4352 + ks*32);
            #pragma unroll
            for (int mi = 0; mi < 2; mi++) {
                #pragma unroll
                for (int j = 0; j < 4; j++) {
                    mma16816(acc[mi][2*j],   af[mi], bf[j][0], bf[j][1]);
                    mma16816(acc[mi][2*j+1], af[mi], bf[j][2], bf[j][3]);
                }
            }
        }

        // store with bias
        const int r0 = mbase + wr*32 + (lane >> 2);
        #pragma unroll
        for (int mi = 0; mi < 2; mi++) {
            #pragma unroll
            for (int j = 0; j < 8; j++) {
                int cl = wc*64 + j*8 + (lane & 3)*2;
                float b0 = bias_s[cl], b1 = bias_s[cl+1];
                float* p0 = C + (size_t)(r0 + mi*16)*512 + nt*128 + cl;
                float2 v0 = { acc[mi][j][0] + b0, acc[mi][j][1] + b1 };
                float2 v1 = { acc[mi][j][2] + b0, acc[mi][j][3] + b1 };
                *(float2*)p0 = v0;
                *(float2*)(p0 + 8*512) = v1;
            }
        }
        __syncthreads();
    }
}

// ---------------- LSTM recurrence (unchanged from R12) ---------------------
#define LSTM_SMEM (8*512*16 + 2*128*4 + 64)

template<int WRITE_ALL>
__global__ void __launch_bounds__(512, 1) lstm_rec(const float* __restrict__ xpre,
                                                   const float* __restrict__ Whh,
                                                   float* __restrict__ hout)
{
    extern __shared__ char smraw[];
    ulonglong2* ws3 = (ulonglong2*)smraw;              // [8][512] gate-3 f32 pairs
    float* hs0 = (float*)(smraw + 8*512*16);           // h double buffer
    float* hs1 = hs0 + 128;

    const int j = threadIdx.x;
    const int n = blockIdx.x;
    const int l = j & 31;
    const int w = j >> 5;
    const int q = l & 3;
    const int cell = w*8 + (l >> 2);

    ull wr[48];
    #pragma unroll
    for (int g = 0; g < 3; g++) {
        const float* wp = Whh + (g*128 + cell)*128 + 32*q;
        #pragma unroll
        for (int i = 0; i < 8; i++) {
            float4 v = *(const float4*)(wp + 4*i);
            wr[g*16 + 2*i]     = pk2(v.x, v.y);
            wr[g*16 + 2*i + 1] = pk2(v.z, v.w);
        }
    }
    {
        const float* wp = Whh + (3*128 + cell)*128 + 32*q;
        #pragma unroll
        for (int d = 0; d < 8; d++) {
            ulonglong2 pr;
            pr.x = pk2(wp[4*d+0], wp[4*d+1]);
            pr.y = pk2(wp[4*d+2], wp[4*d+3]);
            ws3[d*512 + j] = pr;
        }
    }

    if (j < 128) { hs0[j] = 0.f; hs1[j] = 0.f; }
    float c = 0.f;
    __syncthreads();

    const float* xp = xpre + (size_t)n*TT*512 + j;
    float xnext = xp[0];
    float* hw = hout + (WRITE_ALL ? ((size_t)n*TT*128 + cell) : ((size_t)n*128 + cell));

    const int wblk = cell >> 5;
    const int wslot = wblk*32 + (((cell & 31) + 8*wblk) & 31);

    int p = 0;
    for (int t = 0; t < TT; t++) {
        F2U A0, A1, A2, A3;
        A0.u = 0ull; A1.u = 0ull; A2.u = 0ull; A3.u = 0ull;
        float xcur = xnext;
        if (t + 1 < TT) xnext = xp[(size_t)(t+1)*512];

        const float* hb = (p ? hs1 : hs0) + q*32;
        #pragma unroll
        for (int s = 0; s < 4; s++) {
            {
                ulonglong2 w3 = ws3[(2*s)*512 + j];
                int off = (8*s + 8*q) & 31;
                ulonglong2 hv = *(const ulonglong2*)(hb + off);
                fma2(A0.u, wr[4*s],      hv.x); fma2(A0.u, wr[4*s+1],      hv.y);
                fma2(A1.u, wr[16+4*s],   hv.x); fma2(A1.u, wr[16+4*s+1],   hv.y);
                fma2(A2.u, wr[32+4*s],   hv.x); fma2(A2.u, wr[32+4*s+1],   hv.y);
                fma2(A3.u, w3.x,         hv.x); fma2(A3.u, w3.y,           hv.y);
            }
            {
                ulonglong2 w3 = ws3[(2*s+1)*512 + j];
                int off = (8*s + 4 + 8*q) & 31;
                ulonglong2 hv = *(const ulonglong2*)(hb + off);
                fma2(A0.u, wr[4*s+2],    hv.x); fma2(A0.u, wr[4*s+3],      hv.y);
                fma2(A1.u, wr[16+4*s+2], hv.x); fma2(A1.u, wr[16+4*s+3],   hv.y);
                fma2(A2.u, wr[32+4*s+2], hv.x); fma2(A2.u, wr[32+4*s+3],   hv.y);
                fma2(A3.u, w3.x,         hv.x); fma2(A3.u, w3.y,           hv.y);
            }
        }

        float p0 = A0.f.x + A0.f.y;
        float p1 = A1.f.x + A1.f.y;
        float p2 = A2.f.x + A2.f.y;
        float p3 = A3.f.x + A3.f.y;

        ull lo = pk2(p0, p1), hi = pk2(p2, p3);
        ull send = (l & 2) ? lo : hi;
        ull recv = shfl_xor64(send, 2);
        ull keep = (l & 2) ? hi : lo;
        F2U s2; s2.u = add2(keep, recv);
        float mine  = (l & 1) ? s2.f.y : s2.f.x;
        float sendf = (l & 1) ? s2.f.x : s2.f.y;
        float other = __shfl_xor_sync(0xFFFFFFFFu, sendf, 1);
        float acc = mine + other + xcur;

        const bool isg = (q == 2);
        float u  = isg ? acc : 0.5f*acc;
        float th = tanh_ap(u);
        float a  = isg ? th : fmaf(0.5f, th, 0.5f);

        const int base = l & ~3;
        float iv = __shfl_sync(0xFFFFFFFFu, a, base);
        float fv = __shfl_sync(0xFFFFFFFFu, a, base + 1);
        float gv = __shfl_sync(0xFFFFFFFFu, a, base + 2);
        float ov = __shfl_sync(0xFFFFFFFFu, a, base + 3);
        c = fv*c + iv*gv;
        float hv = ov * tanh_ap(c);
        p ^= 1;
        if (q == 0) {
            (p ? hs1 : hs0)[wslot] = hv;
            if (WRITE_ALL)      hw[(size_t)t*128] = hv;
            else if (t == TT-1) hw[0] = hv;
        }
        __syncthreads();
    }
}

// ---------------- E0: pseudo-message projections + direct outputs ----------
__global__ void prep_kernel(const float* __restrict__ x_tag,
                            const float* __restrict__ pm,
                            const float* __restrict__ Wvm,
                            float* __restrict__ out, int osz)
{
    const int tid = threadIdx.x;  // 128
    __shared__ float pms[768];
    for (int i = tid; i < 768; i += 128) pms[i] = pm[i];
    __syncthreads();

    float base = 0.f;
    for (int k = 0; k < 768; k++) base += pms[k]*Wvm[k*128 + tid];
    g_vm[tid]       = leaky(base);
    g_vm[128 + tid] = leaky(base + Wvm[768*128 + tid]);

    if (tid < NNODE) {
        int o;
        o = 236 + tid*2 + 0; if (o < osz) out[o] = x_tag[tid*3+0];
        o = 236 + tid*2 + 1; if (o < osz) out[o] = x_tag[tid*3+1];
        float a = x_tag[tid*3+2];
        o = 474 + tid; if (o < osz) out[o] = (a == 0.f) ? 1.f : 0.f;
        o = 592 + tid; if (o < osz) out[o] = (a == 1.f) ? 1.f : 0.f;
    }
    if (tid == 0) {
        int cnt = 0;
        for (int i = 0; i < NNODE; i++) if (x_tag[i*3+2] == 0.f) cnt++;
        g_flag[0] = (cnt > 0) ? 1.f : 0.f;
    }
}

// ---------------- Gram matrices for l_ort -----------------------------
__global__ void gram_kernel(const float* __restrict__ Wum, const float* __restrict__ Wvm,
                            const float* __restrict__ Wup, const float* __restrict__ Wvp)
{
    const int bid = blockIdx.x;
    const int mat = bid >> 7;
    const int k   = bid & 127;
    const int l   = threadIdx.x;  // 128
    const float* W; int rows;
    if      (mat == 0) { W = Wum; rows = 769; }
    else if (mat == 1) { W = Wvm; rows = 769; }
    else if (mat == 2) { W = Wup; rows = 128; }
    else               { W = Wvp; rows = 128; }
    float acc = 0.f;
    for (int i = 0; i < rows; i++) acc += W[i*128 + k] * W[i*128 + l];
    g_G[mat*16384 + k*128 + l] = acc;
}

// ---------------- E1: per-node MLP chain -> n -------------------------
__global__ void node_kernel(const float* __restrict__ x_tag,
                            const float* __restrict__ Wup,
                            const float* __restrict__ W_hyb, const float* __restrict__ b_hyb,
                            const float* __restrict__ W_act, const float* __restrict__ b_act,
                            const float* __restrict__ W_inact, const float* __restrict__ b_inact)
{
    const int n = blockIdx.x, tid = threadIdx.x;  // 256
    __shared__ float p[128], up[128], vm_s[128], hh[256];
    const float act = x_tag[n*3+2];
    if (tid < 128) {
        p[tid]    = leaky(g_h2last[n*128 + tid]);
        vm_s[tid] = (act == 1.f) ? g_vm[128 + tid] : g_vm[tid];
    }
    __syncthreads();
    if (tid < 128) {
        float a = 0.f;
        for (int k = 0; k < 128; k++) a += p[k]*Wup[k*128 + tid];
        up[tid] = leaky(a);
    }
    __syncthreads();
    {
        float a = b_hyb[tid];
        for (int k = 0; k < 128; k++) {
            float u_ = up[k], v_ = vm_s[k];
            a += u_*W_hyb[k*256 + tid] + (u_ + v_)*W_hyb[(128+k)*256 + tid] + v_*W_hyb[(256+k)*256 + tid];
        }
        hh[tid] = leaky(a);
    }
    __syncthreads();
    {
        float na = b_act[tid], ni = b_inact[tid];
        for (int k = 0; k < 256; k++) {
            float h_ = hh[k];
            na += h_*W_act[k*256 + tid];
            ni += h_*W_inact[k*256 + tid];
        }
        na += x_tag[n*3+0]*W_act[256*256 + tid] + x_tag[n*3+1]*W_act[257*256 + tid];
        g_n[n*256 + tid] = leaky(na*(1.f - act) + ni*act);
    }
}

// ---------------- E2: per-node pair projections -----------------------
__global__ void proj_kernel(const float* __restrict__ Wphin,
                            const float* __restrict__ Won,
                            const float* __restrict__ Weo)
{
    const int n = blockIdx.x, tid = threadIdx.x;  // 256
    __shared__ float nn_s[256];
    nn_s[tid] = g_n[n*256 + tid];
    __syncthreads();
    if (tid < 192) {
        float pb = 0.f, pa = 0.f;
        for (int k = 0; k < 256; k++) {
            float v = nn_s[k];
            pb += v*Wphin[k*192 + tid];
            pa += v*Wphin[(256+k)*192 + tid];
        }
        g_Pb[n*192 + tid] = pb;
        g_Pa[n*192 + tid] = pa;
    }
    float qb = 0.f, qa = 0.f, rb = 0.f, ra = 0.f;
    for (int k = 0; k < 256; k++) {
        float v = nn_s[k];
        qb += v*Won[k*256 + tid];
        qa += v*Won[(256+k)*256 + tid];
        rb += v*Weo[(256+k)*256 + tid];
        ra += v*Weo[(512+k)*256 + tid];
    }
    g_Qb[n*256 + tid] = qb;
    g_Qa[n*256 + tid] = qa;
    g_Rb[n*256 + tid] = rb;
    g_Ra[n*256 + tid] = ra;
}

// ---------------- E3: phi column + masked softmaxes -> alpha ----------
__device__ __forceinline__ float blockmax128(float v, float* red){
    int tid = threadIdx.x; red[tid] = v; __syncthreads();
    #pragma unroll
    for (int s = 64; s > 0; s >>= 1) { if (tid < s) red[tid] = fmaxf(red[tid], red[tid+s]); __syncthreads(); }
    float r = red[0]; __syncthreads(); return r;
}
__device__ __forceinline__ float blocksum128(float v, float* red){
    int tid = threadIdx.x; red[tid] = v; __syncthreads();
    #pragma unroll
    for (int s = 64; s > 0; s >>= 1) { if (tid < s) red[tid] += red[tid+s]; __syncthreads(); }
    float r = red[0]; __syncthreads(); return r;
}

__global__ void phi_alpha_kernel(const float* __restrict__ x_tag,
                                 const float* __restrict__ aphi)
{
    const int b = blockIdx.x;
    const int tid = threadIdx.x;  // 128
    __shared__ float pb_s[192], ap_s[192], red[128];
    for (int i = tid; i < 192; i += 128) { pb_s[i] = g_Pb[b*192 + i]; ap_s[i] = aphi[i]; }
    __syncthreads();

    float ph = 0.f, v1 = 0.f;
    if (tid < NNODE) {
        const float* pa = g_Pa + tid*192;
        #pragma unroll 8
        for (int d = 0; d < 192; d++) ph += leaky(pb_s[d] + pa[d]) * ap_s[d];
        v1 = (x_tag[tid*3+2] == 0.f) ? 1.f : 0.f;
    }

    const float NEG = -1000000000.f;
    float m1 = (tid < NNODE) ? (v1 > 0.f ? ph : NEG) : -INFINITY;
    float m0 = (tid < NNODE) ? (v1 > 0.f ? NEG : ph) : -INFINITY;
    float ma = (tid < NNODE) ? ph : -INFINITY;

    float mx = blockmax128(m1, red);
    float e  = (tid < NNODE) ? __expf(m1 - mx) : 0.f;
    float s  = blocksum128(e, red);
    float sm1 = e / s;

    mx = blockmax128(m0, red);
    e  = (tid < NNODE) ? __expf(m0 - mx) : 0.f;
    s  = blocksum128(e, red);
    float sm0 = e / s;

    mx = blockmax128(ma, red);
    e  = (tid < NNODE) ? __expf(ma - mx) : 0.f;
    s  = blocksum128(e, red);
    float sma = e / s;

    if (tid < NNODE) {
        float a = (g_flag[0] > 0.f) ? (v1 > 0.f ? sm1 : sm0) : sma;
        g_alpha[tid*NNODE + b] = a;
    }
}

// ---------------- E4: hyper messages + y_hat --------------------------
__global__ void hyper_kernel(const float* __restrict__ x_tag,
                             const float* __restrict__ Weo,
                             const float* __restrict__ Wi,
                             const float* __restrict__ bi,
                             float* __restrict__ out, int osz)
{
    const int n = blockIdx.x, tid = threadIdx.x;  // 256
    __shared__ float qa[256], ra[256], nn_s[256], u[256], al[NNODE], red[256];
    qa[tid]   = g_Qa[n*256 + tid];
    ra[tid]   = g_Ra[n*256 + tid];
    nn_s[tid] = g_n[n*256 + tid];
    if (tid < NNODE) al[tid] = g_alpha[n*NNODE + tid];
    __syncthreads();

    float uacc = 0.f, racc = 0.f, alsum = 0.f;
    const float qad = qa[tid];
    for (int j = 0; j < NNODE; j++) {
        float a_ = al[j];
        uacc  += a_ * leaky(g_Qb[j*256 + tid] + qad);
        racc  += a_ * g_Rb[j*256 + tid];
        alsum += a_;
    }
    u[tid] = uacc;
    __syncthreads();

    float T = racc + alsum*ra[tid];
    for (int k = 0; k < 256; k++) T += u[k]*Weo[k*256 + tid];

    const float act = x_tag[n*3+2];
    float hm0 = leaky(act*T);
    float hm1 = leaky((1.f - act)*T);

    const float* Win = Wi + (size_t)n*768*2;
    float p0 = nn_s[tid]*Win[tid*2+0] + hm0*Win[(256+tid)*2+0] + hm1*Win[(512+tid)*2+0];
    float p1 = nn_s[tid]*Win[tid*2+1] + hm0*Win[(256+tid)*2+1] + hm1*Win[(512+tid)*2+1];

    red[tid] = p0; __syncthreads();
    #pragma unroll
    for (int s = 128; s > 0; s >>= 1) { if (tid < s) red[tid] += red[tid+s]; __syncthreads(); }
    float y0 = red[0] + bi[n*2+0]; __syncthreads();

    red[tid] = p1; __syncthreads();
    #pragma unroll
    for (int s = 128; s > 0; s >>= 1) { if (tid < s) red[tid] += red[tid+s]; __syncthreads(); }
    float y1 = red[0] + bi[n*2+1];

    if (tid == 0) {
        float mx = fmaxf(y0, y1);
        float e0 = __expf(y0 - mx), e1 = __expf(y1 - mx);
        int o;
        o = n*2+0; if (o < osz) out[o] = e0/(e0+e1);
        o = n*2+1; if (o < osz) out[o] = e1/(e0+e1);
    }
}

// ---------------- E5: l_ort + l_pol -----------------------------------
__global__ void finals_kernel(const float* __restrict__ x_tag,
                              float* __restrict__ out, int osz)
{
    const int tid = threadIdx.x;  // 256
    __shared__ float red[256], w[NNODE];

    float s1 = 0.f, s2 = 0.f;
    for (int i = tid; i < 16384; i += 256) {
        s1 += g_G[i]          * g_G[16384 + i];
        s2 += g_G[32768 + i]  * g_G[49152 + i];
    }
    red[tid] = s1; __syncthreads();
    #pragma unroll
    for (int s = 128; s > 0; s >>= 1) { if (tid < s) red[tid] += red[tid+s]; __syncthreads(); }
    float S1 = red[0]; __syncthreads();
    red[tid] = s2; __syncthreads();
    #pragma unroll
    for (int s = 128; s > 0; s >>= 1) { if (tid < s) red[tid] += red[tid+s]; __syncthreads(); }
    float S2 = red[0]; __syncthreads();
    if (tid == 0 && 472 < osz) out[472] = sqrtf(S1) + sqrtf(S2);

    if (tid < NNODE) {
        float nr = 0.f;
        const float* np = g_n + tid*256;
        for (int d = 0; d < 256; d++) nr += np[d]*np[d];
        nr = fmaxf(sqrtf(nr), 1e-8f);
        float diff = x_tag[tid*3+1] - x_tag[tid*3+0];
        float sg = (diff > 0.f ? 1.f : (diff < 0.f ? -1.f : 0.f));
        sg *= (x_tag[tid*3+2] == 0.f) ? 1.f : 0.f;
        w[tid] = sg / nr;
    }
    __syncthreads();
    float v = 0.f;
    for (int i = 0; i < NNODE; i++) v += w[i]*g_n[i*256 + tid];
    red[tid] = v*v; __syncthreads();
    #pragma unroll
    for (int s = 128; s > 0; s >>= 1) { if (tid < s) red[tid] += red[tid+s]; __syncthreads(); }
    if (tid == 0 && 473 < osz) out[473] = red[0];
}

// ---------------- launch ----------------------------------------------
extern "C" void kernel_launch(void* const* d_in, const int* in_sizes, int n_in,
                              void* d_out, int out_size)
{
    const float* x       = (const float*)d_in[0];
    const float* x_tag   = (const float*)d_in[1];
    const float* W_ih0   = (const float*)d_in[2];
    const float* W_hh0   = (const float*)d_in[3];
    const float* b_ih0   = (const float*)d_in[4];
    const float* b_hh0   = (const float*)d_in[5];
    const float* W_ih1   = (const float*)d_in[6];
    const float* W_hh1   = (const float*)d_in[7];
    const float* b_ih1   = (const float*)d_in[8];
    const float* b_hh1   = (const float*)d_in[9];
    const float* pm      = (const float*)d_in[10];
    const float* Wum     = (const float*)d_in[11];
    const float* Wvm     = (const float*)d_in[12];
    const float* Wup     = (const float*)d_in[13];
    const float* Wvp     = (const float*)d_in[14];
    const float* W_hyb   = (const float*)d_in[15];
    const float* b_hyb   = (const float*)d_in[16];
    const float* W_act   = (const float*)d_in[17];
    const float* b_act   = (const float*)d_in[18];
    const float* W_inact = (const float*)d_in[19];
    const float* b_inact = (const float*)d_in[20];
    const float* Wphin   = (const float*)d_in[21];
    const float* aphi    = (const float*)d_in[22];
    const float* Won     = (const float*)d_in[23];
    const float* Weo     = (const float*)d_in[24];
    const float* Wi      = (const float*)d_in[25];
    const float* bi      = (const float*)d_in[26];
    float* out = (float*)d_out;

    float *xpre = nullptr, *h1 = nullptr, *h2last = nullptr;
    cudaGetSymbolAddress((void**)&xpre,   g_xpre);
    cudaGetSymbolAddress((void**)&h1,     g_h1);
    cudaGetSymbolAddress((void**)&h2last, g_h2last);

    cudaFuncSetAttribute(gemm_mma, cudaFuncAttributeMaxDynamicSharedMemorySize, MA_SMEM);
    cudaFuncSetAttribute(lstm_rec<1>, cudaFuncAttributeMaxDynamicSharedMemorySize, LSTM_SMEM);
    cudaFuncSetAttribute(lstm_rec<0>, cudaFuncAttributeMaxDynamicSharedMemorySize, LSTM_SMEM);

    // layer 0
    convW<<<512, 128>>>(W_ih0, b_ih0, b_hh0);
    gemm_mma<<<M_ROWS/128, 256, MA_SMEM>>>(x, xpre);
    lstm_rec<1><<<NNODE, 512, LSTM_SMEM>>>(xpre, W_hh0, h1);
    // layer 1
    convW<<<512, 128>>>(W_ih1, b_ih1, b_hh1);
    gemm_mma<<<M_ROWS/128, 256, MA_SMEM>>>(h1, xpre);
    lstm_rec<0><<<NNODE, 512, LSTM_SMEM>>>(xpre, W_hh1, h2last);

    // epilogue
    prep_kernel<<<1, 128>>>(x_tag, pm, Wvm, out, out_size);
    gram_kernel<<<512, 128>>>(Wum, Wvm, Wup, Wvp);
    node_kernel<<<NNODE, 256>>>(x_tag, Wup, W_hyb, b_hyb, W_act, b_act, W_inact, b_inact);
    proj_kernel<<<NNODE, 256>>>(Wphin, Won, Weo);
    phi_alpha_kernel<<<NNODE, 128>>>(x_tag, aphi);
    hyper_kernel<<<NNODE, 256>>>(x_tag, Weo, Wi, bi, out, out_size);
    finals_kernel<<<1, 256>>>(x_tag, out, out_size);
}